// round 9
// baseline (speedup 1.0000x reference)
#include <cuda_runtime.h>
#include <cuda_fp16.h>
#include <stdint.h>

#define BZ 8
#define TT 2048
#define FT 512
#define HD 512
#define MTOT (BZ * TT)   // 16384

// ---------------- scratch (device globals; allocation-free) ----------------
__device__ __align__(16) __half g_qh[MTOT * FT], g_ql[MTOT * FT];
__device__ __align__(16) __half g_kh[MTOT * FT], g_kl[MTOT * FT];
__device__ __align__(16) __half g_vh[MTOT * FT], g_vl[MTOT * FT];
__device__ __align__(16) __half g_Wqh[FT * HD], g_Wql[FT * HD];
__device__ __align__(16) __half g_Wkh[FT * HD], g_Wkl[FT * HD];
__device__ __align__(16) __half g_Wvh[FT * HD], g_Wvl[FT * HD];
__device__ __align__(16) __half g_Qh[MTOT * HD], g_Ql[MTOT * HD];
__device__ __align__(16) __half g_Kh[MTOT * HD], g_Kl[MTOT * HD];
__device__ __align__(16) __half g_Vh[MTOT * HD], g_Vl[MTOT * HD];
__device__ __align__(16) __half g_Vth[(size_t)BZ * HD * TT], g_Vtl[(size_t)BZ * HD * TT];
__device__ __align__(16) float g_S[(size_t)BZ * TT * TT];
__device__ __align__(16) __half g_Ph[(size_t)BZ * TT * TT];

// ---------------- helpers ----------------
__device__ __forceinline__ uint32_t smem_u32(const void* p) {
    uint32_t a;
    asm("{ .reg .u64 t; cvta.to.shared.u64 t, %1; cvt.u32.u64 %0, t; }" : "=r"(a) : "l"(p));
    return a;
}

#define CP16(dst, src) \
    asm volatile("cp.async.cg.shared.global [%0], [%1], 16;" :: "r"(dst), "l"(src) : "memory")

#define LDSM4(r, addr) \
    asm volatile("ldmatrix.sync.aligned.m8n8.x4.shared.b16 {%0,%1,%2,%3}, [%4];" \
                 : "=r"((r)[0]), "=r"((r)[1]), "=r"((r)[2]), "=r"((r)[3]) : "r"(addr))

#define MMAF32(d, a, b0, b1) \
    asm volatile("mma.sync.aligned.m16n8k16.row.col.f32.f16.f16.f32 " \
                 "{%0,%1,%2,%3}, {%4,%5,%6,%7}, {%8,%9}, {%0,%1,%2,%3};" \
                 : "+f"((d)[0]), "+f"((d)[1]), "+f"((d)[2]), "+f"((d)[3]) \
                 : "r"((a)[0]), "r"((a)[1]), "r"((a)[2]), "r"((a)[3]), "r"(b0), "r"(b1))

// ---------------- warp-MMA GEMM ----------------
// D[m,n] = sum_k A[m,k]*B[n,k], fp16 split, f32 accumulate.
// TERMS=3: Ah*Bh + Ah*Bl + Al*Bh  (A split + B split)
// TERMS=2: Ah*Bh + Ah*Bl          (A plain fp16, B split; Al tile unused)
// K-chunk 32 (64B rows, SW64 swizzle), double-buffered, 64KB smem, 2 CTAs/SM.
static constexpr int TILE_B = 8192;             // 128 rows x 64 bytes
static constexpr int STAGE_B = 4 * TILE_B;      // Ah, Al, Bh, Bl = 32 KB
static constexpr int GEMM_SMEM = 2 * STAGE_B;   // 64 KB

__device__ __forceinline__ void load_tile(uint32_t dstbase, const __half* src, int ld, int tid)
{
    #pragma unroll
    for (int j = 0; j < 2; j++) {
        const int seg = tid + j * 256;          // 512 segs of 16B
        const int row = seg >> 2;               // 0..127
        const int colb = (seg & 3) * 16;        // 0..48
        const uint32_t off = (uint32_t)(row * 64 + colb);
        const uint32_t sw = off ^ ((off >> 3) & 0x30);
        CP16(dstbase + sw, (const char*)src + (long)row * ld * 2 + colb);
    }
}

template <int MODE, int TERMS>
__global__ __launch_bounds__(256, 2)
void gemm_mma(const __half* __restrict__ Ah, const __half* __restrict__ Al,
              const __half* __restrict__ Bh, const __half* __restrict__ Bl,
              int lda, int ldb, long sA, long sB, int K,
              const float* __restrict__ bias, float scale,
              float* __restrict__ outF, __half* __restrict__ outH, __half* __restrict__ outL,
              int ldo, long sO)
{
    extern __shared__ char smem[];
    const uint32_t sbase = smem_u32(smem);
    const int tid = threadIdx.x;
    const int wid = tid >> 5;
    const int L = tid & 31;
    const int bm = blockIdx.y * 128;
    const int bn = blockIdx.x * 128;
    const int wm = wid & 1;       // 0..1  (64 rows each)
    const int wn = wid >> 1;      // 0..3  (32 cols each)

    const __half* pAh = Ah + (long)blockIdx.z * sA + (long)bm * lda;
    const __half* pAl = Al + (long)blockIdx.z * sA + (long)bm * lda;
    const __half* pBh = Bh + (long)blockIdx.z * sB + (long)bn * ldb;
    const __half* pBl = Bl + (long)blockIdx.z * sB + (long)bn * ldb;

    const int lr = L & 15;
    const int lc = (L >> 4) * 16;
    uint32_t aoffu[4], apat[4], boffu[2], bpat[2];
    #pragma unroll
    for (int mt = 0; mt < 4; mt++) {
        const uint32_t off = (uint32_t)((wm * 64 + mt * 16 + lr) * 64 + lc);
        aoffu[mt] = off;
        apat[mt] = (off >> 3) & 0x30;
    }
    #pragma unroll
    for (int ng = 0; ng < 2; ng++) {
        const uint32_t off = (uint32_t)((wn * 32 + ng * 16 + lr) * 64 + lc);
        boffu[ng] = off;
        bpat[ng] = (off >> 3) & 0x30;
    }

    float acc[4][4][4];
    #pragma unroll
    for (int mt = 0; mt < 4; mt++)
        #pragma unroll
        for (int nt = 0; nt < 4; nt++)
            #pragma unroll
            for (int r = 0; r < 4; r++)
                acc[mt][nt][r] = 0.0f;

    const int nchunk = K / 32;

    load_tile(sbase + 0 * TILE_B, pAh, lda, tid);
    if (TERMS == 3) load_tile(sbase + 1 * TILE_B, pAl, lda, tid);
    load_tile(sbase + 2 * TILE_B, pBh, ldb, tid);
    load_tile(sbase + 3 * TILE_B, pBl, ldb, tid);
    asm volatile("cp.async.commit_group;" ::: "memory");

    for (int ck = 0; ck < nchunk; ck++) {
        const int buf = ck & 1;
        if (ck + 1 < nchunk) {
            const int k0 = (ck + 1) * 32;
            const uint32_t db = sbase + (buf ^ 1) * STAGE_B;
            load_tile(db + 0 * TILE_B, pAh + k0, lda, tid);
            if (TERMS == 3) load_tile(db + 1 * TILE_B, pAl + k0, lda, tid);
            load_tile(db + 2 * TILE_B, pBh + k0, ldb, tid);
            load_tile(db + 3 * TILE_B, pBl + k0, ldb, tid);
            asm volatile("cp.async.commit_group;" ::: "memory");
            asm volatile("cp.async.wait_group 1;" ::: "memory");
        } else {
            asm volatile("cp.async.wait_group 0;" ::: "memory");
        }
        __syncthreads();

        const uint32_t cb = sbase + buf * STAGE_B;
        #pragma unroll
        for (int kk = 0; kk < 2; kk++) {
            uint32_t bh[2][4], bl[2][4];
            #pragma unroll
            for (int ng = 0; ng < 2; ng++) {
                const uint32_t sw = (boffu[ng] + kk * 32) ^ bpat[ng];
                LDSM4(bh[ng], cb + 2 * TILE_B + sw);
                LDSM4(bl[ng], cb + 3 * TILE_B + sw);
            }
            #pragma unroll
            for (int mt = 0; mt < 4; mt++) {
                uint32_t ah[4], al[4];
                const uint32_t sw = (aoffu[mt] + kk * 32) ^ apat[mt];
                LDSM4(ah, cb + 0 * TILE_B + sw);
                if (TERMS == 3) LDSM4(al, cb + 1 * TILE_B + sw);
                #pragma unroll
                for (int nt = 0; nt < 4; nt++) {
                    const int ng = nt >> 1, h = nt & 1;
                    const uint32_t b0h = bh[ng][h], b1h = bh[ng][h + 2];
                    const uint32_t b0l = bl[ng][h], b1l = bl[ng][h + 2];
                    MMAF32(acc[mt][nt], ah, b0h, b1h);
                    MMAF32(acc[mt][nt], ah, b0l, b1l);
                    if (TERMS == 3) MMAF32(acc[mt][nt], al, b0h, b1h);
                }
            }
        }
        __syncthreads();
    }

    // epilogue
    const int r0 = bm + wm * 64 + (L >> 2);
    const int c0 = bn + wn * 32 + (L & 3) * 2;
    #pragma unroll
    for (int mt = 0; mt < 4; mt++) {
        #pragma unroll
        for (int nt = 0; nt < 4; nt++) {
            const int row = r0 + mt * 16;
            const int col = c0 + nt * 8;
            if (MODE == 1) {
                float* po = outF + (size_t)blockIdx.z * sO;
                *reinterpret_cast<float2*>(po + (size_t)row * ldo + col) =
                    make_float2(acc[mt][nt][0], acc[mt][nt][1]);
                *reinterpret_cast<float2*>(po + (size_t)(row + 8) * ldo + col) =
                    make_float2(acc[mt][nt][2], acc[mt][nt][3]);
            } else {
                const float b0 = bias[col], b1 = bias[col + 1];
                float x0 = (acc[mt][nt][0] + b0) * scale;
                float x1 = (acc[mt][nt][1] + b1) * scale;
                float x2 = (acc[mt][nt][2] + b0) * scale;
                float x3 = (acc[mt][nt][3] + b1) * scale;
                __half h0 = __float2half_rn(x0), h1 = __float2half_rn(x1);
                __half h2 = __float2half_rn(x2), h3 = __float2half_rn(x3);
                __half l0 = __float2half_rn(x0 - __half2float(h0));
                __half l1 = __float2half_rn(x1 - __half2float(h1));
                __half l2 = __float2half_rn(x2 - __half2float(h2));
                __half l3 = __float2half_rn(x3 - __half2float(h3));
                __half2 t;
                t.x = h0; t.y = h1;
                *reinterpret_cast<__half2*>(outH + (size_t)row * ldo + col) = t;
                t.x = h2; t.y = h3;
                *reinterpret_cast<__half2*>(outH + (size_t)(row + 8) * ldo + col) = t;
                t.x = l0; t.y = l1;
                *reinterpret_cast<__half2*>(outL + (size_t)row * ldo + col) = t;
                t.x = l2; t.y = l3;
                *reinterpret_cast<__half2*>(outL + (size_t)(row + 8) * ldo + col) = t;
            }
        }
    }
}

// ---------------- small kernels ----------------
__global__ __launch_bounds__(256) void fsplit(const float* __restrict__ x,
                                              __half* __restrict__ h, __half* __restrict__ l)
{
    const int i = (blockIdx.x * 256 + threadIdx.x) * 4;
    float4 v = *reinterpret_cast<const float4*>(x + i);
    __half h0 = __float2half_rn(v.x), h1 = __float2half_rn(v.y);
    __half h2 = __float2half_rn(v.z), h3 = __float2half_rn(v.w);
    __half l0 = __float2half_rn(v.x - __half2float(h0));
    __half l1 = __float2half_rn(v.y - __half2float(h1));
    __half l2 = __float2half_rn(v.z - __half2float(h2));
    __half l3 = __float2half_rn(v.w - __half2float(h3));
    __half2 a;
    a.x = h0; a.y = h1; *reinterpret_cast<__half2*>(h + i) = a;
    a.x = h2; a.y = h3; *reinterpret_cast<__half2*>(h + i + 2) = a;
    a.x = l0; a.y = l1; *reinterpret_cast<__half2*>(l + i) = a;
    a.x = l2; a.y = l3; *reinterpret_cast<__half2*>(l + i + 2) = a;
}

// W [K=512, N=512] -> Wt hi/lo [N, K]
__global__ __launch_bounds__(256) void wsplit(const float* __restrict__ W,
                                              __half* __restrict__ Wth, __half* __restrict__ Wtl)
{
    __shared__ float t[32][33];
    const int n0 = blockIdx.x * 32, k0 = blockIdx.y * 32;
    const int tx = threadIdx.x & 31, ty = threadIdx.x >> 5;
    #pragma unroll
    for (int i = 0; i < 4; i++) {
        const int r = ty + i * 8;
        t[r][tx] = W[(size_t)(k0 + r) * HD + n0 + tx];
    }
    __syncthreads();
    #pragma unroll
    for (int i = 0; i < 4; i++) {
        const int r = ty + i * 8;          // n
        const float v = t[tx][r];
        __half h = __float2half_rn(v);
        __half l = __float2half_rn(v - __half2float(h));
        const size_t dst = (size_t)(n0 + r) * FT + k0 + tx;
        Wth[dst] = h;
        Wtl[dst] = l;
    }
}

// V hi/lo [B*T, H] -> Vt hi/lo [B][H][T]
__global__ __launch_bounds__(256) void transpose_v(const __half* __restrict__ Vh,
                                                   const __half* __restrict__ Vl,
                                                   __half* __restrict__ Vth, __half* __restrict__ Vtl)
{
    __shared__ __half th[32][33], tl[32][33];
    const int b = blockIdx.z;
    const int h0 = blockIdx.x * 32, s0 = blockIdx.y * 32;
    const int tx = threadIdx.x & 31, ty = threadIdx.x >> 5;
    #pragma unroll
    for (int i = 0; i < 4; i++) {
        const int r = ty + i * 8;
        const size_t src = ((size_t)b * TT + s0 + r) * HD + h0 + tx;
        th[r][tx] = Vh[src];
        tl[r][tx] = Vl[src];
    }
    __syncthreads();
    #pragma unroll
    for (int i = 0; i < 4; i++) {
        const int r = ty + i * 8;          // h
        const size_t dst = ((size_t)b * HD + h0 + r) * TT + s0 + tx;
        Vth[dst] = th[tx][r];
        Vtl[dst] = tl[tx][r];
    }
}

// softmax over rows of 2048; writes P as plain fp16 (PV uses 2-term split on V only)
__global__ __launch_bounds__(256) void softmax_k(const float* __restrict__ S,
                                                 __half* __restrict__ Ph)
{
    const size_t off = (size_t)blockIdx.x * TT;
    const int tid = threadIdx.x;
    const float* p = S + off + tid * 8;
    float v[8];
    float4 a = *reinterpret_cast<const float4*>(p);
    float4 b = *reinterpret_cast<const float4*>(p + 4);
    v[0] = a.x; v[1] = a.y; v[2] = a.z; v[3] = a.w;
    v[4] = b.x; v[5] = b.y; v[6] = b.z; v[7] = b.w;

    __shared__ float red[8];
    float m = v[0];
    #pragma unroll
    for (int i = 1; i < 8; i++) m = fmaxf(m, v[i]);
    #pragma unroll
    for (int o = 16; o > 0; o >>= 1) m = fmaxf(m, __shfl_xor_sync(0xffffffffu, m, o));
    if ((tid & 31) == 0) red[tid >> 5] = m;
    __syncthreads();
    float M = red[0];
    #pragma unroll
    for (int i = 1; i < 8; i++) M = fmaxf(M, red[i]);
    __syncthreads();

    float s = 0.f;
    #pragma unroll
    for (int i = 0; i < 8; i++) { v[i] = __expf(v[i] - M); s += v[i]; }
    #pragma unroll
    for (int o = 16; o > 0; o >>= 1) s += __shfl_xor_sync(0xffffffffu, s, o);
    if ((tid & 31) == 0) red[tid >> 5] = s;
    __syncthreads();
    float tot = 0.f;
    #pragma unroll
    for (int i = 0; i < 8; i++) tot += red[i];
    const float inv = __fdividef(1.0f, tot);

    __half* ph = Ph + off + tid * 8;
    #pragma unroll
    for (int i = 0; i < 8; i += 2) {
        __half2 t;
        t.x = __float2half_rn(v[i] * inv);
        t.y = __float2half_rn(v[i + 1] * inv);
        *reinterpret_cast<__half2*>(ph + i) = t;
    }
}

// ---------------- launch ----------------
extern "C" void kernel_launch(void* const* d_in, const int* in_sizes, int n_in,
                              void* d_out, int out_size)
{
    const float* q  = (const float*)d_in[0];
    const float* k  = (const float*)d_in[1];
    const float* v  = (const float*)d_in[2];
    const float* Wq = (const float*)d_in[3];
    const float* bq = (const float*)d_in[4];
    const float* Wk = (const float*)d_in[5];
    const float* bk = (const float*)d_in[6];
    const float* Wv = (const float*)d_in[7];
    const float* bv = (const float*)d_in[8];
    float* out = (float*)d_out;

    __half *qh, *ql, *kh, *kl, *vh, *vl;
    __half *wqh, *wql, *wkh, *wkl, *wvh, *wvl;
    __half *Qh, *Ql, *Kh, *Kl, *Vh, *Vl, *Vth, *Vtl, *Ph;
    float* S;
    cudaGetSymbolAddress((void**)&qh, g_qh);   cudaGetSymbolAddress((void**)&ql, g_ql);
    cudaGetSymbolAddress((void**)&kh, g_kh);   cudaGetSymbolAddress((void**)&kl, g_kl);
    cudaGetSymbolAddress((void**)&vh, g_vh);   cudaGetSymbolAddress((void**)&vl, g_vl);
    cudaGetSymbolAddress((void**)&wqh, g_Wqh); cudaGetSymbolAddress((void**)&wql, g_Wql);
    cudaGetSymbolAddress((void**)&wkh, g_Wkh); cudaGetSymbolAddress((void**)&wkl, g_Wkl);
    cudaGetSymbolAddress((void**)&wvh, g_Wvh); cudaGetSymbolAddress((void**)&wvl, g_Wvl);
    cudaGetSymbolAddress((void**)&Qh, g_Qh);   cudaGetSymbolAddress((void**)&Ql, g_Ql);
    cudaGetSymbolAddress((void**)&Kh, g_Kh);   cudaGetSymbolAddress((void**)&Kl, g_Kl);
    cudaGetSymbolAddress((void**)&Vh, g_Vh);   cudaGetSymbolAddress((void**)&Vl, g_Vl);
    cudaGetSymbolAddress((void**)&Vth, g_Vth); cudaGetSymbolAddress((void**)&Vtl, g_Vtl);
    cudaGetSymbolAddress((void**)&S, g_S);
    cudaGetSymbolAddress((void**)&Ph, g_Ph);

    cudaFuncSetAttribute((const void*)gemm_mma<0, 3>, cudaFuncAttributeMaxDynamicSharedMemorySize, GEMM_SMEM);
    cudaFuncSetAttribute((const void*)gemm_mma<1, 3>, cudaFuncAttributeMaxDynamicSharedMemorySize, GEMM_SMEM);
    cudaFuncSetAttribute((const void*)gemm_mma<1, 2>, cudaFuncAttributeMaxDynamicSharedMemorySize, GEMM_SMEM);

    // 1) split inputs
    fsplit<<<MTOT * FT / 1024, 256>>>(q, qh, ql);
    fsplit<<<MTOT * FT / 1024, 256>>>(k, kh, kl);
    fsplit<<<MTOT * FT / 1024, 256>>>(v, vh, vl);
    // 2) transpose+split weights
    wsplit<<<dim3(16, 16), 256>>>(Wq, wqh, wql);
    wsplit<<<dim3(16, 16), 256>>>(Wk, wkh, wkl);
    wsplit<<<dim3(16, 16), 256>>>(Wv, wvh, wvl);
    // 3) projections, 3-term (scale 0.25 folded into Q)
    dim3 gp(HD / 128, MTOT / 128, 1);
    gemm_mma<0, 3><<<gp, 256, GEMM_SMEM>>>(qh, ql, wqh, wql, FT, FT, 0, 0, FT,
                                           bq, 0.25f, nullptr, Qh, Ql, HD, 0);
    gemm_mma<0, 3><<<gp, 256, GEMM_SMEM>>>(kh, kl, wkh, wkl, FT, FT, 0, 0, FT,
                                           bk, 1.0f, nullptr, Kh, Kl, HD, 0);
    gemm_mma<0, 3><<<gp, 256, GEMM_SMEM>>>(vh, vl, wvh, wvl, FT, FT, 0, 0, FT,
                                           bv, 1.0f, nullptr, Vh, Vl, HD, 0);
    // 4) transpose V
    transpose_v<<<dim3(HD / 32, TT / 32, BZ), 256>>>(Vh, Vl, Vth, Vtl);
    // 5) energy S = (0.25 Q) K^T, 3-term
    dim3 ge(TT / 128, TT / 128, BZ);
    gemm_mma<1, 3><<<ge, 256, GEMM_SMEM>>>(Qh, Ql, Kh, Kl, HD, HD,
                                           (long)TT * HD, (long)TT * HD, HD,
                                           nullptr, 1.0f, S, nullptr, nullptr,
                                           TT, (long)TT * TT);
    // 6) softmax -> P plain fp16
    softmax_k<<<MTOT, 256>>>(S, Ph);
    // 7) out = P V, 2-term (P plain, V split)
    dim3 go(HD / 128, TT / 128, BZ);
    gemm_mma<1, 2><<<go, 256, GEMM_SMEM>>>(Ph, Ph, Vth, Vtl, TT, TT,
                                           (long)TT * TT, (long)HD * TT, TT,
                                           nullptr, 1.0f, out, nullptr, nullptr,
                                           HD, (long)TT * HD);
}

// round 10
// speedup vs baseline: 1.1628x; 1.1628x over previous
#include <cuda_runtime.h>
#include <cuda_fp16.h>
#include <stdint.h>

#define BZ 8
#define TT 2048
#define FT 512
#define HD 512
#define MTOT (BZ * TT)   // 16384

// ---------------- scratch (device globals; allocation-free) ----------------
__device__ __align__(16) __half g_qh[MTOT * FT], g_ql[MTOT * FT];
__device__ __align__(16) __half g_kh[MTOT * FT], g_kl[MTOT * FT];
__device__ __align__(16) __half g_vh[MTOT * FT], g_vl[MTOT * FT];
__device__ __align__(16) __half g_Wqh[FT * HD], g_Wql[FT * HD];
__device__ __align__(16) __half g_Wkh[FT * HD], g_Wkl[FT * HD];
__device__ __align__(16) __half g_Wvh[FT * HD], g_Wvl[FT * HD];
__device__ __align__(16) __half g_Qh[MTOT * HD], g_Ql[MTOT * HD];
__device__ __align__(16) __half g_Kh[MTOT * HD], g_Kl[MTOT * HD];
__device__ __align__(16) __half g_Vh[MTOT * HD], g_Vl[MTOT * HD];
__device__ __align__(16) __half g_Vth[(size_t)BZ * HD * TT], g_Vtl[(size_t)BZ * HD * TT];
__device__ __align__(16) float g_S[(size_t)BZ * TT * TT];
__device__ __align__(16) __half g_Ph[(size_t)BZ * TT * TT];

// ---------------- helpers ----------------
__device__ __forceinline__ uint32_t smem_u32(const void* p) {
    uint32_t a;
    asm("{ .reg .u64 t; cvta.to.shared.u64 t, %1; cvt.u32.u64 %0, t; }" : "=r"(a) : "l"(p));
    return a;
}

#define CP16(dst, src) \
    asm volatile("cp.async.cg.shared.global [%0], [%1], 16;" :: "r"(dst), "l"(src) : "memory")

#define LDSM4(r, addr) \
    asm volatile("ldmatrix.sync.aligned.m8n8.x4.shared.b16 {%0,%1,%2,%3}, [%4];" \
                 : "=r"((r)[0]), "=r"((r)[1]), "=r"((r)[2]), "=r"((r)[3]) : "r"(addr))

#define MMAF32(d, a, b0, b1) \
    asm volatile("mma.sync.aligned.m16n8k16.row.col.f32.f16.f16.f32 " \
                 "{%0,%1,%2,%3}, {%4,%5,%6,%7}, {%8,%9}, {%0,%1,%2,%3};" \
                 : "+f"((d)[0]), "+f"((d)[1]), "+f"((d)[2]), "+f"((d)[3]) \
                 : "r"((a)[0]), "r"((a)[1]), "r"((a)[2]), "r"((a)[3]), "r"(b0), "r"(b1))

// ---------------- warp-MMA GEMM ----------------
// D[m,n] = sum_k A[m,k]*B[n,k], fp16 split, f32 accumulate.
// TERMS=3: Ah*Bh + Ah*Bl + Al*Bh  (A split + B split)
// TERMS=2: Ah*Bh + Ah*Bl          (A plain fp16, B split; Al tile unused)
// K-chunk 32 (64B rows, SW64 swizzle), double-buffered, 64KB smem, 2 CTAs/SM.
static constexpr int TILE_B = 8192;             // 128 rows x 64 bytes
static constexpr int STAGE_B = 4 * TILE_B;      // Ah, Al, Bh, Bl = 32 KB
static constexpr int GEMM_SMEM = 2 * STAGE_B;   // 64 KB

__device__ __forceinline__ void load_tile(uint32_t dstbase, const __half* src, int ld, int tid)
{
    #pragma unroll
    for (int j = 0; j < 2; j++) {
        const int seg = tid + j * 256;          // 512 segs of 16B
        const int row = seg >> 2;               // 0..127
        const int colb = (seg & 3) * 16;        // 0..48
        const uint32_t off = (uint32_t)(row * 64 + colb);
        const uint32_t sw = off ^ ((off >> 3) & 0x30);
        CP16(dstbase + sw, (const char*)src + (long)row * ld * 2 + colb);
    }
}

template <int MODE, int TERMS>
__global__ __launch_bounds__(256, 2)
void gemm_mma(const __half* __restrict__ Ah, const __half* __restrict__ Al,
              const __half* __restrict__ Bh, const __half* __restrict__ Bl,
              int lda, int ldb, long sA, long sB, int K,
              const float* __restrict__ bias, float scale,
              float* __restrict__ outF, __half* __restrict__ outH, __half* __restrict__ outL,
              int ldo, long sO)
{
    extern __shared__ char smem[];
    const uint32_t sbase = smem_u32(smem);
    const int tid = threadIdx.x;
    const int wid = tid >> 5;
    const int L = tid & 31;
    const int bm = blockIdx.y * 128;
    const int bn = blockIdx.x * 128;
    const int wm = wid & 1;       // 0..1  (64 rows each)
    const int wn = wid >> 1;      // 0..3  (32 cols each)

    const __half* pAh = Ah + (long)blockIdx.z * sA + (long)bm * lda;
    const __half* pAl = Al + (long)blockIdx.z * sA + (long)bm * lda;
    const __half* pBh = Bh + (long)blockIdx.z * sB + (long)bn * ldb;
    const __half* pBl = Bl + (long)blockIdx.z * sB + (long)bn * ldb;

    const int lr = L & 15;
    const int lc = (L >> 4) * 16;
    uint32_t aoffu[4], apat[4], boffu[2], bpat[2];
    #pragma unroll
    for (int mt = 0; mt < 4; mt++) {
        const uint32_t off = (uint32_t)((wm * 64 + mt * 16 + lr) * 64 + lc);
        aoffu[mt] = off;
        apat[mt] = (off >> 3) & 0x30;
    }
    #pragma unroll
    for (int ng = 0; ng < 2; ng++) {
        const uint32_t off = (uint32_t)((wn * 32 + ng * 16 + lr) * 64 + lc);
        boffu[ng] = off;
        bpat[ng] = (off >> 3) & 0x30;
    }

    float acc[4][4][4];
    #pragma unroll
    for (int mt = 0; mt < 4; mt++)
        #pragma unroll
        for (int nt = 0; nt < 4; nt++)
            #pragma unroll
            for (int r = 0; r < 4; r++)
                acc[mt][nt][r] = 0.0f;

    const int nchunk = K / 32;

    load_tile(sbase + 0 * TILE_B, pAh, lda, tid);
    if (TERMS == 3) load_tile(sbase + 1 * TILE_B, pAl, lda, tid);
    load_tile(sbase + 2 * TILE_B, pBh, ldb, tid);
    load_tile(sbase + 3 * TILE_B, pBl, ldb, tid);
    asm volatile("cp.async.commit_group;" ::: "memory");

    for (int ck = 0; ck < nchunk; ck++) {
        const int buf = ck & 1;
        if (ck + 1 < nchunk) {
            const int k0 = (ck + 1) * 32;
            const uint32_t db = sbase + (buf ^ 1) * STAGE_B;
            load_tile(db + 0 * TILE_B, pAh + k0, lda, tid);
            if (TERMS == 3) load_tile(db + 1 * TILE_B, pAl + k0, lda, tid);
            load_tile(db + 2 * TILE_B, pBh + k0, ldb, tid);
            load_tile(db + 3 * TILE_B, pBl + k0, ldb, tid);
            asm volatile("cp.async.commit_group;" ::: "memory");
            asm volatile("cp.async.wait_group 1;" ::: "memory");
        } else {
            asm volatile("cp.async.wait_group 0;" ::: "memory");
        }
        __syncthreads();

        const uint32_t cb = sbase + buf * STAGE_B;
        #pragma unroll
        for (int kk = 0; kk < 2; kk++) {
            uint32_t bh[2][4], bl[2][4];
            #pragma unroll
            for (int ng = 0; ng < 2; ng++) {
                const uint32_t sw = (boffu[ng] + kk * 32) ^ bpat[ng];
                LDSM4(bh[ng], cb + 2 * TILE_B + sw);
                LDSM4(bl[ng], cb + 3 * TILE_B + sw);
            }
            #pragma unroll
            for (int mt = 0; mt < 4; mt++) {
                uint32_t ah[4], al[4];
                const uint32_t sw = (aoffu[mt] + kk * 32) ^ apat[mt];
                LDSM4(ah, cb + 0 * TILE_B + sw);
                if (TERMS == 3) LDSM4(al, cb + 1 * TILE_B + sw);
                #pragma unroll
                for (int nt = 0; nt < 4; nt++) {
                    const int ng = nt >> 1, h = nt & 1;
                    const uint32_t b0h = bh[ng][h], b1h = bh[ng][h + 2];
                    const uint32_t b0l = bl[ng][h], b1l = bl[ng][h + 2];
                    MMAF32(acc[mt][nt], ah, b0h, b1h);
                    MMAF32(acc[mt][nt], ah, b0l, b1l);
                    if (TERMS == 3) MMAF32(acc[mt][nt], al, b0h, b1h);
                }
            }
        }
        __syncthreads();
    }

    // epilogue
    const int r0 = bm + wm * 64 + (L >> 2);
    const int c0 = bn + wn * 32 + (L & 3) * 2;
    #pragma unroll
    for (int mt = 0; mt < 4; mt++) {
        #pragma unroll
        for (int nt = 0; nt < 4; nt++) {
            const int row = r0 + mt * 16;
            const int col = c0 + nt * 8;
            if (MODE == 1) {
                float* po = outF + (size_t)blockIdx.z * sO;
                *reinterpret_cast<float2*>(po + (size_t)row * ldo + col) =
                    make_float2(acc[mt][nt][0], acc[mt][nt][1]);
                *reinterpret_cast<float2*>(po + (size_t)(row + 8) * ldo + col) =
                    make_float2(acc[mt][nt][2], acc[mt][nt][3]);
            } else {
                const float b0 = bias[col], b1 = bias[col + 1];
                float x0 = (acc[mt][nt][0] + b0) * scale;
                float x1 = (acc[mt][nt][1] + b1) * scale;
                float x2 = (acc[mt][nt][2] + b0) * scale;
                float x3 = (acc[mt][nt][3] + b1) * scale;
                __half h0 = __float2half_rn(x0), h1 = __float2half_rn(x1);
                __half h2 = __float2half_rn(x2), h3 = __float2half_rn(x3);
                __half l0 = __float2half_rn(x0 - __half2float(h0));
                __half l1 = __float2half_rn(x1 - __half2float(h1));
                __half l2 = __float2half_rn(x2 - __half2float(h2));
                __half l3 = __float2half_rn(x3 - __half2float(h3));
                __half2 t;
                t.x = h0; t.y = h1;
                *reinterpret_cast<__half2*>(outH + (size_t)row * ldo + col) = t;
                t.x = h2; t.y = h3;
                *reinterpret_cast<__half2*>(outH + (size_t)(row + 8) * ldo + col) = t;
                t.x = l0; t.y = l1;
                *reinterpret_cast<__half2*>(outL + (size_t)row * ldo + col) = t;
                t.x = l2; t.y = l3;
                *reinterpret_cast<__half2*>(outL + (size_t)(row + 8) * ldo + col) = t;
            }
        }
    }
}

// ---------------- small kernels ----------------
__global__ __launch_bounds__(256) void fsplit(const float* __restrict__ x,
                                              __half* __restrict__ h, __half* __restrict__ l)
{
    const int i = (blockIdx.x * 256 + threadIdx.x) * 4;
    float4 v = *reinterpret_cast<const float4*>(x + i);
    __half h0 = __float2half_rn(v.x), h1 = __float2half_rn(v.y);
    __half h2 = __float2half_rn(v.z), h3 = __float2half_rn(v.w);
    __half l0 = __float2half_rn(v.x - __half2float(h0));
    __half l1 = __float2half_rn(v.y - __half2float(h1));
    __half l2 = __float2half_rn(v.z - __half2float(h2));
    __half l3 = __float2half_rn(v.w - __half2float(h3));
    __half2 a;
    a.x = h0; a.y = h1; *reinterpret_cast<__half2*>(h + i) = a;
    a.x = h2; a.y = h3; *reinterpret_cast<__half2*>(h + i + 2) = a;
    a.x = l0; a.y = l1; *reinterpret_cast<__half2*>(l + i) = a;
    a.x = l2; a.y = l3; *reinterpret_cast<__half2*>(l + i + 2) = a;
}

// fp32 -> fp16 hi only (no residual needed; used for q feeding the 2-term Q path)
__global__ __launch_bounds__(256) void fsplit_h(const float* __restrict__ x,
                                                __half* __restrict__ h)
{
    const int i = (blockIdx.x * 256 + threadIdx.x) * 4;
    float4 v = *reinterpret_cast<const float4*>(x + i);
    __half2 a;
    a.x = __float2half_rn(v.x); a.y = __float2half_rn(v.y);
    *reinterpret_cast<__half2*>(h + i) = a;
    a.x = __float2half_rn(v.z); a.y = __float2half_rn(v.w);
    *reinterpret_cast<__half2*>(h + i + 2) = a;
}

// W [K=512, N=512] -> Wt hi/lo [N, K]
__global__ __launch_bounds__(256) void wsplit(const float* __restrict__ W,
                                              __half* __restrict__ Wth, __half* __restrict__ Wtl)
{
    __shared__ float t[32][33];
    const int n0 = blockIdx.x * 32, k0 = blockIdx.y * 32;
    const int tx = threadIdx.x & 31, ty = threadIdx.x >> 5;
    #pragma unroll
    for (int i = 0; i < 4; i++) {
        const int r = ty + i * 8;
        t[r][tx] = W[(size_t)(k0 + r) * HD + n0 + tx];
    }
    __syncthreads();
    #pragma unroll
    for (int i = 0; i < 4; i++) {
        const int r = ty + i * 8;          // n
        const float v = t[tx][r];
        __half h = __float2half_rn(v);
        __half l = __float2half_rn(v - __half2float(h));
        const size_t dst = (size_t)(n0 + r) * FT + k0 + tx;
        Wth[dst] = h;
        Wtl[dst] = l;
    }
}

// V hi/lo [B*T, H] -> Vt hi/lo [B][H][T]
__global__ __launch_bounds__(256) void transpose_v(const __half* __restrict__ Vh,
                                                   const __half* __restrict__ Vl,
                                                   __half* __restrict__ Vth, __half* __restrict__ Vtl)
{
    __shared__ __half th[32][33], tl[32][33];
    const int b = blockIdx.z;
    const int h0 = blockIdx.x * 32, s0 = blockIdx.y * 32;
    const int tx = threadIdx.x & 31, ty = threadIdx.x >> 5;
    #pragma unroll
    for (int i = 0; i < 4; i++) {
        const int r = ty + i * 8;
        const size_t src = ((size_t)b * TT + s0 + r) * HD + h0 + tx;
        th[r][tx] = Vh[src];
        tl[r][tx] = Vl[src];
    }
    __syncthreads();
    #pragma unroll
    for (int i = 0; i < 4; i++) {
        const int r = ty + i * 8;          // h
        const size_t dst = ((size_t)b * HD + h0 + r) * TT + s0 + tx;
        Vth[dst] = th[tx][r];
        Vtl[dst] = tl[tx][r];
    }
}

// softmax over rows of 2048; writes P as plain fp16
__global__ __launch_bounds__(256) void softmax_k(const float* __restrict__ S,
                                                 __half* __restrict__ Ph)
{
    const size_t off = (size_t)blockIdx.x * TT;
    const int tid = threadIdx.x;
    const float* p = S + off + tid * 8;
    float v[8];
    float4 a = *reinterpret_cast<const float4*>(p);
    float4 b = *reinterpret_cast<const float4*>(p + 4);
    v[0] = a.x; v[1] = a.y; v[2] = a.z; v[3] = a.w;
    v[4] = b.x; v[5] = b.y; v[6] = b.z; v[7] = b.w;

    __shared__ float red[8];
    float m = v[0];
    #pragma unroll
    for (int i = 1; i < 8; i++) m = fmaxf(m, v[i]);
    #pragma unroll
    for (int o = 16; o > 0; o >>= 1) m = fmaxf(m, __shfl_xor_sync(0xffffffffu, m, o));
    if ((tid & 31) == 0) red[tid >> 5] = m;
    __syncthreads();
    float M = red[0];
    #pragma unroll
    for (int i = 1; i < 8; i++) M = fmaxf(M, red[i]);
    __syncthreads();

    float s = 0.f;
    #pragma unroll
    for (int i = 0; i < 8; i++) { v[i] = __expf(v[i] - M); s += v[i]; }
    #pragma unroll
    for (int o = 16; o > 0; o >>= 1) s += __shfl_xor_sync(0xffffffffu, s, o);
    if ((tid & 31) == 0) red[tid >> 5] = s;
    __syncthreads();
    float tot = 0.f;
    #pragma unroll
    for (int i = 0; i < 8; i++) tot += red[i];
    const float inv = __fdividef(1.0f, tot);

    __half* ph = Ph + off + tid * 8;
    #pragma unroll
    for (int i = 0; i < 8; i += 2) {
        __half2 t;
        t.x = __float2half_rn(v[i] * inv);
        t.y = __float2half_rn(v[i + 1] * inv);
        *reinterpret_cast<__half2*>(ph + i) = t;
    }
}

// ---------------- launch ----------------
extern "C" void kernel_launch(void* const* d_in, const int* in_sizes, int n_in,
                              void* d_out, int out_size)
{
    const float* q  = (const float*)d_in[0];
    const float* k  = (const float*)d_in[1];
    const float* v  = (const float*)d_in[2];
    const float* Wq = (const float*)d_in[3];
    const float* bq = (const float*)d_in[4];
    const float* Wk = (const float*)d_in[5];
    const float* bk = (const float*)d_in[6];
    const float* Wv = (const float*)d_in[7];
    const float* bv = (const float*)d_in[8];
    float* out = (float*)d_out;

    __half *qh, *ql, *kh, *kl, *vh, *vl;
    __half *wqh, *wql, *wkh, *wkl, *wvh, *wvl;
    __half *Qh, *Ql, *Kh, *Kl, *Vh, *Vl, *Vth, *Vtl, *Ph;
    float* S;
    cudaGetSymbolAddress((void**)&qh, g_qh);   cudaGetSymbolAddress((void**)&ql, g_ql);
    cudaGetSymbolAddress((void**)&kh, g_kh);   cudaGetSymbolAddress((void**)&kl, g_kl);
    cudaGetSymbolAddress((void**)&vh, g_vh);   cudaGetSymbolAddress((void**)&vl, g_vl);
    cudaGetSymbolAddress((void**)&wqh, g_Wqh); cudaGetSymbolAddress((void**)&wql, g_Wql);
    cudaGetSymbolAddress((void**)&wkh, g_Wkh); cudaGetSymbolAddress((void**)&wkl, g_Wkl);
    cudaGetSymbolAddress((void**)&wvh, g_Wvh); cudaGetSymbolAddress((void**)&wvl, g_Wvl);
    cudaGetSymbolAddress((void**)&Qh, g_Qh);   cudaGetSymbolAddress((void**)&Ql, g_Ql);
    cudaGetSymbolAddress((void**)&Kh, g_Kh);   cudaGetSymbolAddress((void**)&Kl, g_Kl);
    cudaGetSymbolAddress((void**)&Vh, g_Vh);   cudaGetSymbolAddress((void**)&Vl, g_Vl);
    cudaGetSymbolAddress((void**)&Vth, g_Vth); cudaGetSymbolAddress((void**)&Vtl, g_Vtl);
    cudaGetSymbolAddress((void**)&S, g_S);
    cudaGetSymbolAddress((void**)&Ph, g_Ph);

    cudaFuncSetAttribute((const void*)gemm_mma<0, 2>, cudaFuncAttributeMaxDynamicSharedMemorySize, GEMM_SMEM);
    cudaFuncSetAttribute((const void*)gemm_mma<0, 3>, cudaFuncAttributeMaxDynamicSharedMemorySize, GEMM_SMEM);
    cudaFuncSetAttribute((const void*)gemm_mma<1, 2>, cudaFuncAttributeMaxDynamicSharedMemorySize, GEMM_SMEM);

    // 1) split inputs (q: hi only — Q path is 2-term)
    fsplit_h<<<MTOT * FT / 1024, 256>>>(q, qh);
    fsplit<<<MTOT * FT / 1024, 256>>>(k, kh, kl);
    fsplit<<<MTOT * FT / 1024, 256>>>(v, vh, vl);
    // 2) transpose+split weights
    wsplit<<<dim3(16, 16), 256>>>(Wq, wqh, wql);
    wsplit<<<dim3(16, 16), 256>>>(Wk, wkh, wkl);
    wsplit<<<dim3(16, 16), 256>>>(Wv, wvh, wvl);
    // 3) projections (scale 0.25 folded into Q). Q: 2-term (q plain, W split); K,V: 3-term.
    dim3 gp(HD / 128, MTOT / 128, 1);
    gemm_mma<0, 2><<<gp, 256, GEMM_SMEM>>>(qh, qh, wqh, wql, FT, FT, 0, 0, FT,
                                           bq, 0.25f, nullptr, Qh, Ql, HD, 0);
    gemm_mma<0, 3><<<gp, 256, GEMM_SMEM>>>(kh, kl, wkh, wkl, FT, FT, 0, 0, FT,
                                           bk, 1.0f, nullptr, Kh, Kl, HD, 0);
    gemm_mma<0, 3><<<gp, 256, GEMM_SMEM>>>(vh, vl, wvh, wvl, FT, FT, 0, 0, FT,
                                           bv, 1.0f, nullptr, Vh, Vl, HD, 0);
    // 4) transpose V
    transpose_v<<<dim3(HD / 32, TT / 32, BZ), 256>>>(Vh, Vl, Vth, Vtl);
    // 5) energy S = (0.25 Q) K^T, 2-term (Q plain fp16, K split)
    dim3 ge(TT / 128, TT / 128, BZ);
    gemm_mma<1, 2><<<ge, 256, GEMM_SMEM>>>(Qh, Qh, Kh, Kl, HD, HD,
                                           (long)TT * HD, (long)TT * HD, HD,
                                           nullptr, 1.0f, S, nullptr, nullptr,
                                           TT, (long)TT * TT);
    // 6) softmax -> P plain fp16
    softmax_k<<<MTOT, 256>>>(S, Ph);
    // 7) out = P V, 2-term (P plain, V split)
    dim3 go(HD / 128, TT / 128, BZ);
    gemm_mma<1, 2><<<go, 256, GEMM_SMEM>>>(Ph, Ph, Vth, Vtl, TT, TT,
                                           (long)TT * TT, (long)HD * TT, TT,
                                           nullptr, 1.0f, out, nullptr, nullptr,
                                           HD, (long)TT * HD);
}

// round 11
// speedup vs baseline: 1.2162x; 1.0459x over previous
#include <cuda_runtime.h>
#include <cuda_fp16.h>
#include <stdint.h>

#define BZ 8
#define TT 2048
#define FT 512
#define HD 512
#define MTOT (BZ * TT)   // 16384

// ---------------- scratch (device globals; allocation-free) ----------------
__device__ __align__(16) __half g_qh[MTOT * FT];
__device__ __align__(16) __half g_kh[MTOT * FT], g_kl[MTOT * FT];
__device__ __align__(16) __half g_Gh[FT * HD], g_Gl[FT * HD];
__device__ __align__(16) __half g_Wvh[FT * HD], g_Wvl[FT * HD];
__device__ __align__(16) __half g_Qh[MTOT * HD], g_Ql[MTOT * HD];
__device__ __align__(16) __half g_Vth[(size_t)BZ * HD * TT], g_Vtl[(size_t)BZ * HD * TT];
__device__ __align__(16) __half g_Uh[MTOT * HD], g_Ul[MTOT * HD];
__device__ __align__(16) float g_S[(size_t)BZ * TT * TT];
__device__ __align__(16) __half g_Ph[(size_t)BZ * TT * TT];
__device__ __align__(16) float g_u[FT];
__device__ __align__(16) float g_col[MTOT];

// ---------------- helpers ----------------
__device__ __forceinline__ uint32_t smem_u32(const void* p) {
    uint32_t a;
    asm("{ .reg .u64 t; cvta.to.shared.u64 t, %1; cvt.u32.u64 %0, t; }" : "=r"(a) : "l"(p));
    return a;
}

#define CP16(dst, src) \
    asm volatile("cp.async.cg.shared.global [%0], [%1], 16;" :: "r"(dst), "l"(src) : "memory")

#define LDSM4(r, addr) \
    asm volatile("ldmatrix.sync.aligned.m8n8.x4.shared.b16 {%0,%1,%2,%3}, [%4];" \
                 : "=r"((r)[0]), "=r"((r)[1]), "=r"((r)[2]), "=r"((r)[3]) : "r"(addr))

#define MMAF32(d, a, b0, b1) \
    asm volatile("mma.sync.aligned.m16n8k16.row.col.f32.f16.f16.f32 " \
                 "{%0,%1,%2,%3}, {%4,%5,%6,%7}, {%8,%9}, {%0,%1,%2,%3};" \
                 : "+f"((d)[0]), "+f"((d)[1]), "+f"((d)[2]), "+f"((d)[3]) \
                 : "r"((a)[0]), "r"((a)[1]), "r"((a)[2]), "r"((a)[3]), "r"(b0), "r"(b1))

// ---------------- warp-MMA GEMM ----------------
// D[m,n] = sum_k A[m,k]*B[n,k], fp16 split, f32 accumulate.
// TERMS=3: Ah*Bh + Ah*Bl + Al*Bh   TERMS=2: Ah*Bh + Ah*Bl (A plain)
// MODE 0: out = (acc [+bias])*scale -> fp16 hi/lo (batched via sO)
// MODE 1: out = acc [+bias] -> fp32 (batched via sO)
static constexpr int TILE_B = 8192;             // 128 rows x 64 bytes
static constexpr int STAGE_B = 4 * TILE_B;      // 32 KB
static constexpr int GEMM_SMEM = 2 * STAGE_B;   // 64 KB

__device__ __forceinline__ void load_tile(uint32_t dstbase, const __half* src, int ld, int tid)
{
    #pragma unroll
    for (int j = 0; j < 2; j++) {
        const int seg = tid + j * 256;
        const int row = seg >> 2;
        const int colb = (seg & 3) * 16;
        const uint32_t off = (uint32_t)(row * 64 + colb);
        const uint32_t sw = off ^ ((off >> 3) & 0x30);
        CP16(dstbase + sw, (const char*)src + (long)row * ld * 2 + colb);
    }
}

template <int MODE, int TERMS>
__global__ __launch_bounds__(256, 2)
void gemm_mma(const __half* __restrict__ Ah, const __half* __restrict__ Al,
              const __half* __restrict__ Bh, const __half* __restrict__ Bl,
              int lda, int ldb, long sA, long sB, int K,
              const float* __restrict__ bias, float scale,
              float* __restrict__ outF, __half* __restrict__ outH, __half* __restrict__ outL,
              int ldo, long sO)
{
    extern __shared__ char smem[];
    const uint32_t sbase = smem_u32(smem);
    const int tid = threadIdx.x;
    const int wid = tid >> 5;
    const int L = tid & 31;
    const int bm = blockIdx.y * 128;
    const int bn = blockIdx.x * 128;
    const int wm = wid & 1;
    const int wn = wid >> 1;

    const __half* pAh = Ah + (long)blockIdx.z * sA + (long)bm * lda;
    const __half* pAl = Al + (long)blockIdx.z * sA + (long)bm * lda;
    const __half* pBh = Bh + (long)blockIdx.z * sB + (long)bn * ldb;
    const __half* pBl = Bl + (long)blockIdx.z * sB + (long)bn * ldb;

    const int lr = L & 15;
    const int lc = (L >> 4) * 16;
    uint32_t aoffu[4], apat[4], boffu[2], bpat[2];
    #pragma unroll
    for (int mt = 0; mt < 4; mt++) {
        const uint32_t off = (uint32_t)((wm * 64 + mt * 16 + lr) * 64 + lc);
        aoffu[mt] = off;
        apat[mt] = (off >> 3) & 0x30;
    }
    #pragma unroll
    for (int ng = 0; ng < 2; ng++) {
        const uint32_t off = (uint32_t)((wn * 32 + ng * 16 + lr) * 64 + lc);
        boffu[ng] = off;
        bpat[ng] = (off >> 3) & 0x30;
    }

    float acc[4][4][4];
    #pragma unroll
    for (int mt = 0; mt < 4; mt++)
        #pragma unroll
        for (int nt = 0; nt < 4; nt++)
            #pragma unroll
            for (int r = 0; r < 4; r++)
                acc[mt][nt][r] = 0.0f;

    const int nchunk = K / 32;

    load_tile(sbase + 0 * TILE_B, pAh, lda, tid);
    if (TERMS == 3) load_tile(sbase + 1 * TILE_B, pAl, lda, tid);
    load_tile(sbase + 2 * TILE_B, pBh, ldb, tid);
    load_tile(sbase + 3 * TILE_B, pBl, ldb, tid);
    asm volatile("cp.async.commit_group;" ::: "memory");

    for (int ck = 0; ck < nchunk; ck++) {
        const int buf = ck & 1;
        if (ck + 1 < nchunk) {
            const int k0 = (ck + 1) * 32;
            const uint32_t db = sbase + (buf ^ 1) * STAGE_B;
            load_tile(db + 0 * TILE_B, pAh + k0, lda, tid);
            if (TERMS == 3) load_tile(db + 1 * TILE_B, pAl + k0, lda, tid);
            load_tile(db + 2 * TILE_B, pBh + k0, ldb, tid);
            load_tile(db + 3 * TILE_B, pBl + k0, ldb, tid);
            asm volatile("cp.async.commit_group;" ::: "memory");
            asm volatile("cp.async.wait_group 1;" ::: "memory");
        } else {
            asm volatile("cp.async.wait_group 0;" ::: "memory");
        }
        __syncthreads();

        const uint32_t cb = sbase + buf * STAGE_B;
        #pragma unroll
        for (int kk = 0; kk < 2; kk++) {
            uint32_t bh[2][4], bl[2][4];
            #pragma unroll
            for (int ng = 0; ng < 2; ng++) {
                const uint32_t sw = (boffu[ng] + kk * 32) ^ bpat[ng];
                LDSM4(bh[ng], cb + 2 * TILE_B + sw);
                LDSM4(bl[ng], cb + 3 * TILE_B + sw);
            }
            #pragma unroll
            for (int mt = 0; mt < 4; mt++) {
                uint32_t ah[4], al[4];
                const uint32_t sw = (aoffu[mt] + kk * 32) ^ apat[mt];
                LDSM4(ah, cb + 0 * TILE_B + sw);
                if (TERMS == 3) LDSM4(al, cb + 1 * TILE_B + sw);
                #pragma unroll
                for (int nt = 0; nt < 4; nt++) {
                    const int ng = nt >> 1, h = nt & 1;
                    const uint32_t b0h = bh[ng][h], b1h = bh[ng][h + 2];
                    const uint32_t b0l = bl[ng][h], b1l = bl[ng][h + 2];
                    MMAF32(acc[mt][nt], ah, b0h, b1h);
                    MMAF32(acc[mt][nt], ah, b0l, b1l);
                    if (TERMS == 3) MMAF32(acc[mt][nt], al, b0h, b1h);
                }
            }
        }
        __syncthreads();
    }

    // epilogue
    const int r0 = bm + wm * 64 + (L >> 2);
    const int c0 = bn + wn * 32 + (L & 3) * 2;
    #pragma unroll
    for (int mt = 0; mt < 4; mt++) {
        #pragma unroll
        for (int nt = 0; nt < 4; nt++) {
            const int row = r0 + mt * 16;
            const int col = c0 + nt * 8;
            const float b0 = bias ? bias[col] : 0.0f;
            const float b1 = bias ? bias[col + 1] : 0.0f;
            if (MODE == 1) {
                float* po = outF + (size_t)blockIdx.z * sO;
                *reinterpret_cast<float2*>(po + (size_t)row * ldo + col) =
                    make_float2(acc[mt][nt][0] + b0, acc[mt][nt][1] + b1);
                *reinterpret_cast<float2*>(po + (size_t)(row + 8) * ldo + col) =
                    make_float2(acc[mt][nt][2] + b0, acc[mt][nt][3] + b1);
            } else {
                __half* poH = outH + (size_t)blockIdx.z * sO;
                __half* poL = outL + (size_t)blockIdx.z * sO;
                float x0 = (acc[mt][nt][0] + b0) * scale;
                float x1 = (acc[mt][nt][1] + b1) * scale;
                float x2 = (acc[mt][nt][2] + b0) * scale;
                float x3 = (acc[mt][nt][3] + b1) * scale;
                __half h0 = __float2half_rn(x0), h1 = __float2half_rn(x1);
                __half h2 = __float2half_rn(x2), h3 = __float2half_rn(x3);
                __half l0 = __float2half_rn(x0 - __half2float(h0));
                __half l1 = __float2half_rn(x1 - __half2float(h1));
                __half l2 = __float2half_rn(x2 - __half2float(h2));
                __half l3 = __float2half_rn(x3 - __half2float(h3));
                __half2 t;
                t.x = h0; t.y = h1;
                *reinterpret_cast<__half2*>(poH + (size_t)row * ldo + col) = t;
                t.x = h2; t.y = h3;
                *reinterpret_cast<__half2*>(poH + (size_t)(row + 8) * ldo + col) = t;
                t.x = l0; t.y = l1;
                *reinterpret_cast<__half2*>(poL + (size_t)row * ldo + col) = t;
                t.x = l2; t.y = l3;
                *reinterpret_cast<__half2*>(poL + (size_t)(row + 8) * ldo + col) = t;
            }
        }
    }
}

// ---------------- small kernels ----------------
__global__ __launch_bounds__(256) void fsplit(const float* __restrict__ x,
                                              __half* __restrict__ h, __half* __restrict__ l)
{
    const int i = (blockIdx.x * 256 + threadIdx.x) * 4;
    float4 v = *reinterpret_cast<const float4*>(x + i);
    __half h0 = __float2half_rn(v.x), h1 = __float2half_rn(v.y);
    __half h2 = __float2half_rn(v.z), h3 = __float2half_rn(v.w);
    __half l0 = __float2half_rn(v.x - __half2float(h0));
    __half l1 = __float2half_rn(v.y - __half2float(h1));
    __half l2 = __float2half_rn(v.z - __half2float(h2));
    __half l3 = __float2half_rn(v.w - __half2float(h3));
    __half2 a;
    a.x = h0; a.y = h1; *reinterpret_cast<__half2*>(h + i) = a;
    a.x = h2; a.y = h3; *reinterpret_cast<__half2*>(h + i + 2) = a;
    a.x = l0; a.y = l1; *reinterpret_cast<__half2*>(l + i) = a;
    a.x = l2; a.y = l3; *reinterpret_cast<__half2*>(l + i + 2) = a;
}

__global__ __launch_bounds__(256) void fsplit_h(const float* __restrict__ x,
                                                __half* __restrict__ h)
{
    const int i = (blockIdx.x * 256 + threadIdx.x) * 4;
    float4 v = *reinterpret_cast<const float4*>(x + i);
    __half2 a;
    a.x = __float2half_rn(v.x); a.y = __float2half_rn(v.y);
    *reinterpret_cast<__half2*>(h + i) = a;
    a.x = __float2half_rn(v.z); a.y = __float2half_rn(v.w);
    *reinterpret_cast<__half2*>(h + i + 2) = a;
}

// W [K=512, N=512] -> Wt hi/lo [N, K]  (B operand layout)
__global__ __launch_bounds__(256) void wsplit(const float* __restrict__ W,
                                              __half* __restrict__ Wth, __half* __restrict__ Wtl)
{
    __shared__ float t[32][33];
    const int n0 = blockIdx.x * 32, k0 = blockIdx.y * 32;
    const int tx = threadIdx.x & 31, ty = threadIdx.x >> 5;
    #pragma unroll
    for (int i = 0; i < 4; i++) {
        const int r = ty + i * 8;
        t[r][tx] = W[(size_t)(k0 + r) * HD + n0 + tx];
    }
    __syncthreads();
    #pragma unroll
    for (int i = 0; i < 4; i++) {
        const int r = ty + i * 8;
        const float v = t[tx][r];
        __half h = __float2half_rn(v);
        __half l = __float2half_rn(v - __half2float(h));
        const size_t dst = (size_t)(n0 + r) * FT + k0 + tx;
        Wth[dst] = h;
        Wtl[dst] = l;
    }
}

// G[a,b] = sum_h Wk[a,h]*Wq[b,h]  (= (Wq . Wk^T)^T, the B operand for Q'=q.G)
// fp32 accumulate, split to fp16 hi/lo. 16x16 output tile per block.
__global__ __launch_bounds__(256) void gemmG(const float* __restrict__ Wk_,
                                             const float* __restrict__ Wq_,
                                             __half* __restrict__ Gh, __half* __restrict__ Gl)
{
    __shared__ float sk[16][17], sq[16][17];
    const int a0 = blockIdx.y * 16, b0 = blockIdx.x * 16;
    const int tx = threadIdx.x & 15;
    const int ty = threadIdx.x >> 4;
    float acc = 0.0f;
    for (int h0 = 0; h0 < FT; h0 += 16) {
        sk[ty][tx] = Wk_[(size_t)(a0 + ty) * HD + h0 + tx];
        sq[ty][tx] = Wq_[(size_t)(b0 + ty) * HD + h0 + tx];
        __syncthreads();
        #pragma unroll
        for (int hh = 0; hh < 16; hh++)
            acc = fmaf(sk[ty][hh], sq[tx][hh], acc);
        __syncthreads();
    }
    __half h = __float2half_rn(acc);
    __half l = __float2half_rn(acc - __half2float(h));
    Gh[(size_t)(a0 + ty) * HD + b0 + tx] = h;
    Gl[(size_t)(a0 + ty) * HD + b0 + tx] = l;
}

// u[f] = sum_h Wk[f,h] * bq[h]
__global__ __launch_bounds__(256) void uvec(const float* __restrict__ Wk_,
                                            const float* __restrict__ bq,
                                            float* __restrict__ u)
{
    const int f = blockIdx.x * 8 + (threadIdx.x >> 5);
    const int lane = threadIdx.x & 31;
    float s = 0.0f;
    for (int j = lane; j < FT; j += 32) s = fmaf(Wk_[(size_t)f * HD + j], bq[j], s);
    #pragma unroll
    for (int o = 16; o > 0; o >>= 1) s += __shfl_xor_sync(0xffffffffu, s, o);
    if (lane == 0) u[f] = s;
}

// col[r] = 0.25 * dot(k[r,:], u)   (r over B*T rows)
__global__ __launch_bounds__(256) void colk(const float* __restrict__ k,
                                            const float* __restrict__ u,
                                            float* __restrict__ col)
{
    __shared__ float us[FT];
    for (int i = threadIdx.x; i < FT; i += 256) us[i] = u[i];
    __syncthreads();
    const int r = blockIdx.x * 8 + (threadIdx.x >> 5);
    const int lane = threadIdx.x & 31;
    const float* kr = k + (size_t)r * FT;
    float s = 0.0f;
    for (int j = lane; j < FT; j += 32) s = fmaf(kr[j], us[j], s);
    #pragma unroll
    for (int o = 16; o > 0; o >>= 1) s += __shfl_xor_sync(0xffffffffu, s, o);
    if (lane == 0) col[r] = 0.25f * s;
}

// v [B,T,F] fp32 -> Vt hi/lo [B][F][T] fp16 split
__global__ __launch_bounds__(256) void tsplit_v(const float* __restrict__ v,
                                                __half* __restrict__ Vth, __half* __restrict__ Vtl)
{
    __shared__ float t[32][33];
    const int b = blockIdx.z;
    const int h0 = blockIdx.x * 32, s0 = blockIdx.y * 32;
    const int tx = threadIdx.x & 31, ty = threadIdx.x >> 5;
    #pragma unroll
    for (int i = 0; i < 4; i++) {
        const int r = ty + i * 8;
        t[r][tx] = v[((size_t)b * TT + s0 + r) * FT + h0 + tx];
    }
    __syncthreads();
    #pragma unroll
    for (int i = 0; i < 4; i++) {
        const int r = ty + i * 8;          // h offset
        const float val = t[tx][r];
        __half h = __float2half_rn(val);
        __half l = __float2half_rn(val - __half2float(h));
        const size_t dst = ((size_t)b * HD + h0 + r) * TT + s0 + tx;
        Vth[dst] = h;
        Vtl[dst] = l;
    }
}

// softmax over rows of 2048 with per-key col-term added; writes P as plain fp16
__global__ __launch_bounds__(256) void softmax_k(const float* __restrict__ S,
                                                 const float* __restrict__ col,
                                                 __half* __restrict__ Ph)
{
    const size_t off = (size_t)blockIdx.x * TT;
    const int tid = threadIdx.x;
    const float* p = S + off + tid * 8;
    const float* cr = col + ((size_t)(blockIdx.x >> 11)) * TT + tid * 8;
    float v[8];
    float4 a = *reinterpret_cast<const float4*>(p);
    float4 b = *reinterpret_cast<const float4*>(p + 4);
    float4 ca = *reinterpret_cast<const float4*>(cr);
    float4 cb = *reinterpret_cast<const float4*>(cr + 4);
    v[0] = a.x + ca.x; v[1] = a.y + ca.y; v[2] = a.z + ca.z; v[3] = a.w + ca.w;
    v[4] = b.x + cb.x; v[5] = b.y + cb.y; v[6] = b.z + cb.z; v[7] = b.w + cb.w;

    __shared__ float red[8];
    float m = v[0];
    #pragma unroll
    for (int i = 1; i < 8; i++) m = fmaxf(m, v[i]);
    #pragma unroll
    for (int o = 16; o > 0; o >>= 1) m = fmaxf(m, __shfl_xor_sync(0xffffffffu, m, o));
    if ((tid & 31) == 0) red[tid >> 5] = m;
    __syncthreads();
    float M = red[0];
    #pragma unroll
    for (int i = 1; i < 8; i++) M = fmaxf(M, red[i]);
    __syncthreads();

    float s = 0.f;
    #pragma unroll
    for (int i = 0; i < 8; i++) { v[i] = __expf(v[i] - M); s += v[i]; }
    #pragma unroll
    for (int o = 16; o > 0; o >>= 1) s += __shfl_xor_sync(0xffffffffu, s, o);
    if ((tid & 31) == 0) red[tid >> 5] = s;
    __syncthreads();
    float tot = 0.f;
    #pragma unroll
    for (int i = 0; i < 8; i++) tot += red[i];
    const float inv = __fdividef(1.0f, tot);

    __half* ph = Ph + off + tid * 8;
    #pragma unroll
    for (int i = 0; i < 8; i += 2) {
        __half2 t;
        t.x = __float2half_rn(v[i] * inv);
        t.y = __float2half_rn(v[i + 1] * inv);
        *reinterpret_cast<__half2*>(ph + i) = t;
    }
}

// ---------------- launch ----------------
extern "C" void kernel_launch(void* const* d_in, const int* in_sizes, int n_in,
                              void* d_out, int out_size)
{
    const float* q  = (const float*)d_in[0];
    const float* k  = (const float*)d_in[1];
    const float* v  = (const float*)d_in[2];
    const float* Wq = (const float*)d_in[3];
    const float* bq = (const float*)d_in[4];
    const float* Wk = (const float*)d_in[5];
    // const float* bk = (const float*)d_in[6];   // cancels in softmax (row-constant)
    const float* Wv = (const float*)d_in[7];
    const float* bv = (const float*)d_in[8];
    float* out = (float*)d_out;

    __half *qh, *kh, *kl, *Gh, *Gl, *wvh, *wvl;
    __half *Qh, *Ql, *Vth, *Vtl, *Uh, *Ul, *Ph;
    float *S, *u, *col;
    cudaGetSymbolAddress((void**)&qh, g_qh);
    cudaGetSymbolAddress((void**)&kh, g_kh);   cudaGetSymbolAddress((void**)&kl, g_kl);
    cudaGetSymbolAddress((void**)&Gh, g_Gh);   cudaGetSymbolAddress((void**)&Gl, g_Gl);
    cudaGetSymbolAddress((void**)&wvh, g_Wvh); cudaGetSymbolAddress((void**)&wvl, g_Wvl);
    cudaGetSymbolAddress((void**)&Qh, g_Qh);   cudaGetSymbolAddress((void**)&Ql, g_Ql);
    cudaGetSymbolAddress((void**)&Vth, g_Vth); cudaGetSymbolAddress((void**)&Vtl, g_Vtl);
    cudaGetSymbolAddress((void**)&Uh, g_Uh);   cudaGetSymbolAddress((void**)&Ul, g_Ul);
    cudaGetSymbolAddress((void**)&S, g_S);
    cudaGetSymbolAddress((void**)&Ph, g_Ph);
    cudaGetSymbolAddress((void**)&u, g_u);
    cudaGetSymbolAddress((void**)&col, g_col);

    cudaFuncSetAttribute((const void*)gemm_mma<0, 2>, cudaFuncAttributeMaxDynamicSharedMemorySize, GEMM_SMEM);
    cudaFuncSetAttribute((const void*)gemm_mma<1, 2>, cudaFuncAttributeMaxDynamicSharedMemorySize, GEMM_SMEM);
    cudaFuncSetAttribute((const void*)gemm_mma<1, 3>, cudaFuncAttributeMaxDynamicSharedMemorySize, GEMM_SMEM);

    // 1) input conversions
    fsplit_h<<<MTOT * FT / 1024, 256>>>(q, qh);           // q plain (Q' is 2-term)
    fsplit<<<MTOT * FT / 1024, 256>>>(k, kh, kl);         // k split (S keeps k lo)
    wsplit<<<dim3(16, 16), 256>>>(Wv, wvh, wvl);          // Wv^T split (out GEMM B)
    tsplit_v<<<dim3(HD / 32, TT / 32, BZ), 256>>>(v, Vth, Vtl);  // v^T split (U GEMM B)
    // 2) folded-weight precomputes
    gemmG<<<dim3(HD / 16, FT / 16), 256>>>(Wk, Wq, Gh, Gl);      // G = (Wq Wk^T)^T
    uvec<<<FT / 8, 256>>>(Wk, bq, u);                            // u = Wk bq
    colk<<<MTOT / 8, 256>>>(k, u, col);                          // col = 0.25 k.u
    // 3) Q' = 0.25 * q.G   (2-term)
    gemm_mma<0, 2><<<dim3(HD / 128, MTOT / 128, 1), 256, GEMM_SMEM>>>(
        qh, qh, Gh, Gl, FT, FT, 0, 0, FT,
        nullptr, 0.25f, nullptr, Qh, Ql, HD, 0);
    // 4) S = Q'.k^T   (2-term, k split; col added in softmax)
    gemm_mma<1, 2><<<dim3(TT / 128, TT / 128, BZ), 256, GEMM_SMEM>>>(
        Qh, Qh, kh, kl, HD, FT, (long)TT * HD, (long)TT * FT, HD,
        nullptr, 1.0f, S, nullptr, nullptr, TT, (long)TT * TT);
    // 5) softmax(S + col) -> P fp16
    softmax_k<<<MTOT, 256>>>(S, col, Ph);
    // 6) U = P.v^T   (2-term, v split) -> fp16 hi/lo
    gemm_mma<0, 2><<<dim3(HD / 128, TT / 128, BZ), 256, GEMM_SMEM>>>(
        Ph, Ph, Vth, Vtl, TT, TT, (long)TT * TT, (long)HD * TT, TT,
        nullptr, 1.0f, nullptr, Uh, Ul, HD, (long)TT * HD);
    // 7) out = U.Wv + bv   (3-term: U split, Wv split)
    gemm_mma<1, 3><<<dim3(HD / 128, MTOT / 128, 1), 256, GEMM_SMEM>>>(
        Uh, Ul, wvh, wvl, HD, FT, 0, 0, FT,
        bv, 1.0f, out, nullptr, nullptr, HD, 0);
}

// round 12
// speedup vs baseline: 1.6713x; 1.3742x over previous
#include <cuda_runtime.h>
#include <cuda_fp16.h>
#include <stdint.h>

#define BZ 8
#define TT 2048
#define FT 512
#define HD 512
#define MTOT (BZ * TT)   // 16384

// ---------------- scratch (device globals; allocation-free) ----------------
__device__ __align__(16) __half g_qh[MTOT * FT];
__device__ __align__(16) __half g_kh[MTOT * FT];
__device__ __align__(16) __half g_Gh[FT * HD], g_Gl[FT * HD];
__device__ __align__(16) __half g_Wvh[FT * HD], g_Wvl[FT * HD];
__device__ __align__(16) __half g_Qh[MTOT * HD];
__device__ __align__(16) __half g_Vth[(size_t)BZ * HD * TT];
__device__ __align__(16) __half g_Uh[MTOT * HD];
__device__ __align__(16) float g_S[(size_t)BZ * TT * TT];
__device__ __align__(16) __half g_Ph[(size_t)BZ * TT * TT];
__device__ __align__(16) float g_u[FT];
__device__ __align__(16) float g_col[MTOT];

// ---------------- helpers ----------------
__device__ __forceinline__ uint32_t smem_u32(const void* p) {
    uint32_t a;
    asm("{ .reg .u64 t; cvta.to.shared.u64 t, %1; cvt.u32.u64 %0, t; }" : "=r"(a) : "l"(p));
    return a;
}

#define CP16(dst, src) \
    asm volatile("cp.async.cg.shared.global [%0], [%1], 16;" :: "r"(dst), "l"(src) : "memory")

#define LDSM4(r, addr) \
    asm volatile("ldmatrix.sync.aligned.m8n8.x4.shared.b16 {%0,%1,%2,%3}, [%4];" \
                 : "=r"((r)[0]), "=r"((r)[1]), "=r"((r)[2]), "=r"((r)[3]) : "r"(addr))

#define MMAF32(d, a, b0, b1) \
    asm volatile("mma.sync.aligned.m16n8k16.row.col.f32.f16.f16.f32 " \
                 "{%0,%1,%2,%3}, {%4,%5,%6,%7}, {%8,%9}, {%0,%1,%2,%3};" \
                 : "+f"((d)[0]), "+f"((d)[1]), "+f"((d)[2]), "+f"((d)[3]) \
                 : "r"((a)[0]), "r"((a)[1]), "r"((a)[2]), "r"((a)[3]), "r"(b0), "r"(b1))

// ---------------- warp-MMA GEMM ----------------
// D[m,n] = sum_k A[m,k]*B[n,k], A plain fp16, f32 accumulate.
// TERMS=1: A*Bh            TERMS=2: A*Bh + A*Bl (B split)
// MODE 1: out = acc [+bias] -> fp32 (batched via sO)
// MODE 2: out = acc*scale -> fp16 hi (batched via sO)
static constexpr int TILE_B = 8192;             // 128 rows x 64 bytes
static constexpr int STAGE_B = 3 * TILE_B;      // A, Bh, Bl = 24 KB
static constexpr int GEMM_SMEM = 2 * STAGE_B;   // 48 KB

__device__ __forceinline__ void load_tile(uint32_t dstbase, const __half* src, int ld, int tid)
{
    #pragma unroll
    for (int j = 0; j < 2; j++) {
        const int seg = tid + j * 256;
        const int row = seg >> 2;
        const int colb = (seg & 3) * 16;
        const uint32_t off = (uint32_t)(row * 64 + colb);
        const uint32_t sw = off ^ ((off >> 3) & 0x30);
        CP16(dstbase + sw, (const char*)src + (long)row * ld * 2 + colb);
    }
}

template <int MODE, int TERMS>
__global__ __launch_bounds__(256, 2)
void gemm_mma(const __half* __restrict__ Ah,
              const __half* __restrict__ Bh, const __half* __restrict__ Bl,
              int lda, int ldb, long sA, long sB, int K,
              const float* __restrict__ bias, float scale,
              float* __restrict__ outF, __half* __restrict__ outH,
              int ldo, long sO)
{
    extern __shared__ char smem[];
    const uint32_t sbase = smem_u32(smem);
    const int tid = threadIdx.x;
    const int wid = tid >> 5;
    const int L = tid & 31;
    const int bm = blockIdx.y * 128;
    const int bn = blockIdx.x * 128;
    const int wm = wid & 1;
    const int wn = wid >> 1;

    const __half* pA  = Ah + (long)blockIdx.z * sA + (long)bm * lda;
    const __half* pBh = Bh + (long)blockIdx.z * sB + (long)bn * ldb;
    const __half* pBl = (TERMS == 2) ? Bl + (long)blockIdx.z * sB + (long)bn * ldb : nullptr;

    const int lr = L & 15;
    const int lc = (L >> 4) * 16;
    uint32_t aoffu[4], apat[4], boffu[2], bpat[2];
    #pragma unroll
    for (int mt = 0; mt < 4; mt++) {
        const uint32_t off = (uint32_t)((wm * 64 + mt * 16 + lr) * 64 + lc);
        aoffu[mt] = off;
        apat[mt] = (off >> 3) & 0x30;
    }
    #pragma unroll
    for (int ng = 0; ng < 2; ng++) {
        const uint32_t off = (uint32_t)((wn * 32 + ng * 16 + lr) * 64 + lc);
        boffu[ng] = off;
        bpat[ng] = (off >> 3) & 0x30;
    }

    float acc[4][4][4];
    #pragma unroll
    for (int mt = 0; mt < 4; mt++)
        #pragma unroll
        for (int nt = 0; nt < 4; nt++)
            #pragma unroll
            for (int r = 0; r < 4; r++)
                acc[mt][nt][r] = 0.0f;

    const int nchunk = K / 32;

    load_tile(sbase + 0 * TILE_B, pA, lda, tid);
    load_tile(sbase + 1 * TILE_B, pBh, ldb, tid);
    if (TERMS == 2) load_tile(sbase + 2 * TILE_B, pBl, ldb, tid);
    asm volatile("cp.async.commit_group;" ::: "memory");

    for (int ck = 0; ck < nchunk; ck++) {
        const int buf = ck & 1;
        if (ck + 1 < nchunk) {
            const int k0 = (ck + 1) * 32;
            const uint32_t db = sbase + (buf ^ 1) * STAGE_B;
            load_tile(db + 0 * TILE_B, pA + k0, lda, tid);
            load_tile(db + 1 * TILE_B, pBh + k0, ldb, tid);
            if (TERMS == 2) load_tile(db + 2 * TILE_B, pBl + k0, ldb, tid);
            asm volatile("cp.async.commit_group;" ::: "memory");
            asm volatile("cp.async.wait_group 1;" ::: "memory");
        } else {
            asm volatile("cp.async.wait_group 0;" ::: "memory");
        }
        __syncthreads();

        const uint32_t cb = sbase + buf * STAGE_B;
        #pragma unroll
        for (int kk = 0; kk < 2; kk++) {
            uint32_t bh[2][4], bl[2][4];
            #pragma unroll
            for (int ng = 0; ng < 2; ng++) {
                const uint32_t sw = (boffu[ng] + kk * 32) ^ bpat[ng];
                LDSM4(bh[ng], cb + 1 * TILE_B + sw);
                if (TERMS == 2) LDSM4(bl[ng], cb + 2 * TILE_B + sw);
            }
            #pragma unroll
            for (int mt = 0; mt < 4; mt++) {
                uint32_t ah[4];
                const uint32_t sw = (aoffu[mt] + kk * 32) ^ apat[mt];
                LDSM4(ah, cb + 0 * TILE_B + sw);
                #pragma unroll
                for (int nt = 0; nt < 4; nt++) {
                    const int ng = nt >> 1, h = nt & 1;
                    MMAF32(acc[mt][nt], ah, bh[ng][h], bh[ng][h + 2]);
                    if (TERMS == 2)
                        MMAF32(acc[mt][nt], ah, bl[ng][h], bl[ng][h + 2]);
                }
            }
        }
        __syncthreads();
    }

    // epilogue
    const int r0 = bm + wm * 64 + (L >> 2);
    const int c0 = bn + wn * 32 + (L & 3) * 2;
    #pragma unroll
    for (int mt = 0; mt < 4; mt++) {
        #pragma unroll
        for (int nt = 0; nt < 4; nt++) {
            const int row = r0 + mt * 16;
            const int col = c0 + nt * 8;
            if (MODE == 1) {
                const float b0 = bias ? bias[col] : 0.0f;
                const float b1 = bias ? bias[col + 1] : 0.0f;
                float* po = outF + (size_t)blockIdx.z * sO;
                *reinterpret_cast<float2*>(po + (size_t)row * ldo + col) =
                    make_float2(acc[mt][nt][0] + b0, acc[mt][nt][1] + b1);
                *reinterpret_cast<float2*>(po + (size_t)(row + 8) * ldo + col) =
                    make_float2(acc[mt][nt][2] + b0, acc[mt][nt][3] + b1);
            } else {
                __half* po = outH + (size_t)blockIdx.z * sO;
                __half2 t;
                t.x = __float2half_rn(acc[mt][nt][0] * scale);
                t.y = __float2half_rn(acc[mt][nt][1] * scale);
                *reinterpret_cast<__half2*>(po + (size_t)row * ldo + col) = t;
                t.x = __float2half_rn(acc[mt][nt][2] * scale);
                t.y = __float2half_rn(acc[mt][nt][3] * scale);
                *reinterpret_cast<__half2*>(po + (size_t)(row + 8) * ldo + col) = t;
            }
        }
    }
}

// ---------------- small kernels ----------------
__global__ __launch_bounds__(256) void fsplit_h(const float* __restrict__ x,
                                                __half* __restrict__ h)
{
    const int i = (blockIdx.x * 256 + threadIdx.x) * 4;
    float4 v = *reinterpret_cast<const float4*>(x + i);
    __half2 a;
    a.x = __float2half_rn(v.x); a.y = __float2half_rn(v.y);
    *reinterpret_cast<__half2*>(h + i) = a;
    a.x = __float2half_rn(v.z); a.y = __float2half_rn(v.w);
    *reinterpret_cast<__half2*>(h + i + 2) = a;
}

// W [K=512, N=512] -> Wt hi/lo [N, K]  (B operand layout)
__global__ __launch_bounds__(256) void wsplit(const float* __restrict__ W,
                                              __half* __restrict__ Wth, __half* __restrict__ Wtl)
{
    __shared__ float t[32][33];
    const int n0 = blockIdx.x * 32, k0 = blockIdx.y * 32;
    const int tx = threadIdx.x & 31, ty = threadIdx.x >> 5;
    #pragma unroll
    for (int i = 0; i < 4; i++) {
        const int r = ty + i * 8;
        t[r][tx] = W[(size_t)(k0 + r) * HD + n0 + tx];
    }
    __syncthreads();
    #pragma unroll
    for (int i = 0; i < 4; i++) {
        const int r = ty + i * 8;
        const float v = t[tx][r];
        __half h = __float2half_rn(v);
        __half l = __float2half_rn(v - __half2float(h));
        const size_t dst = (size_t)(n0 + r) * FT + k0 + tx;
        Wth[dst] = h;
        Wtl[dst] = l;
    }
}

// G[a,b] = sum_h Wk[a,h]*Wq[b,h]; split to fp16 hi/lo
__global__ __launch_bounds__(256) void gemmG(const float* __restrict__ Wk_,
                                             const float* __restrict__ Wq_,
                                             __half* __restrict__ Gh, __half* __restrict__ Gl)
{
    __shared__ float sk[16][17], sq[16][17];
    const int a0 = blockIdx.y * 16, b0 = blockIdx.x * 16;
    const int tx = threadIdx.x & 15;
    const int ty = threadIdx.x >> 4;
    float acc = 0.0f;
    for (int h0 = 0; h0 < FT; h0 += 16) {
        sk[ty][tx] = Wk_[(size_t)(a0 + ty) * HD + h0 + tx];
        sq[ty][tx] = Wq_[(size_t)(b0 + ty) * HD + h0 + tx];
        __syncthreads();
        #pragma unroll
        for (int hh = 0; hh < 16; hh++)
            acc = fmaf(sk[ty][hh], sq[tx][hh], acc);
        __syncthreads();
    }
    __half h = __float2half_rn(acc);
    __half l = __float2half_rn(acc - __half2float(h));
    Gh[(size_t)(a0 + ty) * HD + b0 + tx] = h;
    Gl[(size_t)(a0 + ty) * HD + b0 + tx] = l;
}

// u[f] = sum_h Wk[f,h] * bq[h]
__global__ __launch_bounds__(256) void uvec(const float* __restrict__ Wk_,
                                            const float* __restrict__ bq,
                                            float* __restrict__ u)
{
    const int f = blockIdx.x * 8 + (threadIdx.x >> 5);
    const int lane = threadIdx.x & 31;
    float s = 0.0f;
    for (int j = lane; j < FT; j += 32) s = fmaf(Wk_[(size_t)f * HD + j], bq[j], s);
    #pragma unroll
    for (int o = 16; o > 0; o >>= 1) s += __shfl_xor_sync(0xffffffffu, s, o);
    if (lane == 0) u[f] = s;
}

// col[r] = 0.25 * dot(k[r,:], u)
__global__ __launch_bounds__(256) void colk(const float* __restrict__ k,
                                            const float* __restrict__ u,
                                            float* __restrict__ col)
{
    __shared__ float us[FT];
    for (int i = threadIdx.x; i < FT; i += 256) us[i] = u[i];
    __syncthreads();
    const int r = blockIdx.x * 8 + (threadIdx.x >> 5);
    const int lane = threadIdx.x & 31;
    const float* kr = k + (size_t)r * FT;
    float s = 0.0f;
    for (int j = lane; j < FT; j += 32) s = fmaf(kr[j], us[j], s);
    #pragma unroll
    for (int o = 16; o > 0; o >>= 1) s += __shfl_xor_sync(0xffffffffu, s, o);
    if (lane == 0) col[r] = 0.25f * s;
}

// v [B,T,F] fp32 -> Vt [B][F][T] plain fp16
__global__ __launch_bounds__(256) void tsplit_vh(const float* __restrict__ v,
                                                 __half* __restrict__ Vth)
{
    __shared__ float t[32][33];
    const int b = blockIdx.z;
    const int h0 = blockIdx.x * 32, s0 = blockIdx.y * 32;
    const int tx = threadIdx.x & 31, ty = threadIdx.x >> 5;
    #pragma unroll
    for (int i = 0; i < 4; i++) {
        const int r = ty + i * 8;
        t[r][tx] = v[((size_t)b * TT + s0 + r) * FT + h0 + tx];
    }
    __syncthreads();
    #pragma unroll
    for (int i = 0; i < 4; i++) {
        const int r = ty + i * 8;
        const size_t dst = ((size_t)b * HD + h0 + r) * TT + s0 + tx;
        Vth[dst] = __float2half_rn(t[tx][r]);
    }
}

// softmax over rows of 2048 with per-key col-term added; writes P as plain fp16
__global__ __launch_bounds__(256) void softmax_k(const float* __restrict__ S,
                                                 const float* __restrict__ col,
                                                 __half* __restrict__ Ph)
{
    const size_t off = (size_t)blockIdx.x * TT;
    const int tid = threadIdx.x;
    const float* p = S + off + tid * 8;
    const float* cr = col + ((size_t)(blockIdx.x >> 11)) * TT + tid * 8;
    float v[8];
    float4 a = *reinterpret_cast<const float4*>(p);
    float4 b = *reinterpret_cast<const float4*>(p + 4);
    float4 ca = *reinterpret_cast<const float4*>(cr);
    float4 cb = *reinterpret_cast<const float4*>(cr + 4);
    v[0] = a.x + ca.x; v[1] = a.y + ca.y; v[2] = a.z + ca.z; v[3] = a.w + ca.w;
    v[4] = b.x + cb.x; v[5] = b.y + cb.y; v[6] = b.z + cb.z; v[7] = b.w + cb.w;

    __shared__ float red[8];
    float m = v[0];
    #pragma unroll
    for (int i = 1; i < 8; i++) m = fmaxf(m, v[i]);
    #pragma unroll
    for (int o = 16; o > 0; o >>= 1) m = fmaxf(m, __shfl_xor_sync(0xffffffffu, m, o));
    if ((tid & 31) == 0) red[tid >> 5] = m;
    __syncthreads();
    float M = red[0];
    #pragma unroll
    for (int i = 1; i < 8; i++) M = fmaxf(M, red[i]);
    __syncthreads();

    float s = 0.f;
    #pragma unroll
    for (int i = 0; i < 8; i++) { v[i] = __expf(v[i] - M); s += v[i]; }
    #pragma unroll
    for (int o = 16; o > 0; o >>= 1) s += __shfl_xor_sync(0xffffffffu, s, o);
    if ((tid & 31) == 0) red[tid >> 5] = s;
    __syncthreads();
    float tot = 0.f;
    #pragma unroll
    for (int i = 0; i < 8; i++) tot += red[i];
    const float inv = __fdividef(1.0f, tot);

    __half* ph = Ph + off + tid * 8;
    #pragma unroll
    for (int i = 0; i < 8; i += 2) {
        __half2 t;
        t.x = __float2half_rn(v[i] * inv);
        t.y = __float2half_rn(v[i + 1] * inv);
        *reinterpret_cast<__half2*>(ph + i) = t;
    }
}

// ---------------- launch ----------------
extern "C" void kernel_launch(void* const* d_in, const int* in_sizes, int n_in,
                              void* d_out, int out_size)
{
    const float* q  = (const float*)d_in[0];
    const float* k  = (const float*)d_in[1];
    const float* v  = (const float*)d_in[2];
    const float* Wq = (const float*)d_in[3];
    const float* bq = (const float*)d_in[4];
    const float* Wk = (const float*)d_in[5];
    // bk cancels in softmax (row-constant)
    const float* Wv = (const float*)d_in[7];
    const float* bv = (const float*)d_in[8];
    float* out = (float*)d_out;

    __half *qh, *kh, *Gh, *Gl, *wvh, *wvl, *Qh, *Vth, *Uh, *Ph;
    float *S, *u, *col;
    cudaGetSymbolAddress((void**)&qh, g_qh);
    cudaGetSymbolAddress((void**)&kh, g_kh);
    cudaGetSymbolAddress((void**)&Gh, g_Gh);   cudaGetSymbolAddress((void**)&Gl, g_Gl);
    cudaGetSymbolAddress((void**)&wvh, g_Wvh); cudaGetSymbolAddress((void**)&wvl, g_Wvl);
    cudaGetSymbolAddress((void**)&Qh, g_Qh);
    cudaGetSymbolAddress((void**)&Vth, g_Vth);
    cudaGetSymbolAddress((void**)&Uh, g_Uh);
    cudaGetSymbolAddress((void**)&S, g_S);
    cudaGetSymbolAddress((void**)&Ph, g_Ph);
    cudaGetSymbolAddress((void**)&u, g_u);
    cudaGetSymbolAddress((void**)&col, g_col);

    cudaFuncSetAttribute((const void*)gemm_mma<2, 2>, cudaFuncAttributeMaxDynamicSharedMemorySize, GEMM_SMEM);
    cudaFuncSetAttribute((const void*)gemm_mma<1, 1>, cudaFuncAttributeMaxDynamicSharedMemorySize, GEMM_SMEM);
    cudaFuncSetAttribute((const void*)gemm_mma<2, 1>, cudaFuncAttributeMaxDynamicSharedMemorySize, GEMM_SMEM);
    cudaFuncSetAttribute((const void*)gemm_mma<1, 2>, cudaFuncAttributeMaxDynamicSharedMemorySize, GEMM_SMEM);

    // 1) input conversions
    fsplit_h<<<MTOT * FT / 1024, 256>>>(q, qh);                  // q plain
    fsplit_h<<<MTOT * FT / 1024, 256>>>(k, kh);                  // k plain (S is 1-term)
    wsplit<<<dim3(16, 16), 256>>>(Wv, wvh, wvl);                 // Wv^T split (out 2-term)
    tsplit_vh<<<dim3(HD / 32, TT / 32, BZ), 256>>>(v, Vth);      // v^T plain (U 1-term)
    // 2) folded-weight precomputes
    gemmG<<<dim3(HD / 16, FT / 16), 256>>>(Wk, Wq, Gh, Gl);      // G split (Q' 2-term)
    uvec<<<FT / 8, 256>>>(Wk, bq, u);
    colk<<<MTOT / 8, 256>>>(k, u, col);
    // 3) Q' = 0.25 q.G  (2-term, fp16-hi out)
    gemm_mma<2, 2><<<dim3(HD / 128, MTOT / 128, 1), 256, GEMM_SMEM>>>(
        qh, Gh, Gl, FT, FT, 0, 0, FT, nullptr, 0.25f, nullptr, Qh, HD, 0);
    // 4) S = Q'.k^T  (1-term; col added in softmax)
    gemm_mma<1, 1><<<dim3(TT / 128, TT / 128, BZ), 256, GEMM_SMEM>>>(
        Qh, kh, nullptr, HD, FT, (long)TT * HD, (long)TT * FT, HD,
        nullptr, 1.0f, S, nullptr, TT, (long)TT * TT);
    // 5) softmax(S + col) -> P fp16
    softmax_k<<<MTOT, 256>>>(S, col, Ph);
    // 6) U = P.v^T  (1-term, fp16-hi out)
    gemm_mma<2, 1><<<dim3(HD / 128, TT / 128, BZ), 256, GEMM_SMEM>>>(
        Ph, Vth, nullptr, TT, TT, (long)TT * TT, (long)HD * TT, TT,
        nullptr, 1.0f, nullptr, Uh, HD, (long)TT * HD);
    // 7) out = U.Wv + bv  (2-term: U plain, Wv split)
    gemm_mma<1, 2><<<dim3(HD / 128, MTOT / 128, 1), 256, GEMM_SMEM>>>(
        Uh, wvh, wvl, HD, FT, 0, 0, HD, bv, 1.0f, out, nullptr, HD, 0);
}

// round 13
// speedup vs baseline: 1.8051x; 1.0801x over previous
#include <cuda_runtime.h>
#include <cuda_fp16.h>
#include <stdint.h>

#define BZ 8
#define TT 2048
#define FT 512
#define HD 512
#define MTOT (BZ * TT)   // 16384

// ---------------- scratch (device globals; allocation-free) ----------------
__device__ __align__(16) __half g_qh[MTOT * FT];
__device__ __align__(16) __half g_kh[MTOT * FT];
__device__ __align__(16) __half g_Gh[FT * HD];
__device__ __align__(16) __half g_Wvh[FT * HD], g_Wvl[FT * HD];
__device__ __align__(16) __half g_Qh[MTOT * HD];
__device__ __align__(16) __half g_Vth[(size_t)BZ * HD * TT];
__device__ __align__(16) __half g_Uh[MTOT * HD];
__device__ __align__(16) float g_S[(size_t)BZ * TT * TT];
__device__ __align__(16) __half g_Ph[(size_t)BZ * TT * TT];
__device__ __align__(16) float g_u[FT];
__device__ __align__(16) float g_col[MTOT];

// ---------------- helpers ----------------
__device__ __forceinline__ uint32_t smem_u32(const void* p) {
    uint32_t a;
    asm("{ .reg .u64 t; cvta.to.shared.u64 t, %1; cvt.u32.u64 %0, t; }" : "=r"(a) : "l"(p));
    return a;
}

#define CP16(dst, src) \
    asm volatile("cp.async.cg.shared.global [%0], [%1], 16;" :: "r"(dst), "l"(src) : "memory")

#define LDSM4(r, addr) \
    asm volatile("ldmatrix.sync.aligned.m8n8.x4.shared.b16 {%0,%1,%2,%3}, [%4];" \
                 : "=r"((r)[0]), "=r"((r)[1]), "=r"((r)[2]), "=r"((r)[3]) : "r"(addr))

#define MMAF32(d, a, b0, b1) \
    asm volatile("mma.sync.aligned.m16n8k16.row.col.f32.f16.f16.f32 " \
                 "{%0,%1,%2,%3}, {%4,%5,%6,%7}, {%8,%9}, {%0,%1,%2,%3};" \
                 : "+f"((d)[0]), "+f"((d)[1]), "+f"((d)[2]), "+f"((d)[3]) \
                 : "r"((a)[0]), "r"((a)[1]), "r"((a)[2]), "r"((a)[3]), "r"(b0), "r"(b1))

// ---------------- warp-MMA GEMM ----------------
// D[m,n] = sum_k A[m,k]*B[n,k], A plain fp16, f32 accumulate.
// TERMS=1: A*Bh            TERMS=2: A*Bh + A*Bl (B split)
// MODE 1: out = acc [+bias] -> fp32 (batched via sO)
// MODE 2: out = acc*scale -> fp16 hi (batched via sO)
static constexpr int TILE_B = 8192;             // 128 rows x 64 bytes
static constexpr int STAGE_B = 3 * TILE_B;      // A, Bh, Bl = 24 KB
static constexpr int GEMM_SMEM = 2 * STAGE_B;   // 48 KB

__device__ __forceinline__ void load_tile(uint32_t dstbase, const __half* src, int ld, int tid)
{
    #pragma unroll
    for (int j = 0; j < 2; j++) {
        const int seg = tid + j * 256;
        const int row = seg >> 2;
        const int colb = (seg & 3) * 16;
        const uint32_t off = (uint32_t)(row * 64 + colb);
        const uint32_t sw = off ^ ((off >> 3) & 0x30);
        CP16(dstbase + sw, (const char*)src + (long)row * ld * 2 + colb);
    }
}

template <int MODE, int TERMS>
__global__ __launch_bounds__(256, 2)
void gemm_mma(const __half* __restrict__ Ah,
              const __half* __restrict__ Bh, const __half* __restrict__ Bl,
              int lda, int ldb, long sA, long sB, int K,
              const float* __restrict__ bias, float scale,
              float* __restrict__ outF, __half* __restrict__ outH,
              int ldo, long sO)
{
    extern __shared__ char smem[];
    const uint32_t sbase = smem_u32(smem);
    const int tid = threadIdx.x;
    const int wid = tid >> 5;
    const int L = tid & 31;
    const int bm = blockIdx.y * 128;
    const int bn = blockIdx.x * 128;
    const int wm = wid & 1;
    const int wn = wid >> 1;

    const __half* pA  = Ah + (long)blockIdx.z * sA + (long)bm * lda;
    const __half* pBh = Bh + (long)blockIdx.z * sB + (long)bn * ldb;
    const __half* pBl = (TERMS == 2) ? Bl + (long)blockIdx.z * sB + (long)bn * ldb : nullptr;

    const int lr = L & 15;
    const int lc = (L >> 4) * 16;
    uint32_t aoffu[4], apat[4], boffu[2], bpat[2];
    #pragma unroll
    for (int mt = 0; mt < 4; mt++) {
        const uint32_t off = (uint32_t)((wm * 64 + mt * 16 + lr) * 64 + lc);
        aoffu[mt] = off;
        apat[mt] = (off >> 3) & 0x30;
    }
    #pragma unroll
    for (int ng = 0; ng < 2; ng++) {
        const uint32_t off = (uint32_t)((wn * 32 + ng * 16 + lr) * 64 + lc);
        boffu[ng] = off;
        bpat[ng] = (off >> 3) & 0x30;
    }

    float acc[4][4][4];
    #pragma unroll
    for (int mt = 0; mt < 4; mt++)
        #pragma unroll
        for (int nt = 0; nt < 4; nt++)
            #pragma unroll
            for (int r = 0; r < 4; r++)
                acc[mt][nt][r] = 0.0f;

    const int nchunk = K / 32;

    load_tile(sbase + 0 * TILE_B, pA, lda, tid);
    load_tile(sbase + 1 * TILE_B, pBh, ldb, tid);
    if (TERMS == 2) load_tile(sbase + 2 * TILE_B, pBl, ldb, tid);
    asm volatile("cp.async.commit_group;" ::: "memory");

    for (int ck = 0; ck < nchunk; ck++) {
        const int buf = ck & 1;
        if (ck + 1 < nchunk) {
            const int k0 = (ck + 1) * 32;
            const uint32_t db = sbase + (buf ^ 1) * STAGE_B;
            load_tile(db + 0 * TILE_B, pA + k0, lda, tid);
            load_tile(db + 1 * TILE_B, pBh + k0, ldb, tid);
            if (TERMS == 2) load_tile(db + 2 * TILE_B, pBl + k0, ldb, tid);
            asm volatile("cp.async.commit_group;" ::: "memory");
            asm volatile("cp.async.wait_group 1;" ::: "memory");
        } else {
            asm volatile("cp.async.wait_group 0;" ::: "memory");
        }
        __syncthreads();

        const uint32_t cb = sbase + buf * STAGE_B;
        #pragma unroll
        for (int kk = 0; kk < 2; kk++) {
            uint32_t bh[2][4], bl[2][4];
            #pragma unroll
            for (int ng = 0; ng < 2; ng++) {
                const uint32_t sw = (boffu[ng] + kk * 32) ^ bpat[ng];
                LDSM4(bh[ng], cb + 1 * TILE_B + sw);
                if (TERMS == 2) LDSM4(bl[ng], cb + 2 * TILE_B + sw);
            }
            #pragma unroll
            for (int mt = 0; mt < 4; mt++) {
                uint32_t ah[4];
                const uint32_t sw = (aoffu[mt] + kk * 32) ^ apat[mt];
                LDSM4(ah, cb + 0 * TILE_B + sw);
                #pragma unroll
                for (int nt = 0; nt < 4; nt++) {
                    const int ng = nt >> 1, h = nt & 1;
                    MMAF32(acc[mt][nt], ah, bh[ng][h], bh[ng][h + 2]);
                    if (TERMS == 2)
                        MMAF32(acc[mt][nt], ah, bl[ng][h], bl[ng][h + 2]);
                }
            }
        }
        __syncthreads();
    }

    // epilogue
    const int r0 = bm + wm * 64 + (L >> 2);
    const int c0 = bn + wn * 32 + (L & 3) * 2;
    #pragma unroll
    for (int mt = 0; mt < 4; mt++) {
        #pragma unroll
        for (int nt = 0; nt < 4; nt++) {
            const int row = r0 + mt * 16;
            const int col = c0 + nt * 8;
            if (MODE == 1) {
                const float b0 = bias ? bias[col] : 0.0f;
                const float b1 = bias ? bias[col + 1] : 0.0f;
                float* po = outF + (size_t)blockIdx.z * sO;
                *reinterpret_cast<float2*>(po + (size_t)row * ldo + col) =
                    make_float2(acc[mt][nt][0] + b0, acc[mt][nt][1] + b1);
                *reinterpret_cast<float2*>(po + (size_t)(row + 8) * ldo + col) =
                    make_float2(acc[mt][nt][2] + b0, acc[mt][nt][3] + b1);
            } else {
                __half* po = outH + (size_t)blockIdx.z * sO;
                __half2 t;
                t.x = __float2half_rn(acc[mt][nt][0] * scale);
                t.y = __float2half_rn(acc[mt][nt][1] * scale);
                *reinterpret_cast<__half2*>(po + (size_t)row * ldo + col) = t;
                t.x = __float2half_rn(acc[mt][nt][2] * scale);
                t.y = __float2half_rn(acc[mt][nt][3] * scale);
                *reinterpret_cast<__half2*>(po + (size_t)(row + 8) * ldo + col) = t;
            }
        }
    }
}

// ---------------- small kernels ----------------
__global__ __launch_bounds__(256) void fsplit_h(const float* __restrict__ x,
                                                __half* __restrict__ h)
{
    const int i = (blockIdx.x * 256 + threadIdx.x) * 4;
    float4 v = *reinterpret_cast<const float4*>(x + i);
    __half2 a;
    a.x = __float2half_rn(v.x); a.y = __float2half_rn(v.y);
    *reinterpret_cast<__half2*>(h + i) = a;
    a.x = __float2half_rn(v.z); a.y = __float2half_rn(v.w);
    *reinterpret_cast<__half2*>(h + i + 2) = a;
}

// fused k prep: kh = fp16(k), col[r] = 0.25 * dot(k[r,:], u)
// block: 256 threads = 4 rows x 64 threads; each thread does 8 elems.
__global__ __launch_bounds__(256) void kprep(const float* __restrict__ k,
                                             const float* __restrict__ u,
                                             __half* __restrict__ kh,
                                             float* __restrict__ col)
{
    __shared__ float us[FT];
    __shared__ float part[4][2];
    for (int i = threadIdx.x; i < FT; i += 256) us[i] = u[i];
    __syncthreads();

    const int rl = threadIdx.x >> 6;         // 0..3 row within block
    const int t64 = threadIdx.x & 63;        // 0..63
    const size_t row = (size_t)blockIdx.x * 4 + rl;
    const size_t base = row * FT + t64 * 8;

    float4 a = *reinterpret_cast<const float4*>(k + base);
    float4 b = *reinterpret_cast<const float4*>(k + base + 4);
    __half2 h;
    h.x = __float2half_rn(a.x); h.y = __float2half_rn(a.y);
    *reinterpret_cast<__half2*>(kh + base) = h;
    h.x = __float2half_rn(a.z); h.y = __float2half_rn(a.w);
    *reinterpret_cast<__half2*>(kh + base + 2) = h;
    h.x = __float2half_rn(b.x); h.y = __float2half_rn(b.y);
    *reinterpret_cast<__half2*>(kh + base + 4) = h;
    h.x = __float2half_rn(b.z); h.y = __float2half_rn(b.w);
    *reinterpret_cast<__half2*>(kh + base + 6) = h;

    const int j = t64 * 8;
    float s = a.x * us[j] + a.y * us[j + 1] + a.z * us[j + 2] + a.w * us[j + 3]
            + b.x * us[j + 4] + b.y * us[j + 5] + b.z * us[j + 6] + b.w * us[j + 7];
    #pragma unroll
    for (int o = 16; o > 0; o >>= 1) s += __shfl_xor_sync(0xffffffffu, s, o);
    if ((threadIdx.x & 31) == 0) part[rl][(t64 >> 5)] = s;
    __syncthreads();
    if (threadIdx.x < 4)
        col[(size_t)blockIdx.x * 4 + threadIdx.x] =
            0.25f * (part[threadIdx.x][0] + part[threadIdx.x][1]);
}

// W [K=512, N=512] -> Wt hi/lo [N, K]  (B operand layout)
__global__ __launch_bounds__(256) void wsplit(const float* __restrict__ W,
                                              __half* __restrict__ Wth, __half* __restrict__ Wtl)
{
    __shared__ float t[32][33];
    const int n0 = blockIdx.x * 32, k0 = blockIdx.y * 32;
    const int tx = threadIdx.x & 31, ty = threadIdx.x >> 5;
    #pragma unroll
    for (int i = 0; i < 4; i++) {
        const int r = ty + i * 8;
        t[r][tx] = W[(size_t)(k0 + r) * HD + n0 + tx];
    }
    __syncthreads();
    #pragma unroll
    for (int i = 0; i < 4; i++) {
        const int r = ty + i * 8;
        const float v = t[tx][r];
        __half h = __float2half_rn(v);
        __half l = __float2half_rn(v - __half2float(h));
        const size_t dst = (size_t)(n0 + r) * FT + k0 + tx;
        Wth[dst] = h;
        Wtl[dst] = l;
    }
}

// G[a,b] = sum_h Wk[a,h]*Wq[b,h]; plain fp16 out
__global__ __launch_bounds__(256) void gemmG(const float* __restrict__ Wk_,
                                             const float* __restrict__ Wq_,
                                             __half* __restrict__ Gh)
{
    __shared__ float sk[16][17], sq[16][17];
    const int a0 = blockIdx.y * 16, b0 = blockIdx.x * 16;
    const int tx = threadIdx.x & 15;
    const int ty = threadIdx.x >> 4;
    float acc = 0.0f;
    for (int h0 = 0; h0 < FT; h0 += 16) {
        sk[ty][tx] = Wk_[(size_t)(a0 + ty) * HD + h0 + tx];
        sq[ty][tx] = Wq_[(size_t)(b0 + ty) * HD + h0 + tx];
        __syncthreads();
        #pragma unroll
        for (int hh = 0; hh < 16; hh++)
            acc = fmaf(sk[ty][hh], sq[tx][hh], acc);
        __syncthreads();
    }
    Gh[(size_t)(a0 + ty) * HD + b0 + tx] = __float2half_rn(acc);
}

// u[f] = sum_h Wk[f,h] * bq[h]
__global__ __launch_bounds__(256) void uvec(const float* __restrict__ Wk_,
                                            const float* __restrict__ bq,
                                            float* __restrict__ u)
{
    const int f = blockIdx.x * 8 + (threadIdx.x >> 5);
    const int lane = threadIdx.x & 31;
    float s = 0.0f;
    for (int j = lane; j < FT; j += 32) s = fmaf(Wk_[(size_t)f * HD + j], bq[j], s);
    #pragma unroll
    for (int o = 16; o > 0; o >>= 1) s += __shfl_xor_sync(0xffffffffu, s, o);
    if (lane == 0) u[f] = s;
}

// v [B,T,F] fp32 -> Vt [B][F][T] plain fp16
__global__ __launch_bounds__(256) void tsplit_vh(const float* __restrict__ v,
                                                 __half* __restrict__ Vth)
{
    __shared__ float t[32][33];
    const int b = blockIdx.z;
    const int h0 = blockIdx.x * 32, s0 = blockIdx.y * 32;
    const int tx = threadIdx.x & 31, ty = threadIdx.x >> 5;
    #pragma unroll
    for (int i = 0; i < 4; i++) {
        const int r = ty + i * 8;
        t[r][tx] = v[((size_t)b * TT + s0 + r) * FT + h0 + tx];
    }
    __syncthreads();
    #pragma unroll
    for (int i = 0; i < 4; i++) {
        const int r = ty + i * 8;
        const size_t dst = ((size_t)b * HD + h0 + r) * TT + s0 + tx;
        Vth[dst] = __float2half_rn(t[tx][r]);
    }
}

// softmax over rows of 2048 with per-key col-term added; writes P as plain fp16
__global__ __launch_bounds__(256) void softmax_k(const float* __restrict__ S,
                                                 const float* __restrict__ col,
                                                 __half* __restrict__ Ph)
{
    const size_t off = (size_t)blockIdx.x * TT;
    const int tid = threadIdx.x;
    const float* p = S + off + tid * 8;
    const float* cr = col + ((size_t)(blockIdx.x >> 11)) * TT + tid * 8;
    float v[8];
    float4 a = *reinterpret_cast<const float4*>(p);
    float4 b = *reinterpret_cast<const float4*>(p + 4);
    float4 ca = *reinterpret_cast<const float4*>(cr);
    float4 cb = *reinterpret_cast<const float4*>(cr + 4);
    v[0] = a.x + ca.x; v[1] = a.y + ca.y; v[2] = a.z + ca.z; v[3] = a.w + ca.w;
    v[4] = b.x + cb.x; v[5] = b.y + cb.y; v[6] = b.z + cb.z; v[7] = b.w + cb.w;

    __shared__ float red[8];
    float m = v[0];
    #pragma unroll
    for (int i = 1; i < 8; i++) m = fmaxf(m, v[i]);
    #pragma unroll
    for (int o = 16; o > 0; o >>= 1) m = fmaxf(m, __shfl_xor_sync(0xffffffffu, m, o));
    if ((tid & 31) == 0) red[tid >> 5] = m;
    __syncthreads();
    float M = red[0];
    #pragma unroll
    for (int i = 1; i < 8; i++) M = fmaxf(M, red[i]);
    __syncthreads();

    float s = 0.f;
    #pragma unroll
    for (int i = 0; i < 8; i++) { v[i] = __expf(v[i] - M); s += v[i]; }
    #pragma unroll
    for (int o = 16; o > 0; o >>= 1) s += __shfl_xor_sync(0xffffffffu, s, o);
    if ((tid & 31) == 0) red[tid >> 5] = s;
    __syncthreads();
    float tot = 0.f;
    #pragma unroll
    for (int i = 0; i < 8; i++) tot += red[i];
    const float inv = __fdividef(1.0f, tot);

    __half* ph = Ph + off + tid * 8;
    #pragma unroll
    for (int i = 0; i < 8; i += 2) {
        __half2 t;
        t.x = __float2half_rn(v[i] * inv);
        t.y = __float2half_rn(v[i + 1] * inv);
        *reinterpret_cast<__half2*>(ph + i) = t;
    }
}

// ---------------- launch ----------------
extern "C" void kernel_launch(void* const* d_in, const int* in_sizes, int n_in,
                              void* d_out, int out_size)
{
    const float* q  = (const float*)d_in[0];
    const float* k  = (const float*)d_in[1];
    const float* v  = (const float*)d_in[2];
    const float* Wq = (const float*)d_in[3];
    const float* bq = (const float*)d_in[4];
    const float* Wk = (const float*)d_in[5];
    // bk cancels in softmax (row-constant)
    const float* Wv = (const float*)d_in[7];
    const float* bv = (const float*)d_in[8];
    float* out = (float*)d_out;

    __half *qh, *kh, *Gh, *wvh, *wvl, *Qh, *Vth, *Uh, *Ph;
    float *S, *u, *col;
    cudaGetSymbolAddress((void**)&qh, g_qh);
    cudaGetSymbolAddress((void**)&kh, g_kh);
    cudaGetSymbolAddress((void**)&Gh, g_Gh);
    cudaGetSymbolAddress((void**)&wvh, g_Wvh); cudaGetSymbolAddress((void**)&wvl, g_Wvl);
    cudaGetSymbolAddress((void**)&Qh, g_Qh);
    cudaGetSymbolAddress((void**)&Vth, g_Vth);
    cudaGetSymbolAddress((void**)&Uh, g_Uh);
    cudaGetSymbolAddress((void**)&S, g_S);
    cudaGetSymbolAddress((void**)&Ph, g_Ph);
    cudaGetSymbolAddress((void**)&u, g_u);
    cudaGetSymbolAddress((void**)&col, g_col);

    cudaFuncSetAttribute((const void*)gemm_mma<2, 1>, cudaFuncAttributeMaxDynamicSharedMemorySize, GEMM_SMEM);
    cudaFuncSetAttribute((const void*)gemm_mma<1, 1>, cudaFuncAttributeMaxDynamicSharedMemorySize, GEMM_SMEM);
    cudaFuncSetAttribute((const void*)gemm_mma<1, 2>, cudaFuncAttributeMaxDynamicSharedMemorySize, GEMM_SMEM);

    // 1) precompute u (needed by kprep), then input conversions
    uvec<<<FT / 8, 256>>>(Wk, bq, u);
    fsplit_h<<<MTOT * FT / 1024, 256>>>(q, qh);                  // q plain
    kprep<<<MTOT / 4, 256>>>(k, u, kh, col);                     // k plain + col fused
    wsplit<<<dim3(16, 16), 256>>>(Wv, wvh, wvl);                 // Wv^T split (out 2-term)
    tsplit_vh<<<dim3(HD / 32, TT / 32, BZ), 256>>>(v, Vth);      // v^T plain
    gemmG<<<dim3(HD / 16, FT / 16), 256>>>(Wk, Wq, Gh);          // G plain (Q' 1-term)
    // 2) Q' = 0.25 q.G  (1-term, fp16-hi out)
    gemm_mma<2, 1><<<dim3(HD / 128, MTOT / 128, 1), 256, GEMM_SMEM>>>(
        qh, Gh, nullptr, FT, FT, 0, 0, FT, nullptr, 0.25f, nullptr, Qh, HD, 0);
    // 3) S = Q'.k^T  (1-term; col added in softmax)
    gemm_mma<1, 1><<<dim3(TT / 128, TT / 128, BZ), 256, GEMM_SMEM>>>(
        Qh, kh, nullptr, HD, FT, (long)TT * HD, (long)TT * FT, HD,
        nullptr, 1.0f, S, nullptr, TT, (long)TT * TT);
    // 4) softmax(S + col) -> P fp16
    softmax_k<<<MTOT, 256>>>(S, col, Ph);
    // 5) U = P.v^T  (1-term, fp16-hi out)
    gemm_mma<2, 1><<<dim3(HD / 128, TT / 128, BZ), 256, GEMM_SMEM>>>(
        Ph, Vth, nullptr, TT, TT, (long)TT * TT, (long)HD * TT, TT,
        nullptr, 1.0f, nullptr, Uh, HD, (long)TT * HD);
    // 6) out = U.Wv + bv  (2-term: U plain, Wv split)
    gemm_mma<1, 2><<<dim3(HD / 128, MTOT / 128, 1), 256, GEMM_SMEM>>>(
        Uh, wvh, wvl, HD, FT, 0, 0, HD, bv, 1.0f, out, nullptr, HD, 0);
}

// round 14
// speedup vs baseline: 1.8907x; 1.0474x over previous
#include <cuda_runtime.h>
#include <cuda_fp16.h>
#include <stdint.h>
#include <math.h>

#define BZ 8
#define TT 2048
#define FT 512
#define HD 512
#define MTOT (BZ * TT)   // 16384
#define ESHIFT 8.0f

// ---------------- scratch (device globals; allocation-free) ----------------
__device__ __align__(16) __half g_qh[MTOT * FT];
__device__ __align__(16) __half g_kh[MTOT * FT];
__device__ __align__(16) __half g_Gh[FT * HD];
__device__ __align__(16) __half g_Wvh[FT * HD], g_Wvl[FT * HD];
__device__ __align__(16) __half g_Qh[MTOT * HD];
__device__ __align__(16) __half g_Vth[(size_t)BZ * HD * TT];
__device__ __align__(16) __half g_Uh[MTOT * HD];
__device__ __align__(16) __half g_E[(size_t)BZ * TT * TT];      // exp(S - 8), fp16
__device__ __align__(16) float g_u[FT];
__device__ __align__(16) float g_col[MTOT];
__device__ __align__(16) float g_invZ[MTOT];

// ---------------- helpers ----------------
__device__ __forceinline__ uint32_t smem_u32(const void* p) {
    uint32_t a;
    asm("{ .reg .u64 t; cvta.to.shared.u64 t, %1; cvt.u32.u64 %0, t; }" : "=r"(a) : "l"(p));
    return a;
}

#define CP16(dst, src) \
    asm volatile("cp.async.cg.shared.global [%0], [%1], 16;" :: "r"(dst), "l"(src) : "memory")

#define LDSM4(r, addr) \
    asm volatile("ldmatrix.sync.aligned.m8n8.x4.shared.b16 {%0,%1,%2,%3}, [%4];" \
                 : "=r"((r)[0]), "=r"((r)[1]), "=r"((r)[2]), "=r"((r)[3]) : "r"(addr))

#define MMAF32(d, a, b0, b1) \
    asm volatile("mma.sync.aligned.m16n8k16.row.col.f32.f16.f16.f32 " \
                 "{%0,%1,%2,%3}, {%4,%5,%6,%7}, {%8,%9}, {%0,%1,%2,%3};" \
                 : "+f"((d)[0]), "+f"((d)[1]), "+f"((d)[2]), "+f"((d)[3]) \
                 : "r"((a)[0]), "r"((a)[1]), "r"((a)[2]), "r"((a)[3]), "r"(b0), "r"(b1))

// ---------------- warp-MMA GEMM ----------------
// D[m,n] = sum_k A[m,k]*B[n,k], A plain fp16, f32 accumulate.
// TERMS=1: A*Bh            TERMS=2: A*Bh + A*Bl (B split)
// MODE 1: out = acc [+ aux[col]] -> fp32
// MODE 2: out = acc*scale -> fp16
// MODE 3: out = fp16(exp(acc + aux[z*sAux+col] - ESHIFT))     (S -> E)
// MODE 4: out = fp16(acc * aux[z*sAux+row])                   (U with invZ)
static constexpr int TILE_B = 8192;             // 128 rows x 64 bytes
static constexpr int STAGE_B = 3 * TILE_B;      // A, Bh, Bl = 24 KB
static constexpr int GEMM_SMEM = 2 * STAGE_B;   // 48 KB

__device__ __forceinline__ void load_tile(uint32_t dstbase, const __half* src, int ld, int tid)
{
    #pragma unroll
    for (int j = 0; j < 2; j++) {
        const int seg = tid + j * 256;
        const int row = seg >> 2;
        const int colb = (seg & 3) * 16;
        const uint32_t off = (uint32_t)(row * 64 + colb);
        const uint32_t sw = off ^ ((off >> 3) & 0x30);
        CP16(dstbase + sw, (const char*)src + (long)row * ld * 2 + colb);
    }
}

template <int MODE, int TERMS>
__global__ __launch_bounds__(256, 2)
void gemm_mma(const __half* __restrict__ Ah,
              const __half* __restrict__ Bh, const __half* __restrict__ Bl,
              int lda, int ldb, long sA, long sB, int K,
              const float* __restrict__ aux, long sAux, float scale,
              float* __restrict__ outF, __half* __restrict__ outH,
              int ldo, long sO)
{
    extern __shared__ char smem[];
    const uint32_t sbase = smem_u32(smem);
    const int tid = threadIdx.x;
    const int wid = tid >> 5;
    const int L = tid & 31;
    const int bm = blockIdx.y * 128;
    const int bn = blockIdx.x * 128;
    const int wm = wid & 1;
    const int wn = wid >> 1;

    const __half* pA  = Ah + (long)blockIdx.z * sA + (long)bm * lda;
    const __half* pBh = Bh + (long)blockIdx.z * sB + (long)bn * ldb;
    const __half* pBl = (TERMS == 2) ? Bl + (long)blockIdx.z * sB + (long)bn * ldb : nullptr;

    const int lr = L & 15;
    const int lc = (L >> 4) * 16;
    uint32_t aoffu[4], apat[4], boffu[2], bpat[2];
    #pragma unroll
    for (int mt = 0; mt < 4; mt++) {
        const uint32_t off = (uint32_t)((wm * 64 + mt * 16 + lr) * 64 + lc);
        aoffu[mt] = off;
        apat[mt] = (off >> 3) & 0x30;
    }
    #pragma unroll
    for (int ng = 0; ng < 2; ng++) {
        const uint32_t off = (uint32_t)((wn * 32 + ng * 16 + lr) * 64 + lc);
        boffu[ng] = off;
        bpat[ng] = (off >> 3) & 0x30;
    }

    float acc[4][4][4];
    #pragma unroll
    for (int mt = 0; mt < 4; mt++)
        #pragma unroll
        for (int nt = 0; nt < 4; nt++)
            #pragma unroll
            for (int r = 0; r < 4; r++)
                acc[mt][nt][r] = 0.0f;

    const int nchunk = K / 32;

    load_tile(sbase + 0 * TILE_B, pA, lda, tid);
    load_tile(sbase + 1 * TILE_B, pBh, ldb, tid);
    if (TERMS == 2) load_tile(sbase + 2 * TILE_B, pBl, ldb, tid);
    asm volatile("cp.async.commit_group;" ::: "memory");

    for (int ck = 0; ck < nchunk; ck++) {
        const int buf = ck & 1;
        if (ck + 1 < nchunk) {
            const int k0 = (ck + 1) * 32;
            const uint32_t db = sbase + (buf ^ 1) * STAGE_B;
            load_tile(db + 0 * TILE_B, pA + k0, lda, tid);
            load_tile(db + 1 * TILE_B, pBh + k0, ldb, tid);
            if (TERMS == 2) load_tile(db + 2 * TILE_B, pBl + k0, ldb, tid);
            asm volatile("cp.async.commit_group;" ::: "memory");
            asm volatile("cp.async.wait_group 1;" ::: "memory");
        } else {
            asm volatile("cp.async.wait_group 0;" ::: "memory");
        }
        __syncthreads();

        const uint32_t cb = sbase + buf * STAGE_B;
        #pragma unroll
        for (int kk = 0; kk < 2; kk++) {
            uint32_t bh[2][4], bl[2][4];
            #pragma unroll
            for (int ng = 0; ng < 2; ng++) {
                const uint32_t sw = (boffu[ng] + kk * 32) ^ bpat[ng];
                LDSM4(bh[ng], cb + 1 * TILE_B + sw);
                if (TERMS == 2) LDSM4(bl[ng], cb + 2 * TILE_B + sw);
            }
            #pragma unroll
            for (int mt = 0; mt < 4; mt++) {
                uint32_t ah[4];
                const uint32_t sw = (aoffu[mt] + kk * 32) ^ apat[mt];
                LDSM4(ah, cb + 0 * TILE_B + sw);
                #pragma unroll
                for (int nt = 0; nt < 4; nt++) {
                    const int ng = nt >> 1, h = nt & 1;
                    MMAF32(acc[mt][nt], ah, bh[ng][h], bh[ng][h + 2]);
                    if (TERMS == 2)
                        MMAF32(acc[mt][nt], ah, bl[ng][h], bl[ng][h + 2]);
                }
            }
        }
        __syncthreads();
    }

    // epilogue
    const int r0 = bm + wm * 64 + (L >> 2);
    const int c0 = bn + wn * 32 + (L & 3) * 2;
    #pragma unroll
    for (int mt = 0; mt < 4; mt++) {
        #pragma unroll
        for (int nt = 0; nt < 4; nt++) {
            const int row = r0 + mt * 16;
            const int col = c0 + nt * 8;
            if (MODE == 1) {
                const float b0 = aux ? aux[col] : 0.0f;
                const float b1 = aux ? aux[col + 1] : 0.0f;
                float* po = outF + (size_t)blockIdx.z * sO;
                *reinterpret_cast<float2*>(po + (size_t)row * ldo + col) =
                    make_float2(acc[mt][nt][0] + b0, acc[mt][nt][1] + b1);
                *reinterpret_cast<float2*>(po + (size_t)(row + 8) * ldo + col) =
                    make_float2(acc[mt][nt][2] + b0, acc[mt][nt][3] + b1);
            } else if (MODE == 2) {
                __half* po = outH + (size_t)blockIdx.z * sO;
                __half2 t;
                t.x = __float2half_rn(acc[mt][nt][0] * scale);
                t.y = __float2half_rn(acc[mt][nt][1] * scale);
                *reinterpret_cast<__half2*>(po + (size_t)row * ldo + col) = t;
                t.x = __float2half_rn(acc[mt][nt][2] * scale);
                t.y = __float2half_rn(acc[mt][nt][3] * scale);
                *reinterpret_cast<__half2*>(po + (size_t)(row + 8) * ldo + col) = t;
            } else if (MODE == 3) {
                const float b0 = aux[blockIdx.z * sAux + col] - ESHIFT;
                const float b1 = aux[blockIdx.z * sAux + col + 1] - ESHIFT;
                __half* po = outH + (size_t)blockIdx.z * sO;
                __half2 t;
                t.x = __float2half_rn(__expf(acc[mt][nt][0] + b0));
                t.y = __float2half_rn(__expf(acc[mt][nt][1] + b1));
                *reinterpret_cast<__half2*>(po + (size_t)row * ldo + col) = t;
                t.x = __float2half_rn(__expf(acc[mt][nt][2] + b0));
                t.y = __float2half_rn(__expf(acc[mt][nt][3] + b1));
                *reinterpret_cast<__half2*>(po + (size_t)(row + 8) * ldo + col) = t;
            } else {  // MODE 4
                const float rs0 = aux[blockIdx.z * sAux + row];
                const float rs1 = aux[blockIdx.z * sAux + row + 8];
                __half* po = outH + (size_t)blockIdx.z * sO;
                __half2 t;
                t.x = __float2half_rn(acc[mt][nt][0] * rs0);
                t.y = __float2half_rn(acc[mt][nt][1] * rs0);
                *reinterpret_cast<__half2*>(po + (size_t)row * ldo + col) = t;
                t.x = __float2half_rn(acc[mt][nt][2] * rs1);
                t.y = __float2half_rn(acc[mt][nt][3] * rs1);
                *reinterpret_cast<__half2*>(po + (size_t)(row + 8) * ldo + col) = t;
            }
        }
    }
}

// ---------------- small kernels ----------------
__global__ __launch_bounds__(256) void fsplit_h(const float* __restrict__ x,
                                                __half* __restrict__ h)
{
    const int i = (blockIdx.x * 256 + threadIdx.x) * 4;
    float4 v = *reinterpret_cast<const float4*>(x + i);
    __half2 a;
    a.x = __float2half_rn(v.x); a.y = __float2half_rn(v.y);
    *reinterpret_cast<__half2*>(h + i) = a;
    a.x = __float2half_rn(v.z); a.y = __float2half_rn(v.w);
    *reinterpret_cast<__half2*>(h + i + 2) = a;
}

// fused k prep: kh = fp16(k), col[r] = 0.25 * dot(k[r,:], u)
__global__ __launch_bounds__(256) void kprep(const float* __restrict__ k,
                                             const float* __restrict__ u,
                                             __half* __restrict__ kh,
                                             float* __restrict__ col)
{
    __shared__ float us[FT];
    __shared__ float part[4][2];
    for (int i = threadIdx.x; i < FT; i += 256) us[i] = u[i];
    __syncthreads();

    const int rl = threadIdx.x >> 6;
    const int t64 = threadIdx.x & 63;
    const size_t row = (size_t)blockIdx.x * 4 + rl;
    const size_t base = row * FT + t64 * 8;

    float4 a = *reinterpret_cast<const float4*>(k + base);
    float4 b = *reinterpret_cast<const float4*>(k + base + 4);
    __half2 h;
    h.x = __float2half_rn(a.x); h.y = __float2half_rn(a.y);
    *reinterpret_cast<__half2*>(kh + base) = h;
    h.x = __float2half_rn(a.z); h.y = __float2half_rn(a.w);
    *reinterpret_cast<__half2*>(kh + base + 2) = h;
    h.x = __float2half_rn(b.x); h.y = __float2half_rn(b.y);
    *reinterpret_cast<__half2*>(kh + base + 4) = h;
    h.x = __float2half_rn(b.z); h.y = __float2half_rn(b.w);
    *reinterpret_cast<__half2*>(kh + base + 6) = h;

    const int j = t64 * 8;
    float s = a.x * us[j] + a.y * us[j + 1] + a.z * us[j + 2] + a.w * us[j + 3]
            + b.x * us[j + 4] + b.y * us[j + 5] + b.z * us[j + 6] + b.w * us[j + 7];
    #pragma unroll
    for (int o = 16; o > 0; o >>= 1) s += __shfl_xor_sync(0xffffffffu, s, o);
    if ((threadIdx.x & 31) == 0) part[rl][(t64 >> 5)] = s;
    __syncthreads();
    if (threadIdx.x < 4)
        col[(size_t)blockIdx.x * 4 + threadIdx.x] =
            0.25f * (part[threadIdx.x][0] + part[threadIdx.x][1]);
}

// W [K=512, N=512] -> Wt hi/lo [N, K]  (B operand layout)
__global__ __launch_bounds__(256) void wsplit(const float* __restrict__ W,
                                              __half* __restrict__ Wth, __half* __restrict__ Wtl)
{
    __shared__ float t[32][33];
    const int n0 = blockIdx.x * 32, k0 = blockIdx.y * 32;
    const int tx = threadIdx.x & 31, ty = threadIdx.x >> 5;
    #pragma unroll
    for (int i = 0; i < 4; i++) {
        const int r = ty + i * 8;
        t[r][tx] = W[(size_t)(k0 + r) * HD + n0 + tx];
    }
    __syncthreads();
    #pragma unroll
    for (int i = 0; i < 4; i++) {
        const int r = ty + i * 8;
        const float v = t[tx][r];
        __half h = __float2half_rn(v);
        __half l = __float2half_rn(v - __half2float(h));
        const size_t dst = (size_t)(n0 + r) * FT + k0 + tx;
        Wth[dst] = h;
        Wtl[dst] = l;
    }
}

// G[a,b] = sum_h Wk[a,h]*Wq[b,h]; plain fp16 out
__global__ __launch_bounds__(256) void gemmG(const float* __restrict__ Wk_,
                                             const float* __restrict__ Wq_,
                                             __half* __restrict__ Gh)
{
    __shared__ float sk[16][17], sq[16][17];
    const int a0 = blockIdx.y * 16, b0 = blockIdx.x * 16;
    const int tx = threadIdx.x & 15;
    const int ty = threadIdx.x >> 4;
    float acc = 0.0f;
    for (int h0 = 0; h0 < FT; h0 += 16) {
        sk[ty][tx] = Wk_[(size_t)(a0 + ty) * HD + h0 + tx];
        sq[ty][tx] = Wq_[(size_t)(b0 + ty) * HD + h0 + tx];
        __syncthreads();
        #pragma unroll
        for (int hh = 0; hh < 16; hh++)
            acc = fmaf(sk[ty][hh], sq[tx][hh], acc);
        __syncthreads();
    }
    Gh[(size_t)(a0 + ty) * HD + b0 + tx] = __float2half_rn(acc);
}

// u[f] = sum_h Wk[f,h] * bq[h]
__global__ __launch_bounds__(256) void uvec(const float* __restrict__ Wk_,
                                            const float* __restrict__ bq,
                                            float* __restrict__ u)
{
    const int f = blockIdx.x * 8 + (threadIdx.x >> 5);
    const int lane = threadIdx.x & 31;
    float s = 0.0f;
    for (int j = lane; j < FT; j += 32) s = fmaf(Wk_[(size_t)f * HD + j], bq[j], s);
    #pragma unroll
    for (int o = 16; o > 0; o >>= 1) s += __shfl_xor_sync(0xffffffffu, s, o);
    if (lane == 0) u[f] = s;
}

// v [B,T,F] fp32 -> Vt [B][F][T] plain fp16
__global__ __launch_bounds__(256) void tsplit_vh(const float* __restrict__ v,
                                                 __half* __restrict__ Vth)
{
    __shared__ float t[32][33];
    const int b = blockIdx.z;
    const int h0 = blockIdx.x * 32, s0 = blockIdx.y * 32;
    const int tx = threadIdx.x & 31, ty = threadIdx.x >> 5;
    #pragma unroll
    for (int i = 0; i < 4; i++) {
        const int r = ty + i * 8;
        t[r][tx] = v[((size_t)b * TT + s0 + r) * FT + h0 + tx];
    }
    __syncthreads();
    #pragma unroll
    for (int i = 0; i < 4; i++) {
        const int r = ty + i * 8;
        const size_t dst = ((size_t)b * HD + h0 + r) * TT + s0 + tx;
        Vth[dst] = __float2half_rn(t[tx][r]);
    }
}

// invZ[row] = 1 / sum(E[row, :])  (rows of 2048 fp16)
__global__ __launch_bounds__(256) void zsum(const __half* __restrict__ E,
                                            float* __restrict__ invZ)
{
    const size_t off = (size_t)blockIdx.x * TT;
    const int tid = threadIdx.x;
    const float4 raw = *reinterpret_cast<const float4*>(E + off + tid * 8);
    const __half2* hp = reinterpret_cast<const __half2*>(&raw);
    float s = 0.f;
    #pragma unroll
    for (int i = 0; i < 4; i++) {
        const float2 f = __half22float2(hp[i]);
        s += f.x + f.y;
    }
    #pragma unroll
    for (int o = 16; o > 0; o >>= 1) s += __shfl_xor_sync(0xffffffffu, s, o);
    __shared__ float red[8];
    if ((tid & 31) == 0) red[tid >> 5] = s;
    __syncthreads();
    if (tid == 0) {
        float tot = 0.f;
        #pragma unroll
        for (int i = 0; i < 8; i++) tot += red[i];
        invZ[blockIdx.x] = __fdividef(1.0f, tot);
    }
}

// ---------------- launch ----------------
extern "C" void kernel_launch(void* const* d_in, const int* in_sizes, int n_in,
                              void* d_out, int out_size)
{
    const float* q  = (const float*)d_in[0];
    const float* k  = (const float*)d_in[1];
    const float* v  = (const float*)d_in[2];
    const float* Wq = (const float*)d_in[3];
    const float* bq = (const float*)d_in[4];
    const float* Wk = (const float*)d_in[5];
    // bk cancels in softmax (row-constant)
    const float* Wv = (const float*)d_in[7];
    const float* bv = (const float*)d_in[8];
    float* out = (float*)d_out;

    __half *qh, *kh, *Gh, *wvh, *wvl, *Qh, *Vth, *Uh, *E;
    float *u, *col, *invZ;
    cudaGetSymbolAddress((void**)&qh, g_qh);
    cudaGetSymbolAddress((void**)&kh, g_kh);
    cudaGetSymbolAddress((void**)&Gh, g_Gh);
    cudaGetSymbolAddress((void**)&wvh, g_Wvh); cudaGetSymbolAddress((void**)&wvl, g_Wvl);
    cudaGetSymbolAddress((void**)&Qh, g_Qh);
    cudaGetSymbolAddress((void**)&Vth, g_Vth);
    cudaGetSymbolAddress((void**)&Uh, g_Uh);
    cudaGetSymbolAddress((void**)&E, g_E);
    cudaGetSymbolAddress((void**)&u, g_u);
    cudaGetSymbolAddress((void**)&col, g_col);
    cudaGetSymbolAddress((void**)&invZ, g_invZ);

    cudaFuncSetAttribute((const void*)gemm_mma<2, 1>, cudaFuncAttributeMaxDynamicSharedMemorySize, GEMM_SMEM);
    cudaFuncSetAttribute((const void*)gemm_mma<3, 1>, cudaFuncAttributeMaxDynamicSharedMemorySize, GEMM_SMEM);
    cudaFuncSetAttribute((const void*)gemm_mma<4, 1>, cudaFuncAttributeMaxDynamicSharedMemorySize, GEMM_SMEM);
    cudaFuncSetAttribute((const void*)gemm_mma<1, 2>, cudaFuncAttributeMaxDynamicSharedMemorySize, GEMM_SMEM);

    // 1) precompute u, then input conversions
    uvec<<<FT / 8, 256>>>(Wk, bq, u);
    fsplit_h<<<MTOT * FT / 1024, 256>>>(q, qh);                  // q plain
    kprep<<<MTOT / 4, 256>>>(k, u, kh, col);                     // k plain + col fused
    wsplit<<<dim3(16, 16), 256>>>(Wv, wvh, wvl);                 // Wv^T split (out 2-term)
    tsplit_vh<<<dim3(HD / 32, TT / 32, BZ), 256>>>(v, Vth);      // v^T plain
    gemmG<<<dim3(HD / 16, FT / 16), 256>>>(Wk, Wq, Gh);          // G plain (Q' 1-term)
    // 2) Q' = 0.25 q.G
    gemm_mma<2, 1><<<dim3(HD / 128, MTOT / 128, 1), 256, GEMM_SMEM>>>(
        qh, Gh, nullptr, FT, FT, 0, 0, FT, nullptr, 0, 0.25f, nullptr, Qh, HD, 0);
    // 3) E = exp(Q'.k^T + col - 8)  (fused exp epilogue, fp16 out)
    gemm_mma<3, 1><<<dim3(TT / 128, TT / 128, BZ), 256, GEMM_SMEM>>>(
        Qh, kh, nullptr, HD, FT, (long)TT * HD, (long)TT * FT, HD,
        col, TT, 1.0f, nullptr, E, TT, (long)TT * TT);
    // 4) invZ = 1 / rowsum(E)
    zsum<<<MTOT, 256>>>(E, invZ);
    // 5) U = (E.v^T) * invZ[row]  (softmax normalization folded into epilogue)
    gemm_mma<4, 1><<<dim3(HD / 128, TT / 128, BZ), 256, GEMM_SMEM>>>(
        E, Vth, nullptr, TT, TT, (long)TT * TT, (long)HD * TT, TT,
        invZ, TT, 1.0f, nullptr, Uh, HD, (long)TT * HD);
    // 6) out = U.Wv + bv  (2-term: U plain, Wv split)
    gemm_mma<1, 2><<<dim3(HD / 128, MTOT / 128, 1), 256, GEMM_SMEM>>>(
        Uh, wvh, wvl, HD, FT, 0, 0, HD, bv, 0, 1.0f, out, nullptr, HD, 0);
}

// round 15
// speedup vs baseline: 1.9958x; 1.0556x over previous
#include <cuda_runtime.h>
#include <cuda_fp16.h>
#include <stdint.h>
#include <math.h>

#define BZ 8
#define TT 2048
#define FT 512
#define HD 512
#define MTOT (BZ * TT)   // 16384
#define ESHIFT 8.0f

// ---------------- scratch (device globals; allocation-free) ----------------
__device__ __align__(16) __half g_qh[MTOT * FT];
__device__ __align__(16) __half g_kh[MTOT * FT];
__device__ __align__(16) __half g_vh[MTOT * FT];
__device__ __align__(16) __half g_Gh[FT * HD];
__device__ __align__(16) __half g_Wvh[FT * HD];
__device__ __align__(16) __half g_Qh[MTOT * HD];
__device__ __align__(16) __half g_Yt[(size_t)BZ * HD * TT];     // (v.Wv)^T per batch
__device__ __align__(16) __half g_E[(size_t)BZ * TT * TT];      // exp(S - 8), fp16
__device__ __align__(16) float g_u[FT];
__device__ __align__(16) float g_col[MTOT];
__device__ __align__(16) float g_invZ[MTOT];

// ---------------- helpers ----------------
__device__ __forceinline__ uint32_t smem_u32(const void* p) {
    uint32_t a;
    asm("{ .reg .u64 t; cvta.to.shared.u64 t, %1; cvt.u32.u64 %0, t; }" : "=r"(a) : "l"(p));
    return a;
}

#define CP16(dst, src) \
    asm volatile("cp.async.cg.shared.global [%0], [%1], 16;" :: "r"(dst), "l"(src) : "memory")

#define LDSM4(r, addr) \
    asm volatile("ldmatrix.sync.aligned.m8n8.x4.shared.b16 {%0,%1,%2,%3}, [%4];" \
                 : "=r"((r)[0]), "=r"((r)[1]), "=r"((r)[2]), "=r"((r)[3]) : "r"(addr))

#define MMAF32(d, a, b0, b1) \
    asm volatile("mma.sync.aligned.m16n8k16.row.col.f32.f16.f16.f32 " \
                 "{%0,%1,%2,%3}, {%4,%5,%6,%7}, {%8,%9}, {%0,%1,%2,%3};" \
                 : "+f"((d)[0]), "+f"((d)[1]), "+f"((d)[2]), "+f"((d)[3]) \
                 : "r"((a)[0]), "r"((a)[1]), "r"((a)[2]), "r"((a)[3]), "r"(b0), "r"(b1))

// ---------------- warp-MMA GEMM ----------------
// D[m,n] = sum_k A[m,k]*B[n,k], A/B plain fp16, f32 accumulate (1-term).
// MODE 2: out = acc*scale -> fp16
// MODE 3: out = fp16(exp(acc + aux[z*sAux+col] - ESHIFT))          (S -> E)
// MODE 5: out = acc * aux[z*sAux+row] + bias[col] -> fp32          (final)
static constexpr int TILE_B = 8192;             // 128 rows x 64 bytes
static constexpr int STAGE_B = 2 * TILE_B;      // A, B = 16 KB
static constexpr int GEMM_SMEM = 2 * STAGE_B;   // 32 KB

__device__ __forceinline__ void load_tile(uint32_t dstbase, const __half* src, int ld, int tid)
{
    #pragma unroll
    for (int j = 0; j < 2; j++) {
        const int seg = tid + j * 256;
        const int row = seg >> 2;
        const int colb = (seg & 3) * 16;
        const uint32_t off = (uint32_t)(row * 64 + colb);
        const uint32_t sw = off ^ ((off >> 3) & 0x30);
        CP16(dstbase + sw, (const char*)src + (long)row * ld * 2 + colb);
    }
}

template <int MODE>
__global__ __launch_bounds__(256, 2)
void gemm_mma(const __half* __restrict__ Ah, const __half* __restrict__ Bh,
              int lda, int ldb, long sA, long sB, int K,
              const float* __restrict__ aux, long sAux,
              const float* __restrict__ bias, float scale,
              float* __restrict__ outF, __half* __restrict__ outH,
              int ldo, long sO)
{
    extern __shared__ char smem[];
    const uint32_t sbase = smem_u32(smem);
    const int tid = threadIdx.x;
    const int wid = tid >> 5;
    const int L = tid & 31;
    const int bm = blockIdx.y * 128;
    const int bn = blockIdx.x * 128;
    const int wm = wid & 1;
    const int wn = wid >> 1;

    const __half* pA = Ah + (long)blockIdx.z * sA + (long)bm * lda;
    const __half* pB = Bh + (long)blockIdx.z * sB + (long)bn * ldb;

    const int lr = L & 15;
    const int lc = (L >> 4) * 16;
    uint32_t aoffu[4], apat[4], boffu[2], bpat[2];
    #pragma unroll
    for (int mt = 0; mt < 4; mt++) {
        const uint32_t off = (uint32_t)((wm * 64 + mt * 16 + lr) * 64 + lc);
        aoffu[mt] = off;
        apat[mt] = (off >> 3) & 0x30;
    }
    #pragma unroll
    for (int ng = 0; ng < 2; ng++) {
        const uint32_t off = (uint32_t)((wn * 32 + ng * 16 + lr) * 64 + lc);
        boffu[ng] = off;
        bpat[ng] = (off >> 3) & 0x30;
    }

    float acc[4][4][4];
    #pragma unroll
    for (int mt = 0; mt < 4; mt++)
        #pragma unroll
        for (int nt = 0; nt < 4; nt++)
            #pragma unroll
            for (int r = 0; r < 4; r++)
                acc[mt][nt][r] = 0.0f;

    const int nchunk = K / 32;

    load_tile(sbase + 0 * TILE_B, pA, lda, tid);
    load_tile(sbase + 1 * TILE_B, pB, ldb, tid);
    asm volatile("cp.async.commit_group;" ::: "memory");

    for (int ck = 0; ck < nchunk; ck++) {
        const int buf = ck & 1;
        if (ck + 1 < nchunk) {
            const int k0 = (ck + 1) * 32;
            const uint32_t db = sbase + (buf ^ 1) * STAGE_B;
            load_tile(db + 0 * TILE_B, pA + k0, lda, tid);
            load_tile(db + 1 * TILE_B, pB + k0, ldb, tid);
            asm volatile("cp.async.commit_group;" ::: "memory");
            asm volatile("cp.async.wait_group 1;" ::: "memory");
        } else {
            asm volatile("cp.async.wait_group 0;" ::: "memory");
        }
        __syncthreads();

        const uint32_t cb = sbase + buf * STAGE_B;
        #pragma unroll
        for (int kk = 0; kk < 2; kk++) {
            uint32_t bh[2][4];
            #pragma unroll
            for (int ng = 0; ng < 2; ng++) {
                const uint32_t sw = (boffu[ng] + kk * 32) ^ bpat[ng];
                LDSM4(bh[ng], cb + 1 * TILE_B + sw);
            }
            #pragma unroll
            for (int mt = 0; mt < 4; mt++) {
                uint32_t ah[4];
                const uint32_t sw = (aoffu[mt] + kk * 32) ^ apat[mt];
                LDSM4(ah, cb + 0 * TILE_B + sw);
                #pragma unroll
                for (int nt = 0; nt < 4; nt++) {
                    const int ng = nt >> 1, h = nt & 1;
                    MMAF32(acc[mt][nt], ah, bh[ng][h], bh[ng][h + 2]);
                }
            }
        }
        __syncthreads();
    }

    // epilogue
    const int r0 = bm + wm * 64 + (L >> 2);
    const int c0 = bn + wn * 32 + (L & 3) * 2;
    #pragma unroll
    for (int mt = 0; mt < 4; mt++) {
        #pragma unroll
        for (int nt = 0; nt < 4; nt++) {
            const int row = r0 + mt * 16;
            const int col = c0 + nt * 8;
            if (MODE == 2) {
                __half* po = outH + (size_t)blockIdx.z * sO;
                __half2 t;
                t.x = __float2half_rn(acc[mt][nt][0] * scale);
                t.y = __float2half_rn(acc[mt][nt][1] * scale);
                *reinterpret_cast<__half2*>(po + (size_t)row * ldo + col) = t;
                t.x = __float2half_rn(acc[mt][nt][2] * scale);
                t.y = __float2half_rn(acc[mt][nt][3] * scale);
                *reinterpret_cast<__half2*>(po + (size_t)(row + 8) * ldo + col) = t;
            } else if (MODE == 3) {
                const float b0 = aux[blockIdx.z * sAux + col] - ESHIFT;
                const float b1 = aux[blockIdx.z * sAux + col + 1] - ESHIFT;
                __half* po = outH + (size_t)blockIdx.z * sO;
                __half2 t;
                t.x = __float2half_rn(__expf(acc[mt][nt][0] + b0));
                t.y = __float2half_rn(__expf(acc[mt][nt][1] + b1));
                *reinterpret_cast<__half2*>(po + (size_t)row * ldo + col) = t;
                t.x = __float2half_rn(__expf(acc[mt][nt][2] + b0));
                t.y = __float2half_rn(__expf(acc[mt][nt][3] + b1));
                *reinterpret_cast<__half2*>(po + (size_t)(row + 8) * ldo + col) = t;
            } else {  // MODE 5: final output
                const float rs0 = aux[blockIdx.z * sAux + row];
                const float rs1 = aux[blockIdx.z * sAux + row + 8];
                const float b0 = bias[col], b1 = bias[col + 1];
                float* po = outF + (size_t)blockIdx.z * sO;
                *reinterpret_cast<float2*>(po + (size_t)row * ldo + col) =
                    make_float2(fmaf(acc[mt][nt][0], rs0, b0),
                                fmaf(acc[mt][nt][1], rs0, b1));
                *reinterpret_cast<float2*>(po + (size_t)(row + 8) * ldo + col) =
                    make_float2(fmaf(acc[mt][nt][2], rs1, b0),
                                fmaf(acc[mt][nt][3], rs1, b1));
            }
        }
    }
}

// ---------------- small kernels ----------------
__global__ __launch_bounds__(256) void fsplit_h(const float* __restrict__ x,
                                                __half* __restrict__ h)
{
    const int i = (blockIdx.x * 256 + threadIdx.x) * 4;
    float4 v = *reinterpret_cast<const float4*>(x + i);
    __half2 a;
    a.x = __float2half_rn(v.x); a.y = __float2half_rn(v.y);
    *reinterpret_cast<__half2*>(h + i) = a;
    a.x = __float2half_rn(v.z); a.y = __float2half_rn(v.w);
    *reinterpret_cast<__half2*>(h + i + 2) = a;
}

// fused k prep: kh = fp16(k), col[r] = 0.25 * dot(k[r,:], u)
__global__ __launch_bounds__(256) void kprep(const float* __restrict__ k,
                                             const float* __restrict__ u,
                                             __half* __restrict__ kh,
                                             float* __restrict__ col)
{
    __shared__ float us[FT];
    __shared__ float part[4][2];
    for (int i = threadIdx.x; i < FT; i += 256) us[i] = u[i];
    __syncthreads();

    const int rl = threadIdx.x >> 6;
    const int t64 = threadIdx.x & 63;
    const size_t row = (size_t)blockIdx.x * 4 + rl;
    const size_t base = row * FT + t64 * 8;

    float4 a = *reinterpret_cast<const float4*>(k + base);
    float4 b = *reinterpret_cast<const float4*>(k + base + 4);
    __half2 h;
    h.x = __float2half_rn(a.x); h.y = __float2half_rn(a.y);
    *reinterpret_cast<__half2*>(kh + base) = h;
    h.x = __float2half_rn(a.z); h.y = __float2half_rn(a.w);
    *reinterpret_cast<__half2*>(kh + base + 2) = h;
    h.x = __float2half_rn(b.x); h.y = __float2half_rn(b.y);
    *reinterpret_cast<__half2*>(kh + base + 4) = h;
    h.x = __float2half_rn(b.z); h.y = __float2half_rn(b.w);
    *reinterpret_cast<__half2*>(kh + base + 6) = h;

    const int j = t64 * 8;
    float s = a.x * us[j] + a.y * us[j + 1] + a.z * us[j + 2] + a.w * us[j + 3]
            + b.x * us[j + 4] + b.y * us[j + 5] + b.z * us[j + 6] + b.w * us[j + 7];
    #pragma unroll
    for (int o = 16; o > 0; o >>= 1) s += __shfl_xor_sync(0xffffffffu, s, o);
    if ((threadIdx.x & 31) == 0) part[rl][(t64 >> 5)] = s;
    __syncthreads();
    if (threadIdx.x < 4)
        col[(size_t)blockIdx.x * 4 + threadIdx.x] =
            0.25f * (part[threadIdx.x][0] + part[threadIdx.x][1]);
}

// W [K=512, N=512] -> Wt [N, K] plain fp16 (B/A operand layout, transposed)
__global__ __launch_bounds__(256) void whalf(const float* __restrict__ W,
                                             __half* __restrict__ Wth)
{
    __shared__ float t[32][33];
    const int n0 = blockIdx.x * 32, k0 = blockIdx.y * 32;
    const int tx = threadIdx.x & 31, ty = threadIdx.x >> 5;
    #pragma unroll
    for (int i = 0; i < 4; i++) {
        const int r = ty + i * 8;
        t[r][tx] = W[(size_t)(k0 + r) * HD + n0 + tx];
    }
    __syncthreads();
    #pragma unroll
    for (int i = 0; i < 4; i++) {
        const int r = ty + i * 8;
        Wth[(size_t)(n0 + r) * FT + k0 + tx] = __float2half_rn(t[tx][r]);
    }
}

// G[a,b] = sum_h Wk[a,h]*Wq[b,h]; plain fp16 out
__global__ __launch_bounds__(256) void gemmG(const float* __restrict__ Wk_,
                                             const float* __restrict__ Wq_,
                                             __half* __restrict__ Gh)
{
    __shared__ float sk[16][17], sq[16][17];
    const int a0 = blockIdx.y * 16, b0 = blockIdx.x * 16;
    const int tx = threadIdx.x & 15;
    const int ty = threadIdx.x >> 4;
    float acc = 0.0f;
    for (int h0 = 0; h0 < FT; h0 += 16) {
        sk[ty][tx] = Wk_[(size_t)(a0 + ty) * HD + h0 + tx];
        sq[ty][tx] = Wq_[(size_t)(b0 + ty) * HD + h0 + tx];
        __syncthreads();
        #pragma unroll
        for (int hh = 0; hh < 16; hh++)
            acc = fmaf(sk[ty][hh], sq[tx][hh], acc);
        __syncthreads();
    }
    Gh[(size_t)(a0 + ty) * HD + b0 + tx] = __float2half_rn(acc);
}

// u[f] = sum_h Wk[f,h] * bq[h]
__global__ __launch_bounds__(256) void uvec(const float* __restrict__ Wk_,
                                            const float* __restrict__ bq,
                                            float* __restrict__ u)
{
    const int f = blockIdx.x * 8 + (threadIdx.x >> 5);
    const int lane = threadIdx.x & 31;
    float s = 0.0f;
    for (int j = lane; j < FT; j += 32) s = fmaf(Wk_[(size_t)f * HD + j], bq[j], s);
    #pragma unroll
    for (int o = 16; o > 0; o >>= 1) s += __shfl_xor_sync(0xffffffffu, s, o);
    if (lane == 0) u[f] = s;
}

// invZ[row] = 1 / sum(E[row, :])  (rows of 2048 fp16)
__global__ __launch_bounds__(256) void zsum(const __half* __restrict__ E,
                                            float* __restrict__ invZ)
{
    const size_t off = (size_t)blockIdx.x * TT;
    const int tid = threadIdx.x;
    const float4 raw = *reinterpret_cast<const float4*>(E + off + tid * 8);
    const __half2* hp = reinterpret_cast<const __half2*>(&raw);
    float s = 0.f;
    #pragma unroll
    for (int i = 0; i < 4; i++) {
        const float2 f = __half22float2(hp[i]);
        s += f.x + f.y;
    }
    #pragma unroll
    for (int o = 16; o > 0; o >>= 1) s += __shfl_xor_sync(0xffffffffu, s, o);
    __shared__ float red[8];
    if ((tid & 31) == 0) red[tid >> 5] = s;
    __syncthreads();
    if (tid == 0) {
        float tot = 0.f;
        #pragma unroll
        for (int i = 0; i < 8; i++) tot += red[i];
        invZ[blockIdx.x] = __fdividef(1.0f, tot);
    }
}

// ---------------- launch ----------------
extern "C" void kernel_launch(void* const* d_in, const int* in_sizes, int n_in,
                              void* d_out, int out_size)
{
    const float* q  = (const float*)d_in[0];
    const float* k  = (const float*)d_in[1];
    const float* v  = (const float*)d_in[2];
    const float* Wq = (const float*)d_in[3];
    const float* bq = (const float*)d_in[4];
    const float* Wk = (const float*)d_in[5];
    // bk cancels in softmax (row-constant)
    const float* Wv = (const float*)d_in[7];
    const float* bv = (const float*)d_in[8];
    float* out = (float*)d_out;

    __half *qh, *kh, *vh, *Gh, *wvh, *Qh, *Yt, *E;
    float *u, *col, *invZ;
    cudaGetSymbolAddress((void**)&qh, g_qh);
    cudaGetSymbolAddress((void**)&kh, g_kh);
    cudaGetSymbolAddress((void**)&vh, g_vh);
    cudaGetSymbolAddress((void**)&Gh, g_Gh);
    cudaGetSymbolAddress((void**)&wvh, g_Wvh);
    cudaGetSymbolAddress((void**)&Qh, g_Qh);
    cudaGetSymbolAddress((void**)&Yt, g_Yt);
    cudaGetSymbolAddress((void**)&E, g_E);
    cudaGetSymbolAddress((void**)&u, g_u);
    cudaGetSymbolAddress((void**)&col, g_col);
    cudaGetSymbolAddress((void**)&invZ, g_invZ);

    cudaFuncSetAttribute((const void*)gemm_mma<2>, cudaFuncAttributeMaxDynamicSharedMemorySize, GEMM_SMEM);
    cudaFuncSetAttribute((const void*)gemm_mma<3>, cudaFuncAttributeMaxDynamicSharedMemorySize, GEMM_SMEM);
    cudaFuncSetAttribute((const void*)gemm_mma<5>, cudaFuncAttributeMaxDynamicSharedMemorySize, GEMM_SMEM);

    // 1) precompute u, then input conversions
    uvec<<<FT / 8, 256>>>(Wk, bq, u);
    fsplit_h<<<MTOT * FT / 1024, 256>>>(q, qh);                  // q plain
    kprep<<<MTOT / 4, 256>>>(k, u, kh, col);                     // k plain + col fused
    fsplit_h<<<MTOT * FT / 1024, 256>>>(v, vh);                  // v plain (no transpose!)
    whalf<<<dim3(16, 16), 256>>>(Wv, wvh);                       // Wv^T plain fp16
    gemmG<<<dim3(HD / 16, FT / 16), 256>>>(Wk, Wq, Gh);          // G plain
    // 2) Q' = 0.25 q.G
    gemm_mma<2><<<dim3(HD / 128, MTOT / 128, 1), 256, GEMM_SMEM>>>(
        qh, Gh, FT, FT, 0, 0, FT, nullptr, 0, nullptr, 0.25f, nullptr, Qh, HD, 0);
    // 3) Yt[h,t] = sum_f Wv[f,h] v[t,f]  (per batch; produced directly transposed)
    gemm_mma<2><<<dim3(TT / 128, HD / 128, BZ), 256, GEMM_SMEM>>>(
        wvh, vh, FT, FT, 0, (long)TT * FT, FT,
        nullptr, 0, nullptr, 1.0f, nullptr, Yt, TT, (long)HD * TT);
    // 4) E = exp(Q'.k^T + col - 8)
    gemm_mma<3><<<dim3(TT / 128, TT / 128, BZ), 256, GEMM_SMEM>>>(
        Qh, kh, HD, FT, (long)TT * HD, (long)TT * FT, HD,
        col, TT, nullptr, 1.0f, nullptr, E, TT, (long)TT * TT);
    // 5) invZ = 1 / rowsum(E)
    zsum<<<MTOT, 256>>>(E, invZ);
    // 6) out = (E.Yt^T) * invZ[row] + bv
    gemm_mma<5><<<dim3(HD / 128, TT / 128, BZ), 256, GEMM_SMEM>>>(
        E, Yt, TT, TT, (long)TT * TT, (long)HD * TT, TT,
        invZ, TT, bv, 1.0f, out, nullptr, HD, (long)TT * HD);
}

// round 16
// speedup vs baseline: 2.0915x; 1.0479x over previous
#include <cuda_runtime.h>
#include <cuda_fp16.h>
#include <stdint.h>
#include <math.h>

#define BZ 8
#define TT 2048
#define FT 512
#define HD 512
#define MTOT (BZ * TT)   // 16384
#define ESHIFT 8.0f

// ---------------- scratch (device globals; allocation-free) ----------------
__device__ __align__(16) __half g_qh[MTOT * FT];
__device__ __align__(16) __half g_kh[MTOT * FT];
__device__ __align__(16) __half g_vh[MTOT * FT];
__device__ __align__(16) __half g_Gh[FT * HD];
__device__ __align__(16) __half g_Wvh[FT * HD];
__device__ __align__(16) __half g_Qh[MTOT * HD];
__device__ __align__(16) __half g_Yt[(size_t)BZ * HD * TT];     // (v.Wv)^T per batch
__device__ __align__(16) __half g_E[(size_t)BZ * TT * TT];      // exp(S - 8), fp16
__device__ __align__(16) float g_u[FT];
__device__ __align__(16) float g_col[MTOT];
__device__ __align__(16) float g_Zpart[(size_t)MTOT * 16];      // per-(row, bn-tile) partial sums
__device__ __align__(16) float g_invZ[MTOT];

// ---------------- helpers ----------------
__device__ __forceinline__ uint32_t smem_u32(const void* p) {
    uint32_t a;
    asm("{ .reg .u64 t; cvta.to.shared.u64 t, %1; cvt.u32.u64 %0, t; }" : "=r"(a) : "l"(p));
    return a;
}

#define CP16(dst, src) \
    asm volatile("cp.async.cg.shared.global [%0], [%1], 16;" :: "r"(dst), "l"(src) : "memory")

#define LDSM4(r, addr) \
    asm volatile("ldmatrix.sync.aligned.m8n8.x4.shared.b16 {%0,%1,%2,%3}, [%4];" \
                 : "=r"((r)[0]), "=r"((r)[1]), "=r"((r)[2]), "=r"((r)[3]) : "r"(addr))

#define MMAF32(d, a, b0, b1) \
    asm volatile("mma.sync.aligned.m16n8k16.row.col.f32.f16.f16.f32 " \
                 "{%0,%1,%2,%3}, {%4,%5,%6,%7}, {%8,%9}, {%0,%1,%2,%3};" \
                 : "+f"((d)[0]), "+f"((d)[1]), "+f"((d)[2]), "+f"((d)[3]) \
                 : "r"((a)[0]), "r"((a)[1]), "r"((a)[2]), "r"((a)[3]), "r"(b0), "r"(b1))

static constexpr int TILE_B = 8192;             // 128 rows x 64 bytes
static constexpr int STAGE_B = 2 * TILE_B;      // A, B = 16 KB
static constexpr int GEMM_SMEM = 2 * STAGE_B;   // 32 KB

__device__ __forceinline__ void load_tile(uint32_t dstbase, const __half* src, int ld, int tid)
{
    #pragma unroll
    for (int j = 0; j < 2; j++) {
        const int seg = tid + j * 256;
        const int row = seg >> 2;
        const int colb = (seg & 3) * 16;
        const uint32_t off = (uint32_t)(row * 64 + colb);
        const uint32_t sw = off ^ ((off >> 3) & 0x30);
        CP16(dstbase + sw, (const char*)src + (long)row * ld * 2 + colb);
    }
}

// Shared 128x128 (K-chunked) MMA mainloop. acc[mt][nt][r].
__device__ __forceinline__ void gemm_body(const __half* pA, const __half* pB,
                                          int lda, int ldb, int K,
                                          uint32_t sbase, int tid, int wid, int L,
                                          float (&acc)[4][4][4])
{
    const int wm = wid & 1;
    const int wn = wid >> 1;
    const int lr = L & 15;
    const int lc = (L >> 4) * 16;
    uint32_t aoffu[4], apat[4], boffu[2], bpat[2];
    #pragma unroll
    for (int mt = 0; mt < 4; mt++) {
        const uint32_t off = (uint32_t)((wm * 64 + mt * 16 + lr) * 64 + lc);
        aoffu[mt] = off;
        apat[mt] = (off >> 3) & 0x30;
    }
    #pragma unroll
    for (int ng = 0; ng < 2; ng++) {
        const uint32_t off = (uint32_t)((wn * 32 + ng * 16 + lr) * 64 + lc);
        boffu[ng] = off;
        bpat[ng] = (off >> 3) & 0x30;
    }

    #pragma unroll
    for (int mt = 0; mt < 4; mt++)
        #pragma unroll
        for (int nt = 0; nt < 4; nt++)
            #pragma unroll
            for (int r = 0; r < 4; r++)
                acc[mt][nt][r] = 0.0f;

    const int nchunk = K / 32;
    load_tile(sbase + 0 * TILE_B, pA, lda, tid);
    load_tile(sbase + 1 * TILE_B, pB, ldb, tid);
    asm volatile("cp.async.commit_group;" ::: "memory");

    for (int ck = 0; ck < nchunk; ck++) {
        const int buf = ck & 1;
        if (ck + 1 < nchunk) {
            const int k0 = (ck + 1) * 32;
            const uint32_t db = sbase + (buf ^ 1) * STAGE_B;
            load_tile(db + 0 * TILE_B, pA + k0, lda, tid);
            load_tile(db + 1 * TILE_B, pB + k0, ldb, tid);
            asm volatile("cp.async.commit_group;" ::: "memory");
            asm volatile("cp.async.wait_group 1;" ::: "memory");
        } else {
            asm volatile("cp.async.wait_group 0;" ::: "memory");
        }
        __syncthreads();

        const uint32_t cb = sbase + buf * STAGE_B;
        #pragma unroll
        for (int kk = 0; kk < 2; kk++) {
            uint32_t bh[2][4];
            #pragma unroll
            for (int ng = 0; ng < 2; ng++) {
                const uint32_t sw = (boffu[ng] + kk * 32) ^ bpat[ng];
                LDSM4(bh[ng], cb + 1 * TILE_B + sw);
            }
            #pragma unroll
            for (int mt = 0; mt < 4; mt++) {
                uint32_t ah[4];
                const uint32_t sw = (aoffu[mt] + kk * 32) ^ apat[mt];
                LDSM4(ah, cb + 0 * TILE_B + sw);
                #pragma unroll
                for (int nt = 0; nt < 4; nt++) {
                    const int ng = nt >> 1, h = nt & 1;
                    MMAF32(acc[mt][nt], ah, bh[ng][h], bh[ng][h + 2]);
                }
            }
        }
        __syncthreads();
    }
}

// ---------------- E-GEMM: E = fp16(exp(acc + col - 8)), Zpart row sums ----------------
__global__ __launch_bounds__(256, 2)
void gemm_E(const __half* __restrict__ Qh, const __half* __restrict__ kh,
            const float* __restrict__ col, __half* __restrict__ E,
            float* __restrict__ Zpart)
{
    extern __shared__ char smem[];
    const uint32_t sbase = smem_u32(smem);
    const int tid = threadIdx.x;
    const int wid = tid >> 5;
    const int L = tid & 31;
    const int bm = blockIdx.y * 128;
    const int bn = blockIdx.x * 128;
    const int wm = wid & 1;
    const int wn = wid >> 1;

    float acc[4][4][4];
    gemm_body(Qh + (long)blockIdx.z * TT * HD + (long)bm * HD,
              kh + (long)blockIdx.z * TT * FT + (long)bn * FT,
              HD, FT, HD, sbase, tid, wid, L, acc);

    float* fpart = reinterpret_cast<float*>(smem);   // [128][4]
    __half* po = E + (size_t)blockIdx.z * TT * TT;
    const int r0 = bm + wm * 64 + (L >> 2);
    const int c0 = bn + wn * 32 + (L & 3) * 2;
    #pragma unroll
    for (int mt = 0; mt < 4; mt++) {
        const int row = r0 + mt * 16;
        float rs0 = 0.f, rs1 = 0.f;
        #pragma unroll
        for (int nt = 0; nt < 4; nt++) {
            const int c = c0 + nt * 8;
            const float b0 = col[blockIdx.z * TT + c] - ESHIFT;
            const float b1 = col[blockIdx.z * TT + c + 1] - ESHIFT;
            const float e0 = __expf(acc[mt][nt][0] + b0);
            const float e1 = __expf(acc[mt][nt][1] + b1);
            const float e2 = __expf(acc[mt][nt][2] + b0);
            const float e3 = __expf(acc[mt][nt][3] + b1);
            __half2 t;
            t.x = __float2half_rn(e0); t.y = __float2half_rn(e1);
            *reinterpret_cast<__half2*>(po + (size_t)row * TT + c) = t;
            t.x = __float2half_rn(e2); t.y = __float2half_rn(e3);
            *reinterpret_cast<__half2*>(po + (size_t)(row + 8) * TT + c) = t;
            rs0 += e0 + e1;
            rs1 += e2 + e3;
        }
        rs0 += __shfl_xor_sync(0xffffffffu, rs0, 1);
        rs0 += __shfl_xor_sync(0xffffffffu, rs0, 2);
        rs1 += __shfl_xor_sync(0xffffffffu, rs1, 1);
        rs1 += __shfl_xor_sync(0xffffffffu, rs1, 2);
        if ((L & 3) == 0) {
            const int rl = wm * 64 + mt * 16 + (L >> 2);
            fpart[rl * 4 + wn] = rs0;
            fpart[(rl + 8) * 4 + wn] = rs1;
        }
    }
    __syncthreads();
    if (tid < 128) {
        const float s = fpart[tid * 4] + fpart[tid * 4 + 1]
                      + fpart[tid * 4 + 2] + fpart[tid * 4 + 3];
        Zpart[((size_t)blockIdx.z * TT + bm + tid) * 16 + blockIdx.x] = s;
    }
}

// ---------------- out-GEMM: out = acc / Z[row] + bv[col] ----------------
__global__ __launch_bounds__(256, 2)
void gemm_out(const __half* __restrict__ E, const __half* __restrict__ Yt,
              const float* __restrict__ invZ, const float* __restrict__ bv,
              float* __restrict__ out)
{
    extern __shared__ char smem[];
    const uint32_t sbase = smem_u32(smem);
    const int tid = threadIdx.x;
    const int wid = tid >> 5;
    const int L = tid & 31;
    const int bm = blockIdx.y * 128;
    const int bn = blockIdx.x * 128;
    const int wm = wid & 1;
    const int wn = wid >> 1;

    float acc[4][4][4];
    gemm_body(E + (size_t)blockIdx.z * TT * TT + (size_t)bm * TT,
              Yt + (size_t)blockIdx.z * HD * TT + (size_t)bn * TT,
              TT, TT, TT, sbase, tid, wid, L, acc);

    float* po = out + (size_t)blockIdx.z * TT * HD;
    const int r0 = bm + wm * 64 + (L >> 2);
    const int c0 = bn + wn * 32 + (L & 3) * 2;
    #pragma unroll
    for (int mt = 0; mt < 4; mt++) {
        const int row = r0 + mt * 16;
        const float rs0 = invZ[blockIdx.z * TT + row];
        const float rs1 = invZ[blockIdx.z * TT + row + 8];
        #pragma unroll
        for (int nt = 0; nt < 4; nt++) {
            const int c = c0 + nt * 8;
            const float b0 = bv[c], b1 = bv[c + 1];
            *reinterpret_cast<float2*>(po + (size_t)row * HD + c) =
                make_float2(fmaf(acc[mt][nt][0], rs0, b0),
                            fmaf(acc[mt][nt][1], rs0, b1));
            *reinterpret_cast<float2*>(po + (size_t)(row + 8) * HD + c) =
                make_float2(fmaf(acc[mt][nt][2], rs1, b0),
                            fmaf(acc[mt][nt][3], rs1, b1));
        }
    }
}

// ---------------- dual GEMM: z<8 -> Yt batch z ; z>=8 -> Q' tiles ----------------
__global__ __launch_bounds__(256, 2)
void gemm_dual(const __half* __restrict__ wvh, const __half* __restrict__ vh,
               const __half* __restrict__ qh, const __half* __restrict__ Gh,
               __half* __restrict__ Yt, __half* __restrict__ Qh)
{
    extern __shared__ char smem[];
    const uint32_t sbase = smem_u32(smem);
    const int tid = threadIdx.x;
    const int wid = tid >> 5;
    const int L = tid & 31;
    const int wm = wid & 1;
    const int wn = wid >> 1;

    const __half* pA;
    const __half* pB;
    __half* po;
    int bm, bn, ldo;
    float scale;
    if (blockIdx.z < 8) {           // Yt[h,t] = sum_f Wv[f,h] v[t,f], batch z
        bm = blockIdx.y * 128;      // h
        bn = blockIdx.x * 128;      // t
        pA = wvh + (long)bm * FT;
        pB = vh + (long)blockIdx.z * TT * FT + (long)bn * FT;
        po = Yt + (size_t)blockIdx.z * HD * TT;
        ldo = TT;
        scale = 1.0f;
    } else {                        // Q' = 0.25 q.G
        const int lin = (blockIdx.z - 8) * 64 + blockIdx.y * 16 + blockIdx.x;
        bm = (lin >> 2) * 128;      // q rows
        bn = (lin & 3) * 128;       // G cols
        pA = qh + (long)bm * FT;
        pB = Gh + (long)bn * FT;
        po = Qh;
        ldo = HD;
        scale = 0.25f;
    }

    float acc[4][4][4];
    gemm_body(pA, pB, FT, FT, FT, sbase, tid, wid, L, acc);

    const int r0 = bm + wm * 64 + (L >> 2);
    const int c0 = bn + wn * 32 + (L & 3) * 2;
    #pragma unroll
    for (int mt = 0; mt < 4; mt++) {
        const int row = r0 + mt * 16;
        #pragma unroll
        for (int nt = 0; nt < 4; nt++) {
            const int c = c0 + nt * 8;
            __half2 t;
            t.x = __float2half_rn(acc[mt][nt][0] * scale);
            t.y = __float2half_rn(acc[mt][nt][1] * scale);
            *reinterpret_cast<__half2*>(po + (size_t)row * ldo + c) = t;
            t.x = __float2half_rn(acc[mt][nt][2] * scale);
            t.y = __float2half_rn(acc[mt][nt][3] * scale);
            *reinterpret_cast<__half2*>(po + (size_t)(row + 8) * ldo + c) = t;
        }
    }
}

// ---------------- small kernels ----------------
// merged q/v fp32->fp16 conversion
__global__ __launch_bounds__(256) void qvhalf(const float* __restrict__ q,
                                              const float* __restrict__ v,
                                              __half* __restrict__ qh,
                                              __half* __restrict__ vh)
{
    const int half = (int)blockIdx.x >= 8192;
    const int blk = (int)blockIdx.x - (half ? 8192 : 0);
    const float* src = half ? v : q;
    __half* dst = half ? vh : qh;
    const int i = (blk * 256 + threadIdx.x) * 4;
    float4 a = *reinterpret_cast<const float4*>(src + i);
    __half2 t;
    t.x = __float2half_rn(a.x); t.y = __float2half_rn(a.y);
    *reinterpret_cast<__half2*>(dst + i) = t;
    t.x = __float2half_rn(a.z); t.y = __float2half_rn(a.w);
    *reinterpret_cast<__half2*>(dst + i + 2) = t;
}

// fused k prep: kh = fp16(k), col[r] = 0.25 * dot(k[r,:], u)
__global__ __launch_bounds__(256) void kprep(const float* __restrict__ k,
                                             const float* __restrict__ u,
                                             __half* __restrict__ kh,
                                             float* __restrict__ col)
{
    __shared__ float us[FT];
    __shared__ float part[4][2];
    for (int i = threadIdx.x; i < FT; i += 256) us[i] = u[i];
    __syncthreads();

    const int rl = threadIdx.x >> 6;
    const int t64 = threadIdx.x & 63;
    const size_t row = (size_t)blockIdx.x * 4 + rl;
    const size_t base = row * FT + t64 * 8;

    float4 a = *reinterpret_cast<const float4*>(k + base);
    float4 b = *reinterpret_cast<const float4*>(k + base + 4);
    __half2 h;
    h.x = __float2half_rn(a.x); h.y = __float2half_rn(a.y);
    *reinterpret_cast<__half2*>(kh + base) = h;
    h.x = __float2half_rn(a.z); h.y = __float2half_rn(a.w);
    *reinterpret_cast<__half2*>(kh + base + 2) = h;
    h.x = __float2half_rn(b.x); h.y = __float2half_rn(b.y);
    *reinterpret_cast<__half2*>(kh + base + 4) = h;
    h.x = __float2half_rn(b.z); h.y = __float2half_rn(b.w);
    *reinterpret_cast<__half2*>(kh + base + 6) = h;

    const int j = t64 * 8;
    float s = a.x * us[j] + a.y * us[j + 1] + a.z * us[j + 2] + a.w * us[j + 3]
            + b.x * us[j + 4] + b.y * us[j + 5] + b.z * us[j + 6] + b.w * us[j + 7];
    #pragma unroll
    for (int o = 16; o > 0; o >>= 1) s += __shfl_xor_sync(0xffffffffu, s, o);
    if ((threadIdx.x & 31) == 0) part[rl][(t64 >> 5)] = s;
    __syncthreads();
    if (threadIdx.x < 4)
        col[(size_t)blockIdx.x * 4 + threadIdx.x] =
            0.25f * (part[threadIdx.x][0] + part[threadIdx.x][1]);
}

// W [K=512, N=512] -> Wt [N, K] plain fp16 (transposed operand layout)
__global__ __launch_bounds__(256) void whalf(const float* __restrict__ W,
                                             __half* __restrict__ Wth)
{
    __shared__ float t[32][33];
    const int n0 = blockIdx.x * 32, k0 = blockIdx.y * 32;
    const int tx = threadIdx.x & 31, ty = threadIdx.x >> 5;
    #pragma unroll
    for (int i = 0; i < 4; i++) {
        const int r = ty + i * 8;
        t[r][tx] = W[(size_t)(k0 + r) * HD + n0 + tx];
    }
    __syncthreads();
    #pragma unroll
    for (int i = 0; i < 4; i++) {
        const int r = ty + i * 8;
        Wth[(size_t)(n0 + r) * FT + k0 + tx] = __float2half_rn(t[tx][r]);
    }
}

// G[a,b] = sum_h Wk[a,h]*Wq[b,h]; plain fp16 out
__global__ __launch_bounds__(256) void gemmG(const float* __restrict__ Wk_,
                                             const float* __restrict__ Wq_,
                                             __half* __restrict__ Gh)
{
    __shared__ float sk[16][17], sq[16][17];
    const int a0 = blockIdx.y * 16, b0 = blockIdx.x * 16;
    const int tx = threadIdx.x & 15;
    const int ty = threadIdx.x >> 4;
    float acc = 0.0f;
    for (int h0 = 0; h0 < FT; h0 += 16) {
        sk[ty][tx] = Wk_[(size_t)(a0 + ty) * HD + h0 + tx];
        sq[ty][tx] = Wq_[(size_t)(b0 + ty) * HD + h0 + tx];
        __syncthreads();
        #pragma unroll
        for (int hh = 0; hh < 16; hh++)
            acc = fmaf(sk[ty][hh], sq[tx][hh], acc);
        __syncthreads();
    }
    Gh[(size_t)(a0 + ty) * HD + b0 + tx] = __float2half_rn(acc);
}

// u[f] = sum_h Wk[f,h] * bq[h]
__global__ __launch_bounds__(256) void uvec(const float* __restrict__ Wk_,
                                            const float* __restrict__ bq,
                                            float* __restrict__ u)
{
    const int f = blockIdx.x * 8 + (threadIdx.x >> 5);
    const int lane = threadIdx.x & 31;
    float s = 0.0f;
    for (int j = lane; j < FT; j += 32) s = fmaf(Wk_[(size_t)f * HD + j], bq[j], s);
    #pragma unroll
    for (int o = 16; o > 0; o >>= 1) s += __shfl_xor_sync(0xffffffffu, s, o);
    if (lane == 0) u[f] = s;
}

// invZ[r] = 1 / sum_i Zpart[r*16+i]
__global__ __launch_bounds__(256) void zred(const float* __restrict__ Zpart,
                                            float* __restrict__ invZ)
{
    const int r = blockIdx.x * 256 + threadIdx.x;
    const float4* p = reinterpret_cast<const float4*>(Zpart + (size_t)r * 16);
    float s = 0.f;
    #pragma unroll
    for (int i = 0; i < 4; i++) {
        const float4 t = p[i];
        s += t.x + t.y + t.z + t.w;
    }
    invZ[r] = __fdividef(1.0f, s);
}

// ---------------- launch ----------------
extern "C" void kernel_launch(void* const* d_in, const int* in_sizes, int n_in,
                              void* d_out, int out_size)
{
    const float* q  = (const float*)d_in[0];
    const float* k  = (const float*)d_in[1];
    const float* v  = (const float*)d_in[2];
    const float* Wq = (const float*)d_in[3];
    const float* bq = (const float*)d_in[4];
    const float* Wk = (const float*)d_in[5];
    // bk cancels in softmax (row-constant)
    const float* Wv = (const float*)d_in[7];
    const float* bv = (const float*)d_in[8];
    float* out = (float*)d_out;

    __half *qh, *kh, *vh, *Gh, *wvh, *Qh, *Yt, *E;
    float *u, *col, *Zpart, *invZ;
    cudaGetSymbolAddress((void**)&qh, g_qh);
    cudaGetSymbolAddress((void**)&kh, g_kh);
    cudaGetSymbolAddress((void**)&vh, g_vh);
    cudaGetSymbolAddress((void**)&Gh, g_Gh);
    cudaGetSymbolAddress((void**)&wvh, g_Wvh);
    cudaGetSymbolAddress((void**)&Qh, g_Qh);
    cudaGetSymbolAddress((void**)&Yt, g_Yt);
    cudaGetSymbolAddress((void**)&E, g_E);
    cudaGetSymbolAddress((void**)&u, g_u);
    cudaGetSymbolAddress((void**)&col, g_col);
    cudaGetSymbolAddress((void**)&Zpart, g_Zpart);
    cudaGetSymbolAddress((void**)&invZ, g_invZ);

    cudaFuncSetAttribute((const void*)gemm_dual, cudaFuncAttributeMaxDynamicSharedMemorySize, GEMM_SMEM);
    cudaFuncSetAttribute((const void*)gemm_E, cudaFuncAttributeMaxDynamicSharedMemorySize, GEMM_SMEM);
    cudaFuncSetAttribute((const void*)gemm_out, cudaFuncAttributeMaxDynamicSharedMemorySize, GEMM_SMEM);

    // 1) precompute + conversions
    uvec<<<FT / 8, 256>>>(Wk, bq, u);
    qvhalf<<<2 * 8192, 256>>>(q, v, qh, vh);
    kprep<<<MTOT / 4, 256>>>(k, u, kh, col);
    whalf<<<dim3(16, 16), 256>>>(Wv, wvh);
    gemmG<<<dim3(HD / 16, FT / 16), 256>>>(Wk, Wq, Gh);
    // 2) merged Q' (0.25 q.G) + Yt (Wv^T v^T) in one launch
    gemm_dual<<<dim3(16, 4, 16), 256, GEMM_SMEM>>>(wvh, vh, qh, Gh, Yt, Qh);
    // 3) E = exp(Q'.k^T + col - 8), with fused deterministic row-sum partials
    gemm_E<<<dim3(16, 16, 8), 256, GEMM_SMEM>>>(Qh, kh, col, E, Zpart);
    // 4) invZ from partials (1 MB vs re-reading 64 MB of E)
    zred<<<MTOT / 256, 256>>>(Zpart, invZ);
    // 5) out = (E.Yt^T) * invZ[row] + bv
    gemm_out<<<dim3(HD / 128, TT / 128, BZ), 256, GEMM_SMEM>>>(E, Yt, invZ, bv, out);
}

// round 17
// speedup vs baseline: 2.1598x; 1.0326x over previous
#include <cuda_runtime.h>
#include <cuda_fp16.h>
#include <stdint.h>
#include <math.h>

#define BZ 8
#define TT 2048
#define FT 512
#define HD 512
#define MTOT (BZ * TT)   // 16384
#define ESHIFT 8.0f

// ---------------- scratch (device globals; allocation-free) ----------------
__device__ __align__(16) __half g_qh[MTOT * FT];
__device__ __align__(16) __half g_kh[MTOT * FT];
__device__ __align__(16) __half g_vh[MTOT * FT];
__device__ __align__(16) __half g_Gh[FT * HD];
__device__ __align__(16) __half g_Wvh[FT * HD];
__device__ __align__(16) __half g_Qh[MTOT * HD];
__device__ __align__(16) __half g_Yt[(size_t)BZ * HD * TT];     // (v.Wv)^T per batch
__device__ __align__(16) __half g_E[(size_t)BZ * TT * TT];      // exp(S - 8), fp16
__device__ __align__(16) float g_u[FT];
__device__ __align__(16) float g_col[MTOT];
__device__ __align__(16) float g_Zpart[(size_t)MTOT * 16];      // per-(row, bn-tile) partials

// ---------------- helpers ----------------
__device__ __forceinline__ uint32_t smem_u32(const void* p) {
    uint32_t a;
    asm("{ .reg .u64 t; cvta.to.shared.u64 t, %1; cvt.u32.u64 %0, t; }" : "=r"(a) : "l"(p));
    return a;
}

#define CP16(dst, src) \
    asm volatile("cp.async.cg.shared.global [%0], [%1], 16;" :: "r"(dst), "l"(src) : "memory")

#define LDSM4(r, addr) \
    asm volatile("ldmatrix.sync.aligned.m8n8.x4.shared.b16 {%0,%1,%2,%3}, [%4];" \
                 : "=r"((r)[0]), "=r"((r)[1]), "=r"((r)[2]), "=r"((r)[3]) : "r"(addr))

#define MMAF32(d, a, b0, b1) \
    asm volatile("mma.sync.aligned.m16n8k16.row.col.f32.f16.f16.f32 " \
                 "{%0,%1,%2,%3}, {%4,%5,%6,%7}, {%8,%9}, {%0,%1,%2,%3};" \
                 : "+f"((d)[0]), "+f"((d)[1]), "+f"((d)[2]), "+f"((d)[3]) \
                 : "r"((a)[0]), "r"((a)[1]), "r"((a)[2]), "r"((a)[3]), "r"(b0), "r"(b1))

static constexpr int TILE_B = 8192;             // 128 rows x 64 bytes
static constexpr int STAGE_B = 2 * TILE_B;      // A, B = 16 KB
static constexpr int GEMM_SMEM = 2 * STAGE_B;   // 32 KB

__device__ __forceinline__ void load_tile(uint32_t dstbase, const __half* src, int ld, int tid)
{
    #pragma unroll
    for (int j = 0; j < 2; j++) {
        const int seg = tid + j * 256;
        const int row = seg >> 2;
        const int colb = (seg & 3) * 16;
        const uint32_t off = (uint32_t)(row * 64 + colb);
        const uint32_t sw = off ^ ((off >> 3) & 0x30);
        CP16(dstbase + sw, (const char*)src + (long)row * ld * 2 + colb);
    }
}

// Shared 128x128 (K-chunked) MMA mainloop.
__device__ __forceinline__ void gemm_body(const __half* pA, const __half* pB,
                                          int lda, int ldb, int K,
                                          uint32_t sbase, int tid, int wid, int L,
                                          float (&acc)[4][4][4])
{
    const int wm = wid & 1;
    const int wn = wid >> 1;
    const int lr = L & 15;
    const int lc = (L >> 4) * 16;
    uint32_t aoffu[4], apat[4], boffu[2], bpat[2];
    #pragma unroll
    for (int mt = 0; mt < 4; mt++) {
        const uint32_t off = (uint32_t)((wm * 64 + mt * 16 + lr) * 64 + lc);
        aoffu[mt] = off;
        apat[mt] = (off >> 3) & 0x30;
    }
    #pragma unroll
    for (int ng = 0; ng < 2; ng++) {
        const uint32_t off = (uint32_t)((wn * 32 + ng * 16 + lr) * 64 + lc);
        boffu[ng] = off;
        bpat[ng] = (off >> 3) & 0x30;
    }

    #pragma unroll
    for (int mt = 0; mt < 4; mt++)
        #pragma unroll
        for (int nt = 0; nt < 4; nt++)
            #pragma unroll
            for (int r = 0; r < 4; r++)
                acc[mt][nt][r] = 0.0f;

    const int nchunk = K / 32;
    load_tile(sbase + 0 * TILE_B, pA, lda, tid);
    load_tile(sbase + 1 * TILE_B, pB, ldb, tid);
    asm volatile("cp.async.commit_group;" ::: "memory");

    for (int ck = 0; ck < nchunk; ck++) {
        const int buf = ck & 1;
        if (ck + 1 < nchunk) {
            const int k0 = (ck + 1) * 32;
            const uint32_t db = sbase + (buf ^ 1) * STAGE_B;
            load_tile(db + 0 * TILE_B, pA + k0, lda, tid);
            load_tile(db + 1 * TILE_B, pB + k0, ldb, tid);
            asm volatile("cp.async.commit_group;" ::: "memory");
            asm volatile("cp.async.wait_group 1;" ::: "memory");
        } else {
            asm volatile("cp.async.wait_group 0;" ::: "memory");
        }
        __syncthreads();

        const uint32_t cb = sbase + buf * STAGE_B;
        #pragma unroll
        for (int kk = 0; kk < 2; kk++) {
            uint32_t bh[2][4];
            #pragma unroll
            for (int ng = 0; ng < 2; ng++) {
                const uint32_t sw = (boffu[ng] + kk * 32) ^ bpat[ng];
                LDSM4(bh[ng], cb + 1 * TILE_B + sw);
            }
            #pragma unroll
            for (int mt = 0; mt < 4; mt++) {
                uint32_t ah[4];
                const uint32_t sw = (aoffu[mt] + kk * 32) ^ apat[mt];
                LDSM4(ah, cb + 0 * TILE_B + sw);
                #pragma unroll
                for (int nt = 0; nt < 4; nt++) {
                    const int ng = nt >> 1, h = nt & 1;
                    MMAF32(acc[mt][nt], ah, bh[ng][h], bh[ng][h + 2]);
                }
            }
        }
        __syncthreads();
    }
}

// ---------------- E-GEMM: E = fp16(exp(acc + col - 8)), Zpart row sums ----------------
__global__ __launch_bounds__(256, 2)
void gemm_E(const __half* __restrict__ Qh, const __half* __restrict__ kh,
            const float* __restrict__ col, __half* __restrict__ E,
            float* __restrict__ Zpart)
{
    extern __shared__ char smem[];
    const uint32_t sbase = smem_u32(smem);
    const int tid = threadIdx.x;
    const int wid = tid >> 5;
    const int L = tid & 31;
    const int bm = blockIdx.y * 128;
    const int bn = blockIdx.x * 128;
    const int wm = wid & 1;
    const int wn = wid >> 1;

    float acc[4][4][4];
    gemm_body(Qh + (long)blockIdx.z * TT * HD + (long)bm * HD,
              kh + (long)blockIdx.z * TT * FT + (long)bn * FT,
              HD, FT, HD, sbase, tid, wid, L, acc);

    float* fpart = reinterpret_cast<float*>(smem);   // [128][4]
    __half* po = E + (size_t)blockIdx.z * TT * TT;
    const int r0 = bm + wm * 64 + (L >> 2);
    const int c0 = bn + wn * 32 + (L & 3) * 2;
    #pragma unroll
    for (int mt = 0; mt < 4; mt++) {
        const int row = r0 + mt * 16;
        float rs0 = 0.f, rs1 = 0.f;
        #pragma unroll
        for (int nt = 0; nt < 4; nt++) {
            const int c = c0 + nt * 8;
            const float b0 = col[blockIdx.z * TT + c] - ESHIFT;
            const float b1 = col[blockIdx.z * TT + c + 1] - ESHIFT;
            const float e0 = __expf(acc[mt][nt][0] + b0);
            const float e1 = __expf(acc[mt][nt][1] + b1);
            const float e2 = __expf(acc[mt][nt][2] + b0);
            const float e3 = __expf(acc[mt][nt][3] + b1);
            __half2 t;
            t.x = __float2half_rn(e0); t.y = __float2half_rn(e1);
            *reinterpret_cast<__half2*>(po + (size_t)row * TT + c) = t;
            t.x = __float2half_rn(e2); t.y = __float2half_rn(e3);
            *reinterpret_cast<__half2*>(po + (size_t)(row + 8) * TT + c) = t;
            rs0 += e0 + e1;
            rs1 += e2 + e3;
        }
        rs0 += __shfl_xor_sync(0xffffffffu, rs0, 1);
        rs0 += __shfl_xor_sync(0xffffffffu, rs0, 2);
        rs1 += __shfl_xor_sync(0xffffffffu, rs1, 1);
        rs1 += __shfl_xor_sync(0xffffffffu, rs1, 2);
        if ((L & 3) == 0) {
            const int rl = wm * 64 + mt * 16 + (L >> 2);
            fpart[rl * 4 + wn] = rs0;
            fpart[(rl + 8) * 4 + wn] = rs1;
        }
    }
    __syncthreads();
    if (tid < 128) {
        const float s = fpart[tid * 4] + fpart[tid * 4 + 1]
                      + fpart[tid * 4 + 2] + fpart[tid * 4 + 3];
        Zpart[((size_t)blockIdx.z * TT + bm + tid) * 16 + blockIdx.x] = s;
    }
}

// ---------------- out-GEMM: out = acc * invZ[row] + bv[col], invZ fused ----------------
__global__ __launch_bounds__(256, 2)
void gemm_out(const __half* __restrict__ E, const __half* __restrict__ Yt,
              const float* __restrict__ Zpart, const float* __restrict__ bv,
              float* __restrict__ out)
{
    extern __shared__ char smem[];
    const uint32_t sbase = smem_u32(smem);
    const int tid = threadIdx.x;
    const int wid = tid >> 5;
    const int L = tid & 31;
    const int bm = blockIdx.y * 128;
    const int bn = blockIdx.x * 128;
    const int wm = wid & 1;
    const int wn = wid >> 1;

    float acc[4][4][4];
    gemm_body(E + (size_t)blockIdx.z * TT * TT + (size_t)bm * TT,
              Yt + (size_t)blockIdx.z * HD * TT + (size_t)bn * TT,
              TT, TT, TT, sbase, tid, wid, L, acc);

    // fused zred: same 4x float4 summation order as the old zred kernel
    float* zsm = reinterpret_cast<float*>(smem);   // 128 floats
    if (tid < 128) {
        const float4* p = reinterpret_cast<const float4*>(
            Zpart + ((size_t)blockIdx.z * TT + bm + tid) * 16);
        float s = 0.f;
        #pragma unroll
        for (int i = 0; i < 4; i++) {
            const float4 t = p[i];
            s += t.x + t.y + t.z + t.w;
        }
        zsm[tid] = __fdividef(1.0f, s);
    }
    __syncthreads();

    float* po = out + (size_t)blockIdx.z * TT * HD;
    const int r0 = bm + wm * 64 + (L >> 2);
    const int c0 = bn + wn * 32 + (L & 3) * 2;
    #pragma unroll
    for (int mt = 0; mt < 4; mt++) {
        const int row = r0 + mt * 16;
        const float rs0 = zsm[row - bm];
        const float rs1 = zsm[row - bm + 8];
        #pragma unroll
        for (int nt = 0; nt < 4; nt++) {
            const int c = c0 + nt * 8;
            const float b0 = bv[c], b1 = bv[c + 1];
            *reinterpret_cast<float2*>(po + (size_t)row * HD + c) =
                make_float2(fmaf(acc[mt][nt][0], rs0, b0),
                            fmaf(acc[mt][nt][1], rs0, b1));
            *reinterpret_cast<float2*>(po + (size_t)(row + 8) * HD + c) =
                make_float2(fmaf(acc[mt][nt][2], rs1, b0),
                            fmaf(acc[mt][nt][3], rs1, b1));
        }
    }
}

// ---------------- dual GEMM: z<8 -> Yt batch z ; z>=8 -> Q' tiles ----------------
__global__ __launch_bounds__(256, 2)
void gemm_dual(const __half* __restrict__ wvh, const __half* __restrict__ vh,
               const __half* __restrict__ qh, const __half* __restrict__ Gh,
               __half* __restrict__ Yt, __half* __restrict__ Qh)
{
    extern __shared__ char smem[];
    const uint32_t sbase = smem_u32(smem);
    const int tid = threadIdx.x;
    const int wid = tid >> 5;
    const int L = tid & 31;
    const int wm = wid & 1;
    const int wn = wid >> 1;

    const __half* pA;
    const __half* pB;
    __half* po;
    int bm, bn, ldo;
    float scale;
    if (blockIdx.z < 8) {           // Yt[h,t] = sum_f Wv[f,h] v[t,f]
        bm = blockIdx.y * 128;
        bn = blockIdx.x * 128;
        pA = wvh + (long)bm * FT;
        pB = vh + (long)blockIdx.z * TT * FT + (long)bn * FT;
        po = Yt + (size_t)blockIdx.z * HD * TT;
        ldo = TT;
        scale = 1.0f;
    } else {                        // Q' = 0.25 q.G
        const int lin = (blockIdx.z - 8) * 64 + blockIdx.y * 16 + blockIdx.x;
        bm = (lin >> 2) * 128;
        bn = (lin & 3) * 128;
        pA = qh + (long)bm * FT;
        pB = Gh + (long)bn * FT;
        po = Qh;
        ldo = HD;
        scale = 0.25f;
    }

    float acc[4][4][4];
    gemm_body(pA, pB, FT, FT, FT, sbase, tid, wid, L, acc);

    const int r0 = bm + wm * 64 + (L >> 2);
    const int c0 = bn + wn * 32 + (L & 3) * 2;
    #pragma unroll
    for (int mt = 0; mt < 4; mt++) {
        const int row = r0 + mt * 16;
        #pragma unroll
        for (int nt = 0; nt < 4; nt++) {
            const int c = c0 + nt * 8;
            __half2 t;
            t.x = __float2half_rn(acc[mt][nt][0] * scale);
            t.y = __float2half_rn(acc[mt][nt][1] * scale);
            *reinterpret_cast<__half2*>(po + (size_t)row * ldo + c) = t;
            t.x = __float2half_rn(acc[mt][nt][2] * scale);
            t.y = __float2half_rn(acc[mt][nt][3] * scale);
            *reinterpret_cast<__half2*>(po + (size_t)(row + 8) * ldo + c) = t;
        }
    }
}

// ---------------- fused prep: whalf (256 blk) + gemmG (1024 blk) + uvec (64 blk) ----
__global__ __launch_bounds__(256)
void prep(const float* __restrict__ Wv, const float* __restrict__ Wk_,
          const float* __restrict__ Wq_, const float* __restrict__ bq,
          __half* __restrict__ Wth, __half* __restrict__ Gh, float* __restrict__ u)
{
    const int bid = blockIdx.x;
    if (bid < 256) {
        // whalf: Wv [K,N] -> Wth [N,K] fp16
        __shared__ float t[32][33];
        const int n0 = (bid & 15) * 32, k0 = (bid >> 4) * 32;
        const int tx = threadIdx.x & 31, ty = threadIdx.x >> 5;
        #pragma unroll
        for (int i = 0; i < 4; i++) {
            const int r = ty + i * 8;
            t[r][tx] = Wv[(size_t)(k0 + r) * HD + n0 + tx];
        }
        __syncthreads();
        #pragma unroll
        for (int i = 0; i < 4; i++) {
            const int r = ty + i * 8;
            Wth[(size_t)(n0 + r) * FT + k0 + tx] = __float2half_rn(t[tx][r]);
        }
    } else if (bid < 1280) {
        // gemmG: G[a,b] = sum_h Wk[a,h]*Wq[b,h]
        __shared__ float sk[16][17], sq[16][17];
        const int lin = bid - 256;
        const int b0 = (lin & 31) * 16, a0 = (lin >> 5) * 16;
        const int tx = threadIdx.x & 15;
        const int ty = threadIdx.x >> 4;
        float acc = 0.0f;
        for (int h0 = 0; h0 < FT; h0 += 16) {
            sk[ty][tx] = Wk_[(size_t)(a0 + ty) * HD + h0 + tx];
            sq[ty][tx] = Wq_[(size_t)(b0 + ty) * HD + h0 + tx];
            __syncthreads();
            #pragma unroll
            for (int hh = 0; hh < 16; hh++)
                acc = fmaf(sk[ty][hh], sq[tx][hh], acc);
            __syncthreads();
        }
        Gh[(size_t)(a0 + ty) * HD + b0 + tx] = __float2half_rn(acc);
    } else {
        // uvec: u[f] = sum_h Wk[f,h] * bq[h]
        const int f = (bid - 1280) * 8 + ((int)threadIdx.x >> 5);
        const int lane = threadIdx.x & 31;
        float s = 0.0f;
        for (int j = lane; j < FT; j += 32) s = fmaf(Wk_[(size_t)f * HD + j], bq[j], s);
        #pragma unroll
        for (int o = 16; o > 0; o >>= 1) s += __shfl_xor_sync(0xffffffffu, s, o);
        if (lane == 0) u[f] = s;
    }
}

// ---------------- fused conv: qvhalf (16384 blk) + kprep (4096 blk) ----------------
__global__ __launch_bounds__(256)
void conv(const float* __restrict__ q, const float* __restrict__ v,
          const float* __restrict__ k, const float* __restrict__ u,
          __half* __restrict__ qh, __half* __restrict__ vh,
          __half* __restrict__ kh, float* __restrict__ col)
{
    const int bid = blockIdx.x;
    if (bid < 16384) {
        const int half = bid >= 8192;
        const int blk = bid - (half ? 8192 : 0);
        const float* src = half ? v : q;
        __half* dst = half ? vh : qh;
        const int i = (blk * 256 + threadIdx.x) * 4;
        float4 a = *reinterpret_cast<const float4*>(src + i);
        __half2 t;
        t.x = __float2half_rn(a.x); t.y = __float2half_rn(a.y);
        *reinterpret_cast<__half2*>(dst + i) = t;
        t.x = __float2half_rn(a.z); t.y = __float2half_rn(a.w);
        *reinterpret_cast<__half2*>(dst + i + 2) = t;
    } else {
        // kprep
        __shared__ float us[FT];
        __shared__ float part[4][2];
        const int blk = bid - 16384;
        for (int i = threadIdx.x; i < FT; i += 256) us[i] = u[i];
        __syncthreads();

        const int rl = threadIdx.x >> 6;
        const int t64 = threadIdx.x & 63;
        const size_t row = (size_t)blk * 4 + rl;
        const size_t base = row * FT + t64 * 8;

        float4 a = *reinterpret_cast<const float4*>(k + base);
        float4 b = *reinterpret_cast<const float4*>(k + base + 4);
        __half2 h;
        h.x = __float2half_rn(a.x); h.y = __float2half_rn(a.y);
        *reinterpret_cast<__half2*>(kh + base) = h;
        h.x = __float2half_rn(a.z); h.y = __float2half_rn(a.w);
        *reinterpret_cast<__half2*>(kh + base + 2) = h;
        h.x = __float2half_rn(b.x); h.y = __float2half_rn(b.y);
        *reinterpret_cast<__half2*>(kh + base + 4) = h;
        h.x = __float2half_rn(b.z); h.y = __float2half_rn(b.w);
        *reinterpret_cast<__half2*>(kh + base + 6) = h;

        const int j = t64 * 8;
        float s = a.x * us[j] + a.y * us[j + 1] + a.z * us[j + 2] + a.w * us[j + 3]
                + b.x * us[j + 4] + b.y * us[j + 5] + b.z * us[j + 6] + b.w * us[j + 7];
        #pragma unroll
        for (int o = 16; o > 0; o >>= 1) s += __shfl_xor_sync(0xffffffffu, s, o);
        if ((threadIdx.x & 31) == 0) part[rl][(t64 >> 5)] = s;
        __syncthreads();
        if (threadIdx.x < 4)
            col[(size_t)blk * 4 + threadIdx.x] =
                0.25f * (part[threadIdx.x][0] + part[threadIdx.x][1]);
    }
}

// ---------------- launch ----------------
extern "C" void kernel_launch(void* const* d_in, const int* in_sizes, int n_in,
                              void* d_out, int out_size)
{
    const float* q  = (const float*)d_in[0];
    const float* k  = (const float*)d_in[1];
    const float* v  = (const float*)d_in[2];
    const float* Wq = (const float*)d_in[3];
    const float* bq = (const float*)d_in[4];
    const float* Wk = (const float*)d_in[5];
    // bk cancels in softmax (row-constant)
    const float* Wv = (const float*)d_in[7];
    const float* bv = (const float*)d_in[8];
    float* out = (float*)d_out;

    __half *qh, *kh, *vh, *Gh, *wvh, *Qh, *Yt, *E;
    float *u, *col, *Zpart;
    cudaGetSymbolAddress((void**)&qh, g_qh);
    cudaGetSymbolAddress((void**)&kh, g_kh);
    cudaGetSymbolAddress((void**)&vh, g_vh);
    cudaGetSymbolAddress((void**)&Gh, g_Gh);
    cudaGetSymbolAddress((void**)&wvh, g_Wvh);
    cudaGetSymbolAddress((void**)&Qh, g_Qh);
    cudaGetSymbolAddress((void**)&Yt, g_Yt);
    cudaGetSymbolAddress((void**)&E, g_E);
    cudaGetSymbolAddress((void**)&u, g_u);
    cudaGetSymbolAddress((void**)&col, g_col);
    cudaGetSymbolAddress((void**)&Zpart, g_Zpart);

    cudaFuncSetAttribute((const void*)gemm_dual, cudaFuncAttributeMaxDynamicSharedMemorySize, GEMM_SMEM);
    cudaFuncSetAttribute((const void*)gemm_E, cudaFuncAttributeMaxDynamicSharedMemorySize, GEMM_SMEM);
    cudaFuncSetAttribute((const void*)gemm_out, cudaFuncAttributeMaxDynamicSharedMemorySize, GEMM_SMEM);

    // 1) weight prep (whalf + gemmG + uvec in one launch)
    prep<<<1344, 256>>>(Wv, Wk, Wq, bq, wvh, Gh, u);
    // 2) input conversions (q,v fp16 + k fp16/col in one launch)
    conv<<<16384 + 4096, 256>>>(q, v, k, u, qh, vh, kh, col);
    // 3) merged Q' (0.25 q.G) + Yt (Wv^T v^T)
    gemm_dual<<<dim3(16, 4, 16), 256, GEMM_SMEM>>>(wvh, vh, qh, Gh, Yt, Qh);
    // 4) E = exp(Q'.k^T + col - 8) with fused deterministic row-sum partials
    gemm_E<<<dim3(16, 16, 8), 256, GEMM_SMEM>>>(Qh, kh, col, E, Zpart);
    // 5) out = (E.Yt^T) * invZ[row] + bv  (invZ reduced in-kernel from Zpart)
    gemm_out<<<dim3(HD / 128, TT / 128, BZ), 256, GEMM_SMEM>>>(E, Yt, Zpart, bv, out);
}